// round 2
// baseline (speedup 1.0000x reference)
#include <cuda_runtime.h>
#include <math.h>

#define SEQ 4096
#define DMODEL 512
#define NHEAD 8
#define HDIM 64
#define FDIM 2048
#define NEXP 8
#define NPAIR (SEQ * 2)

// ---------------- scratch (device globals; no allocations allowed) ----------
__device__ float g_xn[SEQ * DMODEL];           // layernorm output (reused ln1/ln2)
__device__ float g_qkv[SEQ * 3 * DMODEL];      // qkv projection
__device__ float g_attn[SEQ * DMODEL];         // attention output (pre out-proj)
__device__ float g_xg[NPAIR * DMODEL];         // gathered tokens for MoE
__device__ float g_h1[NPAIR * FDIM];           // expert up-proj 1 (then fused g)
__device__ float g_h2[NPAIR * FDIM];           // expert up-proj 2
__device__ int   g_tidx[NPAIR];                // top2 expert index per (token,k)
__device__ float g_tscale[NPAIR];              // top2 gate prob per (token,k)
__device__ int   g_counts[NEXP];
__device__ int   g_cursor[NEXP];
__device__ int   g_off[NEXP];
__device__ int   g_rowTok[NPAIR];
__device__ float g_rowScale[NPAIR];

// ---------------- layernorm: one block per row, 128 threads ------------------
__global__ __launch_bounds__(128) void layernorm_k(
    const float* __restrict__ x, const float* __restrict__ g,
    const float* __restrict__ b, float* __restrict__ y)
{
    int t = blockIdx.x;
    int tid = threadIdx.x;
    float4 v = ((const float4*)(x + (size_t)t * DMODEL))[tid];
    float s  = v.x + v.y + v.z + v.w;
    float ss = v.x * v.x + v.y * v.y + v.z * v.z + v.w * v.w;
    #pragma unroll
    for (int o = 16; o > 0; o >>= 1) {
        s  += __shfl_xor_sync(0xffffffffu, s, o);
        ss += __shfl_xor_sync(0xffffffffu, ss, o);
    }
    __shared__ float sw[4], ssw[4];
    __shared__ float meanS, rstdS;
    int lane = tid & 31, w = tid >> 5;
    if (lane == 0) { sw[w] = s; ssw[w] = ss; }
    __syncthreads();
    if (tid == 0) {
        float S = sw[0] + sw[1] + sw[2] + sw[3];
        float SS = ssw[0] + ssw[1] + ssw[2] + ssw[3];
        float mean = S / (float)DMODEL;
        float var = SS / (float)DMODEL - mean * mean;
        meanS = mean;
        rstdS = rsqrtf(var + 1e-5f);
    }
    __syncthreads();
    float mean = meanS, rstd = rstdS;
    float4 gg = ((const float4*)g)[tid];
    float4 bb = ((const float4*)b)[tid];
    float4 o;
    o.x = (v.x - mean) * rstd * gg.x + bb.x;
    o.y = (v.y - mean) * rstd * gg.y + bb.y;
    o.z = (v.z - mean) * rstd * gg.z + bb.z;
    o.w = (v.w - mean) * rstd * gg.w + bb.w;
    ((float4*)(y + (size_t)t * DMODEL))[tid] = o;
}

// ---------------- shared GEMM core: C[M,N] = A[M,K] * B[N,K]^T ---------------
// BM=BN=128, BK=16, 256 threads, 8x8 per-thread register tile.
__device__ __forceinline__ void gemm_core(
    const float* __restrict__ A, const float* __restrict__ B,
    int M, int K, int bm, int bn,
    float (*As)[132], float (*Bs)[132], float acc[8][8])
{
    const int tid = threadIdx.x;
    const int ry = (tid >> 4) << 3;
    const int rx = (tid & 15) << 3;
    for (int k0 = 0; k0 < K; k0 += 16) {
        #pragma unroll
        for (int i = 0; i < 2; i++) {
            int f = tid + i * 256;
            int r = f >> 2;
            int c4 = (f & 3) << 2;
            float4 v = make_float4(0.f, 0.f, 0.f, 0.f);
            int gr = bm + r;
            if (gr < M) v = *(const float4*)(A + (size_t)gr * K + k0 + c4);
            As[c4 + 0][r] = v.x; As[c4 + 1][r] = v.y;
            As[c4 + 2][r] = v.z; As[c4 + 3][r] = v.w;
            float4 wv = *(const float4*)(B + (size_t)(bn + r) * K + k0 + c4);
            Bs[c4 + 0][r] = wv.x; Bs[c4 + 1][r] = wv.y;
            Bs[c4 + 2][r] = wv.z; Bs[c4 + 3][r] = wv.w;
        }
        __syncthreads();
        #pragma unroll
        for (int kk = 0; kk < 16; kk++) {
            float4 a0 = *(const float4*)&As[kk][ry];
            float4 a1 = *(const float4*)&As[kk][ry + 4];
            float4 b0 = *(const float4*)&Bs[kk][rx];
            float4 b1 = *(const float4*)&Bs[kk][rx + 4];
            float a[8] = {a0.x, a0.y, a0.z, a0.w, a1.x, a1.y, a1.z, a1.w};
            float b[8] = {b0.x, b0.y, b0.z, b0.w, b1.x, b1.y, b1.z, b1.w};
            #pragma unroll
            for (int i = 0; i < 8; i++)
                #pragma unroll
                for (int j = 0; j < 8; j++)
                    acc[i][j] = fmaf(a[i], b[j], acc[i][j]);
        }
        __syncthreads();
    }
}

// Plain GEMM with bias + optional residual add.
__global__ __launch_bounds__(256) void gemm_nt(
    const float* __restrict__ A, const float* __restrict__ B,
    const float* __restrict__ bias, const float* __restrict__ resid,
    float* __restrict__ C, int M, int N, int K)
{
    __shared__ float As[16][132];
    __shared__ float Bs[16][132];
    const int bm = blockIdx.y * 128;
    const int bn = blockIdx.x * 128;
    float acc[8][8];
    #pragma unroll
    for (int i = 0; i < 8; i++)
        #pragma unroll
        for (int j = 0; j < 8; j++) acc[i][j] = 0.f;
    gemm_core(A, B, M, K, bm, bn, As, Bs, acc);
    const int tid = threadIdx.x;
    const int ry = (tid >> 4) << 3;
    const int rx = (tid & 15) << 3;
    #pragma unroll
    for (int i = 0; i < 8; i++) {
        int r = bm + ry + i;
        if (r >= M) break;
        #pragma unroll
        for (int j = 0; j < 8; j++) {
            int c = bn + rx + j;
            float v = acc[i][j] + bias[c];
            if (resid) v += resid[(size_t)r * N + c];
            C[(size_t)r * N + c] = v;
        }
    }
}

// MoE up-projection GEMM: per-expert gathered rows, W [E][F][D], bias [E][F].
__global__ __launch_bounds__(256) void moe_up_gemm(
    const float* __restrict__ W, const float* __restrict__ Ball,
    float* __restrict__ Out)
{
    int e = blockIdx.z;
    int M = g_counts[e];
    int bm = blockIdx.y * 128;
    if (bm >= M) return;
    int bn = blockIdx.x * 128;
    const float* A = g_xg + (size_t)g_off[e] * DMODEL;
    const float* B = W + (size_t)e * FDIM * DMODEL;
    const float* bias = Ball + (size_t)e * FDIM;
    float* C = Out + (size_t)g_off[e] * FDIM;
    __shared__ float As[16][132];
    __shared__ float Bs[16][132];
    float acc[8][8];
    #pragma unroll
    for (int i = 0; i < 8; i++)
        #pragma unroll
        for (int j = 0; j < 8; j++) acc[i][j] = 0.f;
    gemm_core(A, B, M, DMODEL, bm, bn, As, Bs, acc);
    const int tid = threadIdx.x;
    const int ry = (tid >> 4) << 3;
    const int rx = (tid & 15) << 3;
    #pragma unroll
    for (int i = 0; i < 8; i++) {
        int r = bm + ry + i;
        if (r >= M) break;
        #pragma unroll
        for (int j = 0; j < 8; j++) {
            int c = bn + rx + j;
            C[(size_t)r * FDIM + c] = acc[i][j] + bias[c];
        }
    }
}

// MoE down GEMM + scaled scatter-add into the residual output.
// A = g_h1 (post silu*mul), B = wo [E][D][F], bias = bo [E][D].
__global__ __launch_bounds__(256) void moe_down_gemm(
    const float* __restrict__ Wo, const float* __restrict__ Bo,
    float* __restrict__ Out)
{
    int e = blockIdx.z;
    int M = g_counts[e];
    int bm = blockIdx.y * 128;
    if (bm >= M) return;
    int bn = blockIdx.x * 128;
    const float* A = g_h1 + (size_t)g_off[e] * FDIM;
    const float* B = Wo + (size_t)e * DMODEL * FDIM;
    const float* bias = Bo + (size_t)e * DMODEL;
    __shared__ float As[16][132];
    __shared__ float Bs[16][132];
    float acc[8][8];
    #pragma unroll
    for (int i = 0; i < 8; i++)
        #pragma unroll
        for (int j = 0; j < 8; j++) acc[i][j] = 0.f;
    gemm_core(A, B, M, FDIM, bm, bn, As, Bs, acc);
    const int tid = threadIdx.x;
    const int ry = (tid >> 4) << 3;
    const int rx = (tid & 15) << 3;
    #pragma unroll
    for (int i = 0; i < 8; i++) {
        int r = bm + ry + i;
        if (r >= M) break;
        int gr = g_off[e] + r;
        int tok = g_rowTok[gr];
        float sc = g_rowScale[gr];
        #pragma unroll
        for (int j = 0; j < 8; j++) {
            int c = bn + rx + j;
            atomicAdd(&Out[(size_t)tok * DMODEL + c], sc * (acc[i][j] + bias[c]));
        }
    }
}

// ---------------- flash attention: Bq=64, Bk=32, hd=64, 256 threads ----------
__global__ __launch_bounds__(256) void flash_attn(
    const float* __restrict__ qkv, float* __restrict__ out)
{
    const int h = blockIdx.y;
    const int q0 = blockIdx.x * 64;
    const int tid = threadIdx.x;
    const int tx = tid & 15, ty = tid >> 4;
    const int ty4 = ty * 4, tx2 = tx * 2, tx4 = tx * 4;

    __shared__ float Qs[64][64];   // [d][row]
    __shared__ float Ks[64][32];   // [d][col]
    __shared__ float Vs[32][64];   // [k][d]
    __shared__ float Ss[64][33];   // scores / probs, padded
    __shared__ float mS[64], lS[64], aS[64];

    // load Q tile transposed
    #pragma unroll
    for (int i = 0; i < 4; i++) {
        int f = tid + i * 256;       // 1024 float4 total
        int r = f >> 4;
        int d4 = (f & 15) << 2;
        float4 v = *(const float4*)(qkv + (size_t)(q0 + r) * 1536 + h * 64 + d4);
        Qs[d4 + 0][r] = v.x; Qs[d4 + 1][r] = v.y;
        Qs[d4 + 2][r] = v.z; Qs[d4 + 3][r] = v.w;
    }
    if (tid < 64) { mS[tid] = -1e30f; lS[tid] = 0.f; }

    float acc[4][4];
    #pragma unroll
    for (int i = 0; i < 4; i++)
        #pragma unroll
        for (int j = 0; j < 4; j++) acc[i][j] = 0.f;

    for (int k0 = 0; k0 < SEQ; k0 += 32) {
        #pragma unroll
        for (int i = 0; i < 2; i++) {
            int f = tid + i * 256;   // 512 float4
            int col = f >> 4;
            int d4 = (f & 15) << 2;
            const float* baseK = qkv + (size_t)(k0 + col) * 1536 + 512 + h * 64 + d4;
            float4 kv = *(const float4*)baseK;
            Ks[d4 + 0][col] = kv.x; Ks[d4 + 1][col] = kv.y;
            Ks[d4 + 2][col] = kv.z; Ks[d4 + 3][col] = kv.w;
            float4 vv = *(const float4*)(baseK + 512);
            *(float4*)&Vs[col][d4] = vv;
        }
        __syncthreads();

        // S = Q K^T * scale
        float s[4][2];
        #pragma unroll
        for (int i = 0; i < 4; i++) { s[i][0] = 0.f; s[i][1] = 0.f; }
        #pragma unroll
        for (int d = 0; d < 64; d++) {
            float4 a = *(const float4*)&Qs[d][ty4];
            float b0 = Ks[d][tx2], b1 = Ks[d][tx2 + 1];
            s[0][0] = fmaf(a.x, b0, s[0][0]); s[0][1] = fmaf(a.x, b1, s[0][1]);
            s[1][0] = fmaf(a.y, b0, s[1][0]); s[1][1] = fmaf(a.y, b1, s[1][1]);
            s[2][0] = fmaf(a.z, b0, s[2][0]); s[2][1] = fmaf(a.z, b1, s[2][1]);
            s[3][0] = fmaf(a.w, b0, s[3][0]); s[3][1] = fmaf(a.w, b1, s[3][1]);
        }
        #pragma unroll
        for (int i = 0; i < 4; i++) {
            Ss[ty4 + i][tx2]     = s[i][0] * 0.125f;
            Ss[ty4 + i][tx2 + 1] = s[i][1] * 0.125f;
        }
        __syncthreads();

        // online softmax per row
        if (tid < 64) {
            int r = tid;
            float mprev = mS[r];
            float mx = mprev;
            #pragma unroll
            for (int j = 0; j < 32; j++) mx = fmaxf(mx, Ss[r][j]);
            float alpha = __expf(mprev - mx);
            float sum = 0.f;
            #pragma unroll
            for (int j = 0; j < 32; j++) {
                float p = __expf(Ss[r][j] - mx);
                Ss[r][j] = p;
                sum += p;
            }
            lS[r] = lS[r] * alpha + sum;
            mS[r] = mx;
            aS[r] = alpha;
        }
        __syncthreads();

        #pragma unroll
        for (int i = 0; i < 4; i++) {
            float al = aS[ty4 + i];
            #pragma unroll
            for (int j = 0; j < 4; j++) acc[i][j] *= al;
        }
        #pragma unroll
        for (int kk = 0; kk < 32; kk++) {
            float4 vv = *(const float4*)&Vs[kk][tx4];
            float p0 = Ss[ty4 + 0][kk];
            float p1 = Ss[ty4 + 1][kk];
            float p2 = Ss[ty4 + 2][kk];
            float p3 = Ss[ty4 + 3][kk];
            acc[0][0] = fmaf(p0, vv.x, acc[0][0]); acc[0][1] = fmaf(p0, vv.y, acc[0][1]);
            acc[0][2] = fmaf(p0, vv.z, acc[0][2]); acc[0][3] = fmaf(p0, vv.w, acc[0][3]);
            acc[1][0] = fmaf(p1, vv.x, acc[1][0]); acc[1][1] = fmaf(p1, vv.y, acc[1][1]);
            acc[1][2] = fmaf(p1, vv.z, acc[1][2]); acc[1][3] = fmaf(p1, vv.w, acc[1][3]);
            acc[2][0] = fmaf(p2, vv.x, acc[2][0]); acc[2][1] = fmaf(p2, vv.y, acc[2][1]);
            acc[2][2] = fmaf(p2, vv.z, acc[2][2]); acc[2][3] = fmaf(p2, vv.w, acc[2][3]);
            acc[3][0] = fmaf(p3, vv.x, acc[3][0]); acc[3][1] = fmaf(p3, vv.y, acc[3][1]);
            acc[3][2] = fmaf(p3, vv.z, acc[3][2]); acc[3][3] = fmaf(p3, vv.w, acc[3][3]);
        }
        __syncthreads();
    }

    #pragma unroll
    for (int i = 0; i < 4; i++) {
        int r = ty4 + i;
        float inv = 1.f / lS[r];
        #pragma unroll
        for (int j = 0; j < 4; j++) {
            out[(size_t)(q0 + r) * DMODEL + h * 64 + tx4 + j] = acc[i][j] * inv;
        }
    }
}

// ---------------- gating: one warp per token ---------------------------------
__global__ __launch_bounds__(128) void gate_topk(
    const float* __restrict__ xn, const float* __restrict__ gw,
    const float* __restrict__ gb)
{
    int warp = threadIdx.x >> 5;
    int lane = threadIdx.x & 31;
    int t = blockIdx.x * 4 + warp;
    float acc[NEXP];
    #pragma unroll
    for (int e = 0; e < NEXP; e++) acc[e] = 0.f;
    for (int d = lane; d < DMODEL; d += 32) {
        float xv = xn[(size_t)t * DMODEL + d];
        #pragma unroll
        for (int e = 0; e < NEXP; e++) acc[e] = fmaf(xv, gw[e * DMODEL + d], acc[e]);
    }
    #pragma unroll
    for (int e = 0; e < NEXP; e++)
        #pragma unroll
        for (int o = 16; o > 0; o >>= 1)
            acc[e] += __shfl_xor_sync(0xffffffffu, acc[e], o);
    if (lane == 0) {
        float lg[NEXP];
        float mx = -1e30f;
        #pragma unroll
        for (int e = 0; e < NEXP; e++) { lg[e] = acc[e] + gb[e]; mx = fmaxf(mx, lg[e]); }
        float sum = 0.f;
        #pragma unroll
        for (int e = 0; e < NEXP; e++) { lg[e] = __expf(lg[e] - mx); sum += lg[e]; }
        float inv = 1.f / sum;
        int e0 = 0; float p0 = lg[0];
        #pragma unroll
        for (int e = 1; e < NEXP; e++) if (lg[e] > p0) { p0 = lg[e]; e0 = e; }
        int e1 = -1; float p1 = -1.f;
        #pragma unroll
        for (int e = 0; e < NEXP; e++)
            if (e != e0 && lg[e] > p1) { p1 = lg[e]; e1 = e; }
        g_tidx[t * 2] = e0;         g_tidx[t * 2 + 1] = e1;
        g_tscale[t * 2] = p0 * inv; g_tscale[t * 2 + 1] = p1 * inv;
        atomicAdd(&g_counts[e0], 1);
        atomicAdd(&g_counts[e1], 1);
    }
}

__global__ void zero_counts_k() {
    if (threadIdx.x < NEXP) { g_counts[threadIdx.x] = 0; g_cursor[threadIdx.x] = 0; }
}

__global__ void calc_offsets_k() {
    int o = 0;
    for (int e = 0; e < NEXP; e++) { g_off[e] = o; o += g_counts[e]; }
}

// gather tokens into expert-contiguous rows; one block per (token, k) pair
__global__ __launch_bounds__(128) void gather_pairs(const float* __restrict__ xn)
{
    int p = blockIdx.x;
    __shared__ int posS;
    if (threadIdx.x == 0) {
        int e = g_tidx[p];
        int pos = g_off[e] + atomicAdd(&g_cursor[e], 1);
        g_rowTok[pos] = p >> 1;
        g_rowScale[pos] = g_tscale[p];
        posS = pos;
    }
    __syncthreads();
    int pos = posS;
    int t = p >> 1;
    ((float4*)(g_xg + (size_t)pos * DMODEL))[threadIdx.x] =
        ((const float4*)(xn + (size_t)t * DMODEL))[threadIdx.x];
}

// h1 = silu(h1) * h2, elementwise over all NPAIR*FDIM values (all rows valid)
__global__ __launch_bounds__(256) void silu_mul_k()
{
    size_t i = (size_t)blockIdx.x * blockDim.x + threadIdx.x;  // float4 index
    float4 a = ((const float4*)g_h1)[i];
    float4 b = ((const float4*)g_h2)[i];
    a.x = a.x / (1.f + __expf(-a.x)) * b.x;
    a.y = a.y / (1.f + __expf(-a.y)) * b.y;
    a.z = a.z / (1.f + __expf(-a.z)) * b.z;
    a.w = a.w / (1.f + __expf(-a.w)) * b.w;
    ((float4*)g_h1)[i] = a;
}

// ---------------- launch -----------------------------------------------------
extern "C" void kernel_launch(void* const* d_in, const int* in_sizes, int n_in,
                              void* d_out, int out_size)
{
    const float* src        = (const float*)d_in[0];
    const float* in_proj_w  = (const float*)d_in[1];
    const float* in_proj_b  = (const float*)d_in[2];
    const float* out_proj_w = (const float*)d_in[3];
    const float* out_proj_b = (const float*)d_in[4];
    const float* ln1_g      = (const float*)d_in[5];
    const float* ln1_b      = (const float*)d_in[6];
    const float* ln2_g      = (const float*)d_in[7];
    const float* ln2_b      = (const float*)d_in[8];
    const float* gate_w     = (const float*)d_in[9];
    const float* gate_b     = (const float*)d_in[10];
    const float* w1         = (const float*)d_in[11];
    const float* b1         = (const float*)d_in[12];
    const float* w2         = (const float*)d_in[13];
    const float* b2         = (const float*)d_in[14];
    const float* wo         = (const float*)d_in[15];
    const float* bo         = (const float*)d_in[16];
    float* out = (float*)d_out;

    float *xn, *qkv, *attn, *h1, *h2;
    cudaGetSymbolAddress((void**)&xn,   g_xn);
    cudaGetSymbolAddress((void**)&qkv,  g_qkv);
    cudaGetSymbolAddress((void**)&attn, g_attn);
    cudaGetSymbolAddress((void**)&h1,   g_h1);
    cudaGetSymbolAddress((void**)&h2,   g_h2);

    zero_counts_k<<<1, 32>>>();

    // ---- attention block ----
    layernorm_k<<<SEQ, 128>>>(src, ln1_g, ln1_b, xn);
    gemm_nt<<<dim3(12, 32), 256>>>(xn, in_proj_w, in_proj_b, nullptr, qkv,
                                   SEQ, 3 * DMODEL, DMODEL);
    flash_attn<<<dim3(64, NHEAD), 256>>>(qkv, attn);
    gemm_nt<<<dim3(4, 32), 256>>>(attn, out_proj_w, out_proj_b, src, out,
                                  SEQ, DMODEL, DMODEL);   // out = x1 (residual)

    // ---- MoE block ----
    layernorm_k<<<SEQ, 128>>>(out, ln2_g, ln2_b, xn);
    gate_topk<<<SEQ / 4, 128>>>(xn, gate_w, gate_b);
    calc_offsets_k<<<1, 1>>>();
    gather_pairs<<<NPAIR, 128>>>(xn);
    moe_up_gemm<<<dim3(FDIM / 128, SEQ / 128, NEXP), 256>>>(w1, b1, h1);
    moe_up_gemm<<<dim3(FDIM / 128, SEQ / 128, NEXP), 256>>>(w2, b2, h2);
    silu_mul_k<<<(NPAIR * FDIM / 4) / 256, 256>>>();
    moe_down_gemm<<<dim3(DMODEL / 128, SEQ / 128, NEXP), 256>>>(wo, bo, out);
}

// round 3
// speedup vs baseline: 2.5251x; 2.5251x over previous
#include <cuda_runtime.h>
#include <math.h>

#define SEQ 4096
#define DMODEL 512
#define NHEAD 8
#define HDIM 64
#define FDIM 2048
#define NEXP 8
#define NPAIR (SEQ * 2)

// ---------------- scratch (device globals; no allocations allowed) ----------
__device__ float g_xn[SEQ * DMODEL];
__device__ float g_qkv[SEQ * 3 * DMODEL];
__device__ float g_attn[SEQ * DMODEL];
__device__ float g_xg[NPAIR * DMODEL];
__device__ float g_h1[NPAIR * FDIM];
__device__ float g_h2[NPAIR * FDIM];
__device__ int   g_tidx[NPAIR];
__device__ float g_tscale[NPAIR];
__device__ int   g_counts[NEXP];
__device__ int   g_cursor[NEXP];
__device__ int   g_off[NEXP];
__device__ int   g_rowTok[NPAIR];
__device__ float g_rowScale[NPAIR];

// ---------------- tf32 helpers ----------------------------------------------
__device__ __forceinline__ unsigned f2tf(float f) {
    unsigned u;
    asm("cvt.rna.tf32.f32 %0, %1;" : "=r"(u) : "f"(f));
    return u;
}

__device__ __forceinline__ void mma8(float c[4],
    unsigned a0, unsigned a1, unsigned a2, unsigned a3,
    unsigned b0, unsigned b1)
{
    asm volatile(
        "mma.sync.aligned.m16n8k8.row.col.f32.tf32.tf32.f32 "
        "{%0,%1,%2,%3}, {%4,%5,%6,%7}, {%8,%9}, {%0,%1,%2,%3};\n"
        : "+f"(c[0]), "+f"(c[1]), "+f"(c[2]), "+f"(c[3])
        : "r"(a0), "r"(a1), "r"(a2), "r"(a3), "r"(b0), "r"(b1));
}

// ---------------- layernorm ---------------------------------------------------
__global__ __launch_bounds__(128) void layernorm_k(
    const float* __restrict__ x, const float* __restrict__ g,
    const float* __restrict__ b, float* __restrict__ y)
{
    int t = blockIdx.x;
    int tid = threadIdx.x;
    float4 v = ((const float4*)(x + (size_t)t * DMODEL))[tid];
    float s  = v.x + v.y + v.z + v.w;
    float ss = v.x * v.x + v.y * v.y + v.z * v.z + v.w * v.w;
    #pragma unroll
    for (int o = 16; o > 0; o >>= 1) {
        s  += __shfl_xor_sync(0xffffffffu, s, o);
        ss += __shfl_xor_sync(0xffffffffu, ss, o);
    }
    __shared__ float sw[4], ssw[4];
    __shared__ float meanS, rstdS;
    int lane = tid & 31, w = tid >> 5;
    if (lane == 0) { sw[w] = s; ssw[w] = ss; }
    __syncthreads();
    if (tid == 0) {
        float S = sw[0] + sw[1] + sw[2] + sw[3];
        float SS = ssw[0] + ssw[1] + ssw[2] + ssw[3];
        float mean = S / (float)DMODEL;
        float var = SS / (float)DMODEL - mean * mean;
        meanS = mean;
        rstdS = rsqrtf(var + 1e-5f);
    }
    __syncthreads();
    float mean = meanS, rstd = rstdS;
    float4 gg = ((const float4*)g)[tid];
    float4 bb = ((const float4*)b)[tid];
    float4 o;
    o.x = (v.x - mean) * rstd * gg.x + bb.x;
    o.y = (v.y - mean) * rstd * gg.y + bb.y;
    o.z = (v.z - mean) * rstd * gg.z + bb.z;
    o.w = (v.w - mean) * rstd * gg.w + bb.w;
    ((float4*)(y + (size_t)t * DMODEL))[tid] = o;
}

// ---------------- tf32 mma GEMM core: C[M,N] = A[M,K] * B[N,K]^T --------------
// BM=128 BN=128 BK=16, 256 threads (8 warps, 2x4), warp tile 64x32 (m16n8k8).
// Both A and B stored row-major [row][k] in smem, ld=20 u32 (conflict-free frags).
__device__ __forceinline__ void gemm_tf32_core(
    const float* __restrict__ A, const float* __restrict__ B,
    int M, int K, int bm, int bn,
    unsigned (*As)[20], unsigned (*Bs)[20], float c[4][4][4])
{
    const int tid = threadIdx.x;
    const int lane = tid & 31;
    const int g = lane >> 2, tig = lane & 3;
    const int w = tid >> 5;
    const int wm = (w >> 2) << 6;
    const int wn = (w & 3) << 5;
    const int rr0 = tid >> 2;        // 0..63
    const int c4  = (tid & 3) << 2;  // 0,4,8,12
    const int nk = K >> 4;

    float4 pa[2], pb[2];
    #pragma unroll
    for (int i = 0; i < 2; i++) {
        int rr = rr0 + (i << 6);
        pa[i] = (bm + rr < M)
              ? *(const float4*)(A + (size_t)(bm + rr) * K + c4)
              : make_float4(0.f, 0.f, 0.f, 0.f);
        pb[i] = *(const float4*)(B + (size_t)(bn + rr) * K + c4);
    }

    for (int kt = 0; kt < nk; kt++) {
        #pragma unroll
        for (int i = 0; i < 2; i++) {
            int rr = rr0 + (i << 6);
            uint4 ua; ua.x = f2tf(pa[i].x); ua.y = f2tf(pa[i].y);
                      ua.z = f2tf(pa[i].z); ua.w = f2tf(pa[i].w);
            *(uint4*)&As[rr][c4] = ua;
            uint4 ub; ub.x = f2tf(pb[i].x); ub.y = f2tf(pb[i].y);
                      ub.z = f2tf(pb[i].z); ub.w = f2tf(pb[i].w);
            *(uint4*)&Bs[rr][c4] = ub;
        }
        __syncthreads();
        if (kt + 1 < nk) {
            int k0 = (kt + 1) << 4;
            #pragma unroll
            for (int i = 0; i < 2; i++) {
                int rr = rr0 + (i << 6);
                pa[i] = (bm + rr < M)
                      ? *(const float4*)(A + (size_t)(bm + rr) * K + k0 + c4)
                      : make_float4(0.f, 0.f, 0.f, 0.f);
                pb[i] = *(const float4*)(B + (size_t)(bn + rr) * K + k0 + c4);
            }
        }
        #pragma unroll
        for (int kk = 0; kk < 2; kk++) {
            const int kb = kk << 3;
            unsigned a[4][4], b[4][2];
            #pragma unroll
            for (int mi = 0; mi < 4; mi++) {
                int m0 = wm + (mi << 4);
                a[mi][0] = As[m0 + g][kb + tig];
                a[mi][1] = As[m0 + g + 8][kb + tig];
                a[mi][2] = As[m0 + g][kb + tig + 4];
                a[mi][3] = As[m0 + g + 8][kb + tig + 4];
            }
            #pragma unroll
            for (int ni = 0; ni < 4; ni++) {
                int n0 = wn + (ni << 3);
                b[ni][0] = Bs[n0 + g][kb + tig];
                b[ni][1] = Bs[n0 + g][kb + tig + 4];
            }
            #pragma unroll
            for (int mi = 0; mi < 4; mi++)
                #pragma unroll
                for (int ni = 0; ni < 4; ni++)
                    mma8(c[mi][ni], a[mi][0], a[mi][1], a[mi][2], a[mi][3],
                         b[ni][0], b[ni][1]);
        }
        __syncthreads();
    }
}

#define GEMM_PROLOGUE() \
    __shared__ unsigned As[128][20]; \
    __shared__ unsigned Bs[128][20]; \
    float c[4][4][4]; \
    _Pragma("unroll") \
    for (int mi = 0; mi < 4; mi++) \
        _Pragma("unroll") \
        for (int ni = 0; ni < 4; ni++) \
            _Pragma("unroll") \
            for (int j = 0; j < 4; j++) c[mi][ni][j] = 0.f; \
    const int lane = threadIdx.x & 31; \
    const int g = lane >> 2, tig = lane & 3; \
    const int w = threadIdx.x >> 5; \
    const int wm = (w >> 2) << 6, wn = (w & 3) << 5;

// Plain GEMM + bias + optional residual.
__global__ __launch_bounds__(256) void gemm_nt(
    const float* __restrict__ A, const float* __restrict__ B,
    const float* __restrict__ bias, const float* __restrict__ resid,
    float* __restrict__ C, int M, int N, int K)
{
    const int bm = blockIdx.y * 128;
    const int bn = blockIdx.x * 128;
    GEMM_PROLOGUE();
    gemm_tf32_core(A, B, M, K, bm, bn, As, Bs, c);
    #pragma unroll
    for (int mi = 0; mi < 4; mi++) {
        #pragma unroll
        for (int half = 0; half < 2; half++) {
            int row = bm + wm + (mi << 4) + g + half * 8;
            if (row >= M) continue;
            #pragma unroll
            for (int ni = 0; ni < 4; ni++) {
                int col = bn + wn + (ni << 3) + 2 * tig;
                float v0 = c[mi][ni][half * 2]     + bias[col];
                float v1 = c[mi][ni][half * 2 + 1] + bias[col + 1];
                if (resid) {
                    v0 += resid[(size_t)row * N + col];
                    v1 += resid[(size_t)row * N + col + 1];
                }
                float2 v; v.x = v0; v.y = v1;
                *(float2*)&C[(size_t)row * N + col] = v;
            }
        }
    }
}

// MoE up-proj #1: h1 = x@w1^T + b1
__global__ __launch_bounds__(256) void moe_up1(
    const float* __restrict__ W, const float* __restrict__ Ball)
{
    int e = blockIdx.z;
    int M = g_counts[e];
    int bm = blockIdx.y * 128;
    if (bm >= M) return;
    int bn = blockIdx.x * 128;
    const float* A = g_xg + (size_t)g_off[e] * DMODEL;
    const float* B = W + (size_t)e * FDIM * DMODEL;
    const float* bias = Ball + (size_t)e * FDIM;
    float* C = g_h1 + (size_t)g_off[e] * FDIM;
    GEMM_PROLOGUE();
    gemm_tf32_core(A, B, M, DMODEL, bm, bn, As, Bs, c);
    #pragma unroll
    for (int mi = 0; mi < 4; mi++)
        #pragma unroll
        for (int half = 0; half < 2; half++) {
            int row = bm + wm + (mi << 4) + g + half * 8;
            if (row >= M) continue;
            #pragma unroll
            for (int ni = 0; ni < 4; ni++) {
                int col = bn + wn + (ni << 3) + 2 * tig;
                float2 v;
                v.x = c[mi][ni][half * 2]     + bias[col];
                v.y = c[mi][ni][half * 2 + 1] + bias[col + 1];
                *(float2*)&C[(size_t)row * FDIM + col] = v;
            }
        }
}

// MoE up-proj #2 fused with silu: h1 = silu(h1) * (x@w2^T + b2)
__global__ __launch_bounds__(256) void moe_up2(
    const float* __restrict__ W, const float* __restrict__ Ball)
{
    int e = blockIdx.z;
    int M = g_counts[e];
    int bm = blockIdx.y * 128;
    if (bm >= M) return;
    int bn = blockIdx.x * 128;
    const float* A = g_xg + (size_t)g_off[e] * DMODEL;
    const float* B = W + (size_t)e * FDIM * DMODEL;
    const float* bias = Ball + (size_t)e * FDIM;
    float* H = g_h1 + (size_t)g_off[e] * FDIM;
    GEMM_PROLOGUE();
    gemm_tf32_core(A, B, M, DMODEL, bm, bn, As, Bs, c);
    #pragma unroll
    for (int mi = 0; mi < 4; mi++)
        #pragma unroll
        for (int half = 0; half < 2; half++) {
            int row = bm + wm + (mi << 4) + g + half * 8;
            if (row >= M) continue;
            #pragma unroll
            for (int ni = 0; ni < 4; ni++) {
                int col = bn + wn + (ni << 3) + 2 * tig;
                float2 gv = *(const float2*)&H[(size_t)row * FDIM + col];
                float h2v0 = c[mi][ni][half * 2]     + bias[col];
                float h2v1 = c[mi][ni][half * 2 + 1] + bias[col + 1];
                float s0 = gv.x / (1.f + __expf(-gv.x));
                float s1 = gv.y / (1.f + __expf(-gv.y));
                float2 v; v.x = s0 * h2v0; v.y = s1 * h2v1;
                *(float2*)&H[(size_t)row * FDIM + col] = v;
            }
        }
}

// MoE down GEMM + scaled scatter-add.
__global__ __launch_bounds__(256) void moe_down(
    const float* __restrict__ Wo, const float* __restrict__ Bo,
    float* __restrict__ Out)
{
    int e = blockIdx.z;
    int M = g_counts[e];
    int bm = blockIdx.y * 128;
    if (bm >= M) return;
    int bn = blockIdx.x * 128;
    const float* A = g_h1 + (size_t)g_off[e] * FDIM;
    const float* B = Wo + (size_t)e * DMODEL * FDIM;
    const float* bias = Bo + (size_t)e * DMODEL;
    GEMM_PROLOGUE();
    gemm_tf32_core(A, B, M, FDIM, bm, bn, As, Bs, c);
    #pragma unroll
    for (int mi = 0; mi < 4; mi++)
        #pragma unroll
        for (int half = 0; half < 2; half++) {
            int row = bm + wm + (mi << 4) + g + half * 8;
            if (row >= M) continue;
            int gr = g_off[e] + row;
            int tok = g_rowTok[gr];
            float sc = g_rowScale[gr];
            #pragma unroll
            for (int ni = 0; ni < 4; ni++) {
                int col = bn + wn + (ni << 3) + 2 * tig;
                atomicAdd(&Out[(size_t)tok * DMODEL + col],
                          sc * (c[mi][ni][half * 2] + bias[col]));
                atomicAdd(&Out[(size_t)tok * DMODEL + col + 1],
                          sc * (c[mi][ni][half * 2 + 1] + bias[col + 1]));
            }
        }
}

// ---------------- tf32 mma flash attention ------------------------------------
// Bq=64, Bk=64, 128 threads (4 warps); warp w owns q-rows [w*16, w*16+16).
// Softmax state (m,l) lives in registers (row = fragment groupID).
#define ATTN_SMEM_U32 (3 * 64 * 72 + 4 * 16 * 68)
__global__ __launch_bounds__(128) void flash_attn_tf32(
    const float* __restrict__ qkv, float* __restrict__ out)
{
    extern __shared__ unsigned sm[];
    unsigned (*Qs)[72] = (unsigned(*)[72])sm;               // [m][d]
    unsigned (*Ks)[72] = (unsigned(*)[72])(sm + 64 * 72);   // [col][d]
    unsigned (*Vs)[72] = (unsigned(*)[72])(sm + 2 * 64 * 72); // [k][d]
    const int tid = threadIdx.x;
    const int w = tid >> 5, lane = tid & 31;
    const int g = lane >> 2, tig = lane & 3;
    unsigned (*Ps)[68] = (unsigned(*)[68])(sm + 3 * 64 * 72 + w * 16 * 68);
    const int h = blockIdx.y;
    const int q0 = blockIdx.x * 64;
    const float L2E = 1.4426950408889634f;

    // load Q tile (tf32)
    #pragma unroll
    for (int i = 0; i < 8; i++) {
        int f = tid + i * 128;
        int r = f >> 4, d4 = (f & 15) << 2;
        float4 v = *(const float4*)(qkv + (size_t)(q0 + r) * 1536 + h * 64 + d4);
        uint4 u; u.x = f2tf(v.x); u.y = f2tf(v.y); u.z = f2tf(v.z); u.w = f2tf(v.w);
        *(uint4*)&Qs[r][d4] = u;
    }

    float o[8][4];
    #pragma unroll
    for (int nt = 0; nt < 8; nt++)
        #pragma unroll
        for (int j = 0; j < 4; j++) o[nt][j] = 0.f;
    float mr0 = -1e30f, mr1 = -1e30f, lr0 = 0.f, lr1 = 0.f;

    const int m0 = w * 16;

    for (int k0 = 0; k0 < SEQ; k0 += 64) {
        __syncthreads();   // previous K/V reads done (also covers Q on iter 0)
        #pragma unroll
        for (int i = 0; i < 8; i++) {
            int f = tid + i * 128;
            int col = f >> 4, d4 = (f & 15) << 2;
            const float* base = qkv + (size_t)(k0 + col) * 1536 + 512 + h * 64 + d4;
            float4 kv = *(const float4*)base;
            uint4 uk; uk.x = f2tf(kv.x); uk.y = f2tf(kv.y); uk.z = f2tf(kv.z); uk.w = f2tf(kv.w);
            *(uint4*)&Ks[col][d4] = uk;
            float4 vv = *(const float4*)(base + 512);
            uint4 uv; uv.x = f2tf(vv.x); uv.y = f2tf(vv.y); uv.z = f2tf(vv.z); uv.w = f2tf(vv.w);
            *(uint4*)&Vs[col][d4] = uv;
        }
        __syncthreads();

        // S = Q K^T  (16 x 64 per warp)
        float s[8][4];
        #pragma unroll
        for (int nt = 0; nt < 8; nt++)
            #pragma unroll
            for (int j = 0; j < 4; j++) s[nt][j] = 0.f;
        #pragma unroll
        for (int kt = 0; kt < 8; kt++) {
            int kb = kt << 3;
            unsigned a0 = Qs[m0 + g][kb + tig];
            unsigned a1 = Qs[m0 + g + 8][kb + tig];
            unsigned a2 = Qs[m0 + g][kb + tig + 4];
            unsigned a3 = Qs[m0 + g + 8][kb + tig + 4];
            #pragma unroll
            for (int nt = 0; nt < 8; nt++) {
                unsigned b0 = Ks[(nt << 3) + g][kb + tig];
                unsigned b1 = Ks[(nt << 3) + g][kb + tig + 4];
                mma8(s[nt], a0, a1, a2, a3, b0, b1);
            }
        }

        // online softmax; rows g (regs 0,1) and g+8 (regs 2,3)
        float mx0 = -1e30f, mx1 = -1e30f;
        #pragma unroll
        for (int nt = 0; nt < 8; nt++) {
            s[nt][0] *= 0.125f; s[nt][1] *= 0.125f;
            s[nt][2] *= 0.125f; s[nt][3] *= 0.125f;
            mx0 = fmaxf(mx0, fmaxf(s[nt][0], s[nt][1]));
            mx1 = fmaxf(mx1, fmaxf(s[nt][2], s[nt][3]));
        }
        mx0 = fmaxf(mx0, __shfl_xor_sync(0xffffffffu, mx0, 1));
        mx0 = fmaxf(mx0, __shfl_xor_sync(0xffffffffu, mx0, 2));
        mx1 = fmaxf(mx1, __shfl_xor_sync(0xffffffffu, mx1, 1));
        mx1 = fmaxf(mx1, __shfl_xor_sync(0xffffffffu, mx1, 2));
        float mn0 = fmaxf(mr0, mx0), mn1 = fmaxf(mr1, mx1);
        float al0 = __expf(mr0 - mn0), al1 = __expf(mr1 - mn1);
        float sum0 = 0.f, sum1 = 0.f;
        #pragma unroll
        for (int nt = 0; nt < 8; nt++) {
            float p0 = __expf(s[nt][0] - mn0);
            float p1 = __expf(s[nt][1] - mn0);
            float p2 = __expf(s[nt][2] - mn1);
            float p3 = __expf(s[nt][3] - mn1);
            sum0 += p0 + p1; sum1 += p2 + p3;
            uint2 u0; u0.x = f2tf(p0); u0.y = f2tf(p1);
            *(uint2*)&Ps[g][(nt << 3) + 2 * tig] = u0;
            uint2 u1; u1.x = f2tf(p2); u1.y = f2tf(p3);
            *(uint2*)&Ps[g + 8][(nt << 3) + 2 * tig] = u1;
        }
        sum0 += __shfl_xor_sync(0xffffffffu, sum0, 1);
        sum0 += __shfl_xor_sync(0xffffffffu, sum0, 2);
        sum1 += __shfl_xor_sync(0xffffffffu, sum1, 1);
        sum1 += __shfl_xor_sync(0xffffffffu, sum1, 2);
        lr0 = lr0 * al0 + sum0; mr0 = mn0;
        lr1 = lr1 * al1 + sum1; mr1 = mn1;
        #pragma unroll
        for (int nt = 0; nt < 8; nt++) {
            o[nt][0] *= al0; o[nt][1] *= al0;
            o[nt][2] *= al1; o[nt][3] *= al1;
        }
        __syncwarp();

        // O += P V  (P 16x64 from Ps, V 64x64)
        #pragma unroll
        for (int kt = 0; kt < 8; kt++) {
            int kb = kt << 3;
            unsigned a0 = Ps[g][kb + tig];
            unsigned a1 = Ps[g + 8][kb + tig];
            unsigned a2 = Ps[g][kb + tig + 4];
            unsigned a3 = Ps[g + 8][kb + tig + 4];
            #pragma unroll
            for (int nt = 0; nt < 8; nt++) {
                unsigned b0 = Vs[kb + tig][(nt << 3) + g];
                unsigned b1 = Vs[kb + tig + 4][(nt << 3) + g];
                mma8(o[nt], a0, a1, a2, a3, b0, b1);
            }
        }
    }

    float inv0 = 1.f / lr0, inv1 = 1.f / lr1;
    #pragma unroll
    for (int nt = 0; nt < 8; nt++) {
        int col = h * 64 + (nt << 3) + 2 * tig;
        float2 r0; r0.x = o[nt][0] * inv0; r0.y = o[nt][1] * inv0;
        *(float2*)&out[(size_t)(q0 + m0 + g) * DMODEL + col] = r0;
        float2 r1; r1.x = o[nt][2] * inv1; r1.y = o[nt][3] * inv1;
        *(float2*)&out[(size_t)(q0 + m0 + g + 8) * DMODEL + col] = r1;
    }
}

// ---------------- gating -----------------------------------------------------
__global__ __launch_bounds__(128) void gate_topk(
    const float* __restrict__ xn, const float* __restrict__ gw,
    const float* __restrict__ gb)
{
    int warp = threadIdx.x >> 5;
    int lane = threadIdx.x & 31;
    int t = blockIdx.x * 4 + warp;
    float acc[NEXP];
    #pragma unroll
    for (int e = 0; e < NEXP; e++) acc[e] = 0.f;
    for (int d = lane; d < DMODEL; d += 32) {
        float xv = xn[(size_t)t * DMODEL + d];
        #pragma unroll
        for (int e = 0; e < NEXP; e++) acc[e] = fmaf(xv, gw[e * DMODEL + d], acc[e]);
    }
    #pragma unroll
    for (int e = 0; e < NEXP; e++)
        #pragma unroll
        for (int o = 16; o > 0; o >>= 1)
            acc[e] += __shfl_xor_sync(0xffffffffu, acc[e], o);
    if (lane == 0) {
        float lg[NEXP];
        float mx = -1e30f;
        #pragma unroll
        for (int e = 0; e < NEXP; e++) { lg[e] = acc[e] + gb[e]; mx = fmaxf(mx, lg[e]); }
        float sum = 0.f;
        #pragma unroll
        for (int e = 0; e < NEXP; e++) { lg[e] = __expf(lg[e] - mx); sum += lg[e]; }
        float inv = 1.f / sum;
        int e0 = 0; float p0 = lg[0];
        #pragma unroll
        for (int e = 1; e < NEXP; e++) if (lg[e] > p0) { p0 = lg[e]; e0 = e; }
        int e1 = -1; float p1 = -1.f;
        #pragma unroll
        for (int e = 0; e < NEXP; e++)
            if (e != e0 && lg[e] > p1) { p1 = lg[e]; e1 = e; }
        g_tidx[t * 2] = e0;         g_tidx[t * 2 + 1] = e1;
        g_tscale[t * 2] = p0 * inv; g_tscale[t * 2 + 1] = p1 * inv;
        atomicAdd(&g_counts[e0], 1);
        atomicAdd(&g_counts[e1], 1);
    }
}

__global__ void zero_counts_k() {
    if (threadIdx.x < NEXP) { g_counts[threadIdx.x] = 0; g_cursor[threadIdx.x] = 0; }
}

__global__ void calc_offsets_k() {
    int o = 0;
    for (int e = 0; e < NEXP; e++) { g_off[e] = o; o += g_counts[e]; }
}

__global__ __launch_bounds__(128) void gather_pairs(const float* __restrict__ xn)
{
    int p = blockIdx.x;
    __shared__ int posS;
    if (threadIdx.x == 0) {
        int e = g_tidx[p];
        int pos = g_off[e] + atomicAdd(&g_cursor[e], 1);
        g_rowTok[pos] = p >> 1;
        g_rowScale[pos] = g_tscale[p];
        posS = pos;
    }
    __syncthreads();
    int pos = posS;
    int t = p >> 1;
    ((float4*)(g_xg + (size_t)pos * DMODEL))[threadIdx.x] =
        ((const float4*)(xn + (size_t)t * DMODEL))[threadIdx.x];
}

// ---------------- launch -----------------------------------------------------
extern "C" void kernel_launch(void* const* d_in, const int* in_sizes, int n_in,
                              void* d_out, int out_size)
{
    const float* src        = (const float*)d_in[0];
    const float* in_proj_w  = (const float*)d_in[1];
    const float* in_proj_b  = (const float*)d_in[2];
    const float* out_proj_w = (const float*)d_in[3];
    const float* out_proj_b = (const float*)d_in[4];
    const float* ln1_g      = (const float*)d_in[5];
    const float* ln1_b      = (const float*)d_in[6];
    const float* ln2_g      = (const float*)d_in[7];
    const float* ln2_b      = (const float*)d_in[8];
    const float* gate_w     = (const float*)d_in[9];
    const float* gate_b     = (const float*)d_in[10];
    const float* w1         = (const float*)d_in[11];
    const float* b1         = (const float*)d_in[12];
    const float* w2         = (const float*)d_in[13];
    const float* b2         = (const float*)d_in[14];
    const float* wo         = (const float*)d_in[15];
    const float* bo         = (const float*)d_in[16];
    float* out = (float*)d_out;

    float *xn, *qkv, *attn;
    cudaGetSymbolAddress((void**)&xn,   g_xn);
    cudaGetSymbolAddress((void**)&qkv,  g_qkv);
    cudaGetSymbolAddress((void**)&attn, g_attn);

    const int attn_smem = ATTN_SMEM_U32 * 4;
    cudaFuncSetAttribute(flash_attn_tf32,
                         cudaFuncAttributeMaxDynamicSharedMemorySize, attn_smem);

    zero_counts_k<<<1, 32>>>();

    // ---- attention block ----
    layernorm_k<<<SEQ, 128>>>(src, ln1_g, ln1_b, xn);
    gemm_nt<<<dim3(12, 32), 256>>>(xn, in_proj_w, in_proj_b, nullptr, qkv,
                                   SEQ, 3 * DMODEL, DMODEL);
    flash_attn_tf32<<<dim3(64, NHEAD), 128, attn_smem>>>(qkv, attn);
    gemm_nt<<<dim3(4, 32), 256>>>(attn, out_proj_w, out_proj_b, src, out,
                                  SEQ, DMODEL, DMODEL);

    // ---- MoE block ----
    layernorm_k<<<SEQ, 128>>>(out, ln2_g, ln2_b, xn);
    gate_topk<<<SEQ / 4, 128>>>(xn, gate_w, gate_b);
    calc_offsets_k<<<1, 1>>>();
    gather_pairs<<<NPAIR, 128>>>(xn);
    moe_up1<<<dim3(FDIM / 128, 64, NEXP), 256>>>(w1, b1);
    moe_up2<<<dim3(FDIM / 128, 64, NEXP), 256>>>(w2, b2);
    moe_down<<<dim3(DMODEL / 128, 64, NEXP), 256>>>(wo, bo, out);
}

// round 4
// speedup vs baseline: 2.6327x; 1.0426x over previous
#include <cuda_runtime.h>
#include <math.h>

#define SEQ 4096
#define DMODEL 512
#define NHEAD 8
#define FDIM 2048
#define NEXP 8
#define NPAIR (SEQ * 2)

// ---------------- scratch (device globals; no allocations allowed) ----------
__device__ float g_xn[SEQ * DMODEL];
__device__ float g_qkv[SEQ * 3 * DMODEL];
__device__ float g_attn[SEQ * DMODEL];
__device__ float g_xg[NPAIR * DMODEL];
__device__ float g_h1[NPAIR * FDIM];
__device__ int   g_tidx[NPAIR];
__device__ float g_tscale[NPAIR];
__device__ int   g_counts[NEXP];
__device__ int   g_cursor[NEXP];
__device__ int   g_off[NEXP];
__device__ int   g_rowTok[NPAIR];
__device__ float g_rowScale[NPAIR];

// ---------------- tf32 mma (raw fp32 bits; HW ignores low mantissa) ----------
__device__ __forceinline__ void mma8(float c[4],
    unsigned a0, unsigned a1, unsigned a2, unsigned a3,
    unsigned b0, unsigned b1)
{
    asm volatile(
        "mma.sync.aligned.m16n8k8.row.col.f32.tf32.tf32.f32 "
        "{%0,%1,%2,%3}, {%4,%5,%6,%7}, {%8,%9}, {%0,%1,%2,%3};\n"
        : "+f"(c[0]), "+f"(c[1]), "+f"(c[2]), "+f"(c[3])
        : "r"(a0), "r"(a1), "r"(a2), "r"(a3), "r"(b0), "r"(b1));
}

// ---------------- layernorm ---------------------------------------------------
__global__ __launch_bounds__(128) void layernorm_k(
    const float* __restrict__ x, const float* __restrict__ g,
    const float* __restrict__ b, float* __restrict__ y)
{
    int t = blockIdx.x;
    int tid = threadIdx.x;
    float4 v = ((const float4*)(x + (size_t)t * DMODEL))[tid];
    float s  = v.x + v.y + v.z + v.w;
    float ss = v.x * v.x + v.y * v.y + v.z * v.z + v.w * v.w;
    #pragma unroll
    for (int o = 16; o > 0; o >>= 1) {
        s  += __shfl_xor_sync(0xffffffffu, s, o);
        ss += __shfl_xor_sync(0xffffffffu, ss, o);
    }
    __shared__ float sw[4], ssw[4];
    __shared__ float meanS, rstdS;
    int lane = tid & 31, w = tid >> 5;
    if (lane == 0) { sw[w] = s; ssw[w] = ss; }
    __syncthreads();
    if (tid == 0) {
        float S = sw[0] + sw[1] + sw[2] + sw[3];
        float SS = ssw[0] + ssw[1] + ssw[2] + ssw[3];
        float mean = S / (float)DMODEL;
        float var = SS / (float)DMODEL - mean * mean;
        meanS = mean;
        rstdS = rsqrtf(var + 1e-5f);
    }
    __syncthreads();
    float mean = meanS, rstd = rstdS;
    float4 gg = ((const float4*)g)[tid];
    float4 bb = ((const float4*)b)[tid];
    float4 o;
    o.x = (v.x - mean) * rstd * gg.x + bb.x;
    o.y = (v.y - mean) * rstd * gg.y + bb.y;
    o.z = (v.z - mean) * rstd * gg.z + bb.z;
    o.w = (v.w - mean) * rstd * gg.w + bb.w;
    ((float4*)(y + (size_t)t * DMODEL))[tid] = o;
}

// ---------------- tf32 GEMM core: C[M,N] = A[M,K] * B[N,K]^T ------------------
// BM=BN=128, BK=16, 256 threads (8 warps 2x4), warp tile 64x32.
// Double-buffered smem stages (1 sync/iter), raw fp32 bits into mma.
#define GEMM_SMEM_BYTES (2 * 2 * 128 * 20 * 4)

__device__ __forceinline__ void gemm_tf32_core(
    const float* __restrict__ A, const float* __restrict__ B,
    int M, int K, int bm, int bn,
    float (*As)[128][20], float (*Bs)[128][20], float c[4][4][4])
{
    const int tid = threadIdx.x;
    const int lane = tid & 31;
    const int g = lane >> 2, tig = lane & 3;
    const int w = tid >> 5;
    const int wm = (w >> 2) << 6;
    const int wn = (w & 3) << 5;
    const int rr0 = tid >> 2;        // 0..63
    const int c4  = (tid & 3) << 2;  // 0,4,8,12
    const int nk = K >> 4;

    float4 pa[2], pb[2];
    #pragma unroll
    for (int i = 0; i < 2; i++) {
        int rr = rr0 + (i << 6);
        pa[i] = (bm + rr < M)
              ? *(const float4*)(A + (size_t)(bm + rr) * K + c4)
              : make_float4(0.f, 0.f, 0.f, 0.f);
        pb[i] = *(const float4*)(B + (size_t)(bn + rr) * K + c4);
    }
    #pragma unroll
    for (int i = 0; i < 2; i++) {
        int rr = rr0 + (i << 6);
        *(float4*)&As[0][rr][c4] = pa[i];
        *(float4*)&Bs[0][rr][c4] = pb[i];
    }
    __syncthreads();

    for (int kt = 0; kt < nk; kt++) {
        const int cur = kt & 1;
        if (kt + 1 < nk) {
            const int k0 = (kt + 1) << 4;
            #pragma unroll
            for (int i = 0; i < 2; i++) {
                int rr = rr0 + (i << 6);
                pa[i] = (bm + rr < M)
                      ? *(const float4*)(A + (size_t)(bm + rr) * K + k0 + c4)
                      : make_float4(0.f, 0.f, 0.f, 0.f);
                pb[i] = *(const float4*)(B + (size_t)(bn + rr) * K + k0 + c4);
            }
        }
        #pragma unroll
        for (int kk = 0; kk < 2; kk++) {
            const int kb = kk << 3;
            unsigned a[4][4], b[4][2];
            #pragma unroll
            for (int mi = 0; mi < 4; mi++) {
                int mrow = wm + (mi << 4);
                a[mi][0] = __float_as_uint(As[cur][mrow + g][kb + tig]);
                a[mi][1] = __float_as_uint(As[cur][mrow + g + 8][kb + tig]);
                a[mi][2] = __float_as_uint(As[cur][mrow + g][kb + tig + 4]);
                a[mi][3] = __float_as_uint(As[cur][mrow + g + 8][kb + tig + 4]);
            }
            #pragma unroll
            for (int ni = 0; ni < 4; ni++) {
                int nrow = wn + (ni << 3);
                b[ni][0] = __float_as_uint(Bs[cur][nrow + g][kb + tig]);
                b[ni][1] = __float_as_uint(Bs[cur][nrow + g][kb + tig + 4]);
            }
            #pragma unroll
            for (int mi = 0; mi < 4; mi++)
                #pragma unroll
                for (int ni = 0; ni < 4; ni++)
                    mma8(c[mi][ni], a[mi][0], a[mi][1], a[mi][2], a[mi][3],
                         b[ni][0], b[ni][1]);
        }
        if (kt + 1 < nk) {
            const int nxt = cur ^ 1;
            #pragma unroll
            for (int i = 0; i < 2; i++) {
                int rr = rr0 + (i << 6);
                *(float4*)&As[nxt][rr][c4] = pa[i];
                *(float4*)&Bs[nxt][rr][c4] = pb[i];
            }
            __syncthreads();
        }
    }
}

#define GEMM_PROLOGUE() \
    extern __shared__ float gsm[]; \
    float (*As)[128][20] = (float(*)[128][20])gsm; \
    float (*Bs)[128][20] = (float(*)[128][20])(gsm + 2 * 128 * 20); \
    float c[4][4][4]; \
    _Pragma("unroll") \
    for (int mi = 0; mi < 4; mi++) \
        _Pragma("unroll") \
        for (int ni = 0; ni < 4; ni++) \
            _Pragma("unroll") \
            for (int j = 0; j < 4; j++) c[mi][ni][j] = 0.f; \
    const int lane = threadIdx.x & 31; \
    const int g = lane >> 2, tig = lane & 3; \
    const int w = threadIdx.x >> 5; \
    const int wm = (w >> 2) << 6, wn = (w & 3) << 5;

// Plain GEMM + bias + optional residual.
__global__ __launch_bounds__(256) void gemm_nt(
    const float* __restrict__ A, const float* __restrict__ B,
    const float* __restrict__ bias, const float* __restrict__ resid,
    float* __restrict__ C, int M, int N, int K)
{
    const int bm = blockIdx.y * 128;
    const int bn = blockIdx.x * 128;
    GEMM_PROLOGUE();
    gemm_tf32_core(A, B, M, K, bm, bn, As, Bs, c);
    #pragma unroll
    for (int mi = 0; mi < 4; mi++) {
        #pragma unroll
        for (int half = 0; half < 2; half++) {
            int row = bm + wm + (mi << 4) + g + half * 8;
            if (row >= M) continue;
            #pragma unroll
            for (int ni = 0; ni < 4; ni++) {
                int col = bn + wn + (ni << 3) + 2 * tig;
                float v0 = c[mi][ni][half * 2]     + bias[col];
                float v1 = c[mi][ni][half * 2 + 1] + bias[col + 1];
                if (resid) {
                    v0 += resid[(size_t)row * N + col];
                    v1 += resid[(size_t)row * N + col + 1];
                }
                float2 v; v.x = v0; v.y = v1;
                *(float2*)&C[(size_t)row * N + col] = v;
            }
        }
    }
}

// MoE up-proj #1: h1 = x@w1^T + b1
__global__ __launch_bounds__(256) void moe_up1(
    const float* __restrict__ W, const float* __restrict__ Ball)
{
    int e = blockIdx.z;
    int M = g_counts[e];
    int bm = blockIdx.y * 128;
    if (bm >= M) return;
    int bn = blockIdx.x * 128;
    const float* A = g_xg + (size_t)g_off[e] * DMODEL;
    const float* B = W + (size_t)e * FDIM * DMODEL;
    const float* bias = Ball + (size_t)e * FDIM;
    float* C = g_h1 + (size_t)g_off[e] * FDIM;
    GEMM_PROLOGUE();
    gemm_tf32_core(A, B, M, DMODEL, bm, bn, As, Bs, c);
    #pragma unroll
    for (int mi = 0; mi < 4; mi++)
        #pragma unroll
        for (int half = 0; half < 2; half++) {
            int row = bm + wm + (mi << 4) + g + half * 8;
            if (row >= M) continue;
            #pragma unroll
            for (int ni = 0; ni < 4; ni++) {
                int col = bn + wn + (ni << 3) + 2 * tig;
                float2 v;
                v.x = c[mi][ni][half * 2]     + bias[col];
                v.y = c[mi][ni][half * 2 + 1] + bias[col + 1];
                *(float2*)&C[(size_t)row * FDIM + col] = v;
            }
        }
}

// MoE up-proj #2 fused with silu: h1 = silu(h1) * (x@w2^T + b2)
__global__ __launch_bounds__(256) void moe_up2(
    const float* __restrict__ W, const float* __restrict__ Ball)
{
    int e = blockIdx.z;
    int M = g_counts[e];
    int bm = blockIdx.y * 128;
    if (bm >= M) return;
    int bn = blockIdx.x * 128;
    const float* A = g_xg + (size_t)g_off[e] * DMODEL;
    const float* B = W + (size_t)e * FDIM * DMODEL;
    const float* bias = Ball + (size_t)e * FDIM;
    float* H = g_h1 + (size_t)g_off[e] * FDIM;
    GEMM_PROLOGUE();
    gemm_tf32_core(A, B, M, DMODEL, bm, bn, As, Bs, c);
    #pragma unroll
    for (int mi = 0; mi < 4; mi++)
        #pragma unroll
        for (int half = 0; half < 2; half++) {
            int row = bm + wm + (mi << 4) + g + half * 8;
            if (row >= M) continue;
            #pragma unroll
            for (int ni = 0; ni < 4; ni++) {
                int col = bn + wn + (ni << 3) + 2 * tig;
                float2 gv = *(const float2*)&H[(size_t)row * FDIM + col];
                float h2v0 = c[mi][ni][half * 2]     + bias[col];
                float h2v1 = c[mi][ni][half * 2 + 1] + bias[col + 1];
                float s0 = gv.x / (1.f + __expf(-gv.x));
                float s1 = gv.y / (1.f + __expf(-gv.y));
                float2 v; v.x = s0 * h2v0; v.y = s1 * h2v1;
                *(float2*)&H[(size_t)row * FDIM + col] = v;
            }
        }
}

// MoE down GEMM + scaled scatter-add.
__global__ __launch_bounds__(256) void moe_down(
    const float* __restrict__ Wo, const float* __restrict__ Bo,
    float* __restrict__ Out)
{
    int e = blockIdx.z;
    int M = g_counts[e];
    int bm = blockIdx.y * 128;
    if (bm >= M) return;
    int bn = blockIdx.x * 128;
    const float* A = g_h1 + (size_t)g_off[e] * FDIM;
    const float* B = Wo + (size_t)e * DMODEL * FDIM;
    const float* bias = Bo + (size_t)e * DMODEL;
    GEMM_PROLOGUE();
    gemm_tf32_core(A, B, M, FDIM, bm, bn, As, Bs, c);
    #pragma unroll
    for (int mi = 0; mi < 4; mi++)
        #pragma unroll
        for (int half = 0; half < 2; half++) {
            int row = bm + wm + (mi << 4) + g + half * 8;
            if (row >= M) continue;
            int gr = g_off[e] + row;
            int tok = g_rowTok[gr];
            float sc = g_rowScale[gr];
            #pragma unroll
            for (int ni = 0; ni < 4; ni++) {
                int col = bn + wn + (ni << 3) + 2 * tig;
                atomicAdd(&Out[(size_t)tok * DMODEL + col],
                          sc * (c[mi][ni][half * 2] + bias[col]));
                atomicAdd(&Out[(size_t)tok * DMODEL + col + 1],
                          sc * (c[mi][ni][half * 2 + 1] + bias[col + 1]));
            }
        }
}

// ---------------- tf32 flash attention ---------------------------------------
// Bq=128, Bk=64, 128 threads (4 warps); warp w owns 32 q-rows (2 m-frags).
// Qs/Ks/Ps stride 68 (banks 4g+tig: conflict-free frag reads);
// Vs stride 72 (banks 8tig+g: conflict-free B-frag reads).
#define ATTN_SMEM_FLOATS (128 * 68 + 64 * 68 + 64 * 72 + 128 * 68)

__global__ __launch_bounds__(128) void flash_attn_tf32(
    const float* __restrict__ qkv, float* __restrict__ out)
{
    extern __shared__ float sm[];
    float (*Qs)[68] = (float(*)[68])sm;
    float (*Ks)[68] = (float(*)[68])(sm + 128 * 68);
    float (*Vs)[72] = (float(*)[72])(sm + 128 * 68 + 64 * 68);
    float (*Ps)[68] = (float(*)[68])(sm + 128 * 68 + 64 * 68 + 64 * 72);

    const int tid = threadIdx.x;
    const int w = tid >> 5, lane = tid & 31;
    const int g = lane >> 2, tig = lane & 3;
    const int h = blockIdx.y;
    const int q0 = blockIdx.x * 128;
    const int m0 = w * 32;

    // load Q tile, pre-scaled by 1/sqrt(64) (exact power of two)
    #pragma unroll
    for (int i = 0; i < 16; i++) {
        int f = tid + i * 128;
        int r = f >> 4, d4 = (f & 15) << 2;
        float4 v = *(const float4*)(qkv + (size_t)(q0 + r) * 1536 + h * 64 + d4);
        v.x *= 0.125f; v.y *= 0.125f; v.z *= 0.125f; v.w *= 0.125f;
        *(float4*)&Qs[r][d4] = v;
    }

    float o[2][8][4];
    #pragma unroll
    for (int mi = 0; mi < 2; mi++)
        #pragma unroll
        for (int nt = 0; nt < 8; nt++)
            #pragma unroll
            for (int j = 0; j < 4; j++) o[mi][nt][j] = 0.f;
    float mr[2][2] = {{-1e30f, -1e30f}, {-1e30f, -1e30f}};
    float lr[2][2] = {{0.f, 0.f}, {0.f, 0.f}};

    for (int k0 = 0; k0 < SEQ; k0 += 64) {
        __syncthreads();   // prior PV reads of Ks/Vs complete (covers Q on iter 0)
        #pragma unroll
        for (int i = 0; i < 8; i++) {
            int f = tid + i * 128;
            int col = f >> 4, d4 = (f & 15) << 2;
            const float* base = qkv + (size_t)(k0 + col) * 1536 + 512 + h * 64 + d4;
            *(float4*)&Ks[col][d4] = *(const float4*)base;
            *(float4*)&Vs[col][d4] = *(const float4*)(base + 512);
        }
        __syncthreads();

        // S = Q K^T   (32 x 64 per warp, 2 m-frags)
        float s[2][8][4];
        #pragma unroll
        for (int mi = 0; mi < 2; mi++)
            #pragma unroll
            for (int nt = 0; nt < 8; nt++)
                #pragma unroll
                for (int j = 0; j < 4; j++) s[mi][nt][j] = 0.f;
        #pragma unroll
        for (int kt = 0; kt < 8; kt++) {
            const int kb = kt << 3;
            unsigned a[2][4];
            #pragma unroll
            for (int mi = 0; mi < 2; mi++) {
                int mb = m0 + (mi << 4);
                a[mi][0] = __float_as_uint(Qs[mb + g][kb + tig]);
                a[mi][1] = __float_as_uint(Qs[mb + g + 8][kb + tig]);
                a[mi][2] = __float_as_uint(Qs[mb + g][kb + tig + 4]);
                a[mi][3] = __float_as_uint(Qs[mb + g + 8][kb + tig + 4]);
            }
            #pragma unroll
            for (int nt = 0; nt < 8; nt++) {
                unsigned b0 = __float_as_uint(Ks[(nt << 3) + g][kb + tig]);
                unsigned b1 = __float_as_uint(Ks[(nt << 3) + g][kb + tig + 4]);
                mma8(s[0][nt], a[0][0], a[0][1], a[0][2], a[0][3], b0, b1);
                mma8(s[1][nt], a[1][0], a[1][1], a[1][2], a[1][3], b0, b1);
            }
        }

        // online softmax (registers; quad shfl reductions), P -> smem (raw bits)
        #pragma unroll
        for (int mi = 0; mi < 2; mi++) {
            int mb = m0 + (mi << 4);
            float mx0 = mr[mi][0], mx1 = mr[mi][1];
            #pragma unroll
            for (int nt = 0; nt < 8; nt++) {
                mx0 = fmaxf(mx0, fmaxf(s[mi][nt][0], s[mi][nt][1]));
                mx1 = fmaxf(mx1, fmaxf(s[mi][nt][2], s[mi][nt][3]));
            }
            mx0 = fmaxf(mx0, __shfl_xor_sync(0xffffffffu, mx0, 1));
            mx0 = fmaxf(mx0, __shfl_xor_sync(0xffffffffu, mx0, 2));
            mx1 = fmaxf(mx1, __shfl_xor_sync(0xffffffffu, mx1, 1));
            mx1 = fmaxf(mx1, __shfl_xor_sync(0xffffffffu, mx1, 2));
            float al0 = __expf(mr[mi][0] - mx0);
            float al1 = __expf(mr[mi][1] - mx1);
            float sum0 = 0.f, sum1 = 0.f;
            #pragma unroll
            for (int nt = 0; nt < 8; nt++) {
                float p0 = __expf(s[mi][nt][0] - mx0);
                float p1 = __expf(s[mi][nt][1] - mx0);
                float p2 = __expf(s[mi][nt][2] - mx1);
                float p3 = __expf(s[mi][nt][3] - mx1);
                sum0 += p0 + p1; sum1 += p2 + p3;
                float2 u0; u0.x = p0; u0.y = p1;
                *(float2*)&Ps[mb + g][(nt << 3) + 2 * tig] = u0;
                float2 u1; u1.x = p2; u1.y = p3;
                *(float2*)&Ps[mb + g + 8][(nt << 3) + 2 * tig] = u1;
            }
            sum0 += __shfl_xor_sync(0xffffffffu, sum0, 1);
            sum0 += __shfl_xor_sync(0xffffffffu, sum0, 2);
            sum1 += __shfl_xor_sync(0xffffffffu, sum1, 1);
            sum1 += __shfl_xor_sync(0xffffffffu, sum1, 2);
            lr[mi][0] = lr[mi][0] * al0 + sum0; mr[mi][0] = mx0;
            lr[mi][1] = lr[mi][1] * al1 + sum1; mr[mi][1] = mx1;
            #pragma unroll
            for (int nt = 0; nt < 8; nt++) {
                o[mi][nt][0] *= al0; o[mi][nt][1] *= al0;
                o[mi][nt][2] *= al1; o[mi][nt][3] *= al1;
            }
        }
        __syncwarp();   // P rows are warp-private; make stores visible in-warp

        // O += P V
        #pragma unroll
        for (int kt = 0; kt < 8; kt++) {
            const int kb = kt << 3;
            unsigned a[2][4];
            #pragma unroll
            for (int mi = 0; mi < 2; mi++) {
                int mb = m0 + (mi << 4);
                a[mi][0] = __float_as_uint(Ps[mb + g][kb + tig]);
                a[mi][1] = __float_as_uint(Ps[mb + g + 8][kb + tig]);
                a[mi][2] = __float_as_uint(Ps[mb + g][kb + tig + 4]);
                a[mi][3] = __float_as_uint(Ps[mb + g + 8][kb + tig + 4]);
            }
            #pragma unroll
            for (int nt = 0; nt < 8; nt++) {
                unsigned b0 = __float_as_uint(Vs[kb + tig][(nt << 3) + g]);
                unsigned b1 = __float_as_uint(Vs[kb + tig + 4][(nt << 3) + g]);
                mma8(o[0][nt], a[0][0], a[0][1], a[0][2], a[0][3], b0, b1);
                mma8(o[1][nt], a[1][0], a[1][1], a[1][2], a[1][3], b0, b1);
            }
        }
    }

    #pragma unroll
    for (int mi = 0; mi < 2; mi++) {
        float inv0 = 1.f / lr[mi][0], inv1 = 1.f / lr[mi][1];
        int mb = m0 + (mi << 4);
        #pragma unroll
        for (int nt = 0; nt < 8; nt++) {
            int col = h * 64 + (nt << 3) + 2 * tig;
            float2 r0; r0.x = o[mi][nt][0] * inv0; r0.y = o[mi][nt][1] * inv0;
            *(float2*)&out[(size_t)(q0 + mb + g) * DMODEL + col] = r0;
            float2 r1; r1.x = o[mi][nt][2] * inv1; r1.y = o[mi][nt][3] * inv1;
            *(float2*)&out[(size_t)(q0 + mb + g + 8) * DMODEL + col] = r1;
        }
    }
}

// ---------------- gating -----------------------------------------------------
__global__ __launch_bounds__(128) void gate_topk(
    const float* __restrict__ xn, const float* __restrict__ gw,
    const float* __restrict__ gb)
{
    int warp = threadIdx.x >> 5;
    int lane = threadIdx.x & 31;
    int t = blockIdx.x * 4 + warp;
    float acc[NEXP];
    #pragma unroll
    for (int e = 0; e < NEXP; e++) acc[e] = 0.f;
    for (int d = lane; d < DMODEL; d += 32) {
        float xv = xn[(size_t)t * DMODEL + d];
        #pragma unroll
        for (int e = 0; e < NEXP; e++) acc[e] = fmaf(xv, gw[e * DMODEL + d], acc[e]);
    }
    #pragma unroll
    for (int e = 0; e < NEXP; e++)
        #pragma unroll
        for (int o = 16; o > 0; o >>= 1)
            acc[e] += __shfl_xor_sync(0xffffffffu, acc[e], o);
    if (lane == 0) {
        float lg[NEXP];
        float mx = -1e30f;
        #pragma unroll
        for (int e = 0; e < NEXP; e++) { lg[e] = acc[e] + gb[e]; mx = fmaxf(mx, lg[e]); }
        float sum = 0.f;
        #pragma unroll
        for (int e = 0; e < NEXP; e++) { lg[e] = __expf(lg[e] - mx); sum += lg[e]; }
        float inv = 1.f / sum;
        int e0 = 0; float p0 = lg[0];
        #pragma unroll
        for (int e = 1; e < NEXP; e++) if (lg[e] > p0) { p0 = lg[e]; e0 = e; }
        int e1 = -1; float p1 = -1.f;
        #pragma unroll
        for (int e = 0; e < NEXP; e++)
            if (e != e0 && lg[e] > p1) { p1 = lg[e]; e1 = e; }
        g_tidx[t * 2] = e0;         g_tidx[t * 2 + 1] = e1;
        g_tscale[t * 2] = p0 * inv; g_tscale[t * 2 + 1] = p1 * inv;
        atomicAdd(&g_counts[e0], 1);
        atomicAdd(&g_counts[e1], 1);
    }
}

__global__ void zero_counts_k() {
    if (threadIdx.x < NEXP) { g_counts[threadIdx.x] = 0; g_cursor[threadIdx.x] = 0; }
}

__global__ void calc_offsets_k() {
    int o = 0;
    for (int e = 0; e < NEXP; e++) { g_off[e] = o; o += g_counts[e]; }
}

__global__ __launch_bounds__(128) void gather_pairs(const float* __restrict__ xn)
{
    int p = blockIdx.x;
    __shared__ int posS;
    if (threadIdx.x == 0) {
        int e = g_tidx[p];
        int pos = g_off[e] + atomicAdd(&g_cursor[e], 1);
        g_rowTok[pos] = p >> 1;
        g_rowScale[pos] = g_tscale[p];
        posS = pos;
    }
    __syncthreads();
    int pos = posS;
    int t = p >> 1;
    ((float4*)(g_xg + (size_t)pos * DMODEL))[threadIdx.x] =
        ((const float4*)(xn + (size_t)t * DMODEL))[threadIdx.x];
}

// ---------------- launch -----------------------------------------------------
extern "C" void kernel_launch(void* const* d_in, const int* in_sizes, int n_in,
                              void* d_out, int out_size)
{
    const float* src        = (const float*)d_in[0];
    const float* in_proj_w  = (const float*)d_in[1];
    const float* in_proj_b  = (const float*)d_in[2];
    const float* out_proj_w = (const float*)d_in[3];
    const float* out_proj_b = (const float*)d_in[4];
    const float* ln1_g      = (const float*)d_in[5];
    const float* ln1_b      = (const float*)d_in[6];
    const float* ln2_g      = (const float*)d_in[7];
    const float* ln2_b      = (const float*)d_in[8];
    const float* gate_w     = (const float*)d_in[9];
    const float* gate_b     = (const float*)d_in[10];
    const float* w1         = (const float*)d_in[11];
    const float* b1         = (const float*)d_in[12];
    const float* w2         = (const float*)d_in[13];
    const float* b2         = (const float*)d_in[14];
    const float* wo         = (const float*)d_in[15];
    const float* bo         = (const float*)d_in[16];
    float* out = (float*)d_out;

    float *xn, *qkv, *attn;
    cudaGetSymbolAddress((void**)&xn,   g_xn);
    cudaGetSymbolAddress((void**)&qkv,  g_qkv);
    cudaGetSymbolAddress((void**)&attn, g_attn);

    const int attn_smem = ATTN_SMEM_FLOATS * 4;
    cudaFuncSetAttribute(flash_attn_tf32,
                         cudaFuncAttributeMaxDynamicSharedMemorySize, attn_smem);
    cudaFuncSetAttribute(gemm_nt,
                         cudaFuncAttributeMaxDynamicSharedMemorySize, GEMM_SMEM_BYTES);
    cudaFuncSetAttribute(moe_up1,
                         cudaFuncAttributeMaxDynamicSharedMemorySize, GEMM_SMEM_BYTES);
    cudaFuncSetAttribute(moe_up2,
                         cudaFuncAttributeMaxDynamicSharedMemorySize, GEMM_SMEM_BYTES);
    cudaFuncSetAttribute(moe_down,
                         cudaFuncAttributeMaxDynamicSharedMemorySize, GEMM_SMEM_BYTES);

    zero_counts_k<<<1, 32>>>();

    // ---- attention block ----
    layernorm_k<<<SEQ, 128>>>(src, ln1_g, ln1_b, xn);
    gemm_nt<<<dim3(12, 32), 256, GEMM_SMEM_BYTES>>>(xn, in_proj_w, in_proj_b,
                                                    nullptr, qkv,
                                                    SEQ, 3 * DMODEL, DMODEL);
    flash_attn_tf32<<<dim3(SEQ / 128, NHEAD), 128, attn_smem>>>(qkv, attn);
    gemm_nt<<<dim3(4, 32), 256, GEMM_SMEM_BYTES>>>(attn, out_proj_w, out_proj_b,
                                                   src, out,
                                                   SEQ, DMODEL, DMODEL);

    // ---- MoE block ----
    layernorm_k<<<SEQ, 128>>>(out, ln2_g, ln2_b, xn);
    gate_topk<<<SEQ / 4, 128>>>(xn, gate_w, gate_b);
    calc_offsets_k<<<1, 1>>>();
    gather_pairs<<<NPAIR, 128>>>(xn);
    moe_up1<<<dim3(FDIM / 128, 64, NEXP), 256, GEMM_SMEM_BYTES>>>(w1, b1);
    moe_up2<<<dim3(FDIM / 128, 64, NEXP), 256, GEMM_SMEM_BYTES>>>(w2, b2);
    moe_down<<<dim3(DMODEL / 128, 64, NEXP), 256, GEMM_SMEM_BYTES>>>(wo, bo, out);
}

// round 5
// speedup vs baseline: 4.2268x; 1.6055x over previous
#include <cuda_runtime.h>
#include <cuda_bf16.h>
#include <math.h>

#define SEQ 4096
#define DMODEL 512
#define NHEAD 8
#define FDIM 2048
#define NEXP 8
#define NPAIR (SEQ * 2)

// ---------------- scratch (device globals; no allocations allowed) ----------
__device__ float g_xn[SEQ * DMODEL];                 // fp32 LN out (gate path)
__device__ __nv_bfloat16 g_xnb[SEQ * DMODEL];        // bf16 LN out (GEMM A)
__device__ float g_qkv[SEQ * 3 * DMODEL];
__device__ __nv_bfloat16 g_attnb[SEQ * DMODEL];
__device__ __nv_bfloat16 g_xgb[NPAIR * DMODEL];
__device__ float g_h1[NPAIR * FDIM];
__device__ __nv_bfloat16 g_hb[NPAIR * FDIM];
__device__ __nv_bfloat16 g_bwin[3 * DMODEL * DMODEL];
__device__ __nv_bfloat16 g_bwout[DMODEL * DMODEL];
__device__ __nv_bfloat16 g_bw1[NEXP * FDIM * DMODEL];
__device__ __nv_bfloat16 g_bw2[NEXP * FDIM * DMODEL];
__device__ __nv_bfloat16 g_bwo[NEXP * DMODEL * FDIM];
__device__ int   g_tidx[NPAIR];
__device__ float g_tscale[NPAIR];
__device__ int   g_counts[NEXP];
__device__ int   g_cursor[NEXP];
__device__ int   g_off[NEXP];
__device__ int   g_rowTok[NPAIR];
__device__ float g_rowScale[NPAIR];

// ---------------- helpers -----------------------------------------------------
__device__ __forceinline__ void mma8(float c[4],
    unsigned a0, unsigned a1, unsigned a2, unsigned a3,
    unsigned b0, unsigned b1)
{
    asm volatile(
        "mma.sync.aligned.m16n8k8.row.col.f32.tf32.tf32.f32 "
        "{%0,%1,%2,%3}, {%4,%5,%6,%7}, {%8,%9}, {%0,%1,%2,%3};\n"
        : "+f"(c[0]), "+f"(c[1]), "+f"(c[2]), "+f"(c[3])
        : "r"(a0), "r"(a1), "r"(a2), "r"(a3), "r"(b0), "r"(b1));
}

__device__ __forceinline__ void mma16(float c[4],
    unsigned a0, unsigned a1, unsigned a2, unsigned a3,
    unsigned b0, unsigned b1)
{
    asm volatile(
        "mma.sync.aligned.m16n8k16.row.col.f32.bf16.bf16.f32 "
        "{%0,%1,%2,%3}, {%4,%5,%6,%7}, {%8,%9}, {%0,%1,%2,%3};\n"
        : "+f"(c[0]), "+f"(c[1]), "+f"(c[2]), "+f"(c[3])
        : "r"(a0), "r"(a1), "r"(a2), "r"(a3), "r"(b0), "r"(b1));
}

__device__ __forceinline__ unsigned smem_u32(const void* p) {
    return (unsigned)__cvta_generic_to_shared(p);
}
__device__ __forceinline__ void cpa16(unsigned dst, const void* src, int vbytes) {
    asm volatile("cp.async.cg.shared.global [%0], [%1], 16, %2;\n"
                 :: "r"(dst), "l"(src), "r"(vbytes) : "memory");
}
__device__ __forceinline__ void cpa_commit() {
    asm volatile("cp.async.commit_group;\n" ::: "memory");
}

// ---------------- fp32 -> bf16 array convert (weights, once per launch) ------
__global__ __launch_bounds__(256) void f2bf_k(const float* __restrict__ in,
                                              __nv_bfloat16* __restrict__ out)
{
    size_t i = (size_t)blockIdx.x * 256 + threadIdx.x;   // per 4 elems
    float4 v = ((const float4*)in)[i];
    __nv_bfloat162 p0 = __floats2bfloat162_rn(v.x, v.y);
    __nv_bfloat162 p1 = __floats2bfloat162_rn(v.z, v.w);
    uint2 u; u.x = *(unsigned*)&p0; u.y = *(unsigned*)&p1;
    ((uint2*)out)[i] = u;
}

// ---------------- layernorm (dual fp32 + bf16 output) -------------------------
__global__ __launch_bounds__(128) void layernorm_k(
    const float* __restrict__ x, const float* __restrict__ g,
    const float* __restrict__ b, float* __restrict__ y,
    __nv_bfloat16* __restrict__ yb)
{
    int t = blockIdx.x;
    int tid = threadIdx.x;
    float4 v = ((const float4*)(x + (size_t)t * DMODEL))[tid];
    float s  = v.x + v.y + v.z + v.w;
    float ss = v.x * v.x + v.y * v.y + v.z * v.z + v.w * v.w;
    #pragma unroll
    for (int o = 16; o > 0; o >>= 1) {
        s  += __shfl_xor_sync(0xffffffffu, s, o);
        ss += __shfl_xor_sync(0xffffffffu, ss, o);
    }
    __shared__ float sw[4], ssw[4];
    __shared__ float meanS, rstdS;
    int lane = tid & 31, w = tid >> 5;
    if (lane == 0) { sw[w] = s; ssw[w] = ss; }
    __syncthreads();
    if (tid == 0) {
        float S = sw[0] + sw[1] + sw[2] + sw[3];
        float SS = ssw[0] + ssw[1] + ssw[2] + ssw[3];
        float mean = S / (float)DMODEL;
        float var = SS / (float)DMODEL - mean * mean;
        meanS = mean;
        rstdS = rsqrtf(var + 1e-5f);
    }
    __syncthreads();
    float mean = meanS, rstd = rstdS;
    float4 gg = ((const float4*)g)[tid];
    float4 bb = ((const float4*)b)[tid];
    float4 o;
    o.x = (v.x - mean) * rstd * gg.x + bb.x;
    o.y = (v.y - mean) * rstd * gg.y + bb.y;
    o.z = (v.z - mean) * rstd * gg.z + bb.z;
    o.w = (v.w - mean) * rstd * gg.w + bb.w;
    ((float4*)(y + (size_t)t * DMODEL))[tid] = o;
    __nv_bfloat162 p0 = __floats2bfloat162_rn(o.x, o.y);
    __nv_bfloat162 p1 = __floats2bfloat162_rn(o.z, o.w);
    uint2 u; u.x = *(unsigned*)&p0; u.y = *(unsigned*)&p1;
    ((uint2*)(yb + (size_t)t * DMODEL))[tid] = u;
}

// ---------------- bf16 GEMM core: C[M,N] = A[M,K] * B[N,K]^T ------------------
// BM=BN=128, BK=32, 256 threads (8 warps 2x4), warp tile 64x32, m16n8k16.
// cp.async double-buffered, smem 40KB static -> 2 CTAs/SM.
// Row layout: 16 bf16x2 uints + 4 pad (ld=20): frag banks 20g+tig all distinct.
__device__ __forceinline__ void gemm_bf16_core(
    const __nv_bfloat16* __restrict__ A, const __nv_bfloat16* __restrict__ B,
    int M, int K, int bm, int bn, unsigned* su, float c[4][4][4])
{
    const int tid = threadIdx.x;
    const int lane = tid & 31, g = lane >> 2, tig = lane & 3;
    const int w = tid >> 5, wm = (w >> 2) << 6, wn = (w & 3) << 5;
    const int r = tid >> 1;            // 0..127
    const int seg0 = (tid & 1) << 1;   // 0 or 2
    const int nk = K >> 5;
    const int arow = (bm + r < M) ? (bm + r) : 0;
    const int av = (bm + r < M) ? 16 : 0;
    const __nv_bfloat16* Ar = A + (size_t)arow * K;
    const __nv_bfloat16* Br = B + (size_t)(bn + r) * K;
    const unsigned dstA = smem_u32(su) + (unsigned)(r * 20) * 4;
    const unsigned dstB = dstA + 5120 * 4;

    // stage layout (uints): A buf0 [0,2560) buf1 [2560,5120); B at +5120
    #define GEMM_ISSUE(kt_) do {                                           \
        int buf_ = (kt_) & 1;                                              \
        int k0_ = (kt_) << 5;                                              \
        _Pragma("unroll")                                                  \
        for (int i_ = 0; i_ < 2; i_++) {                                   \
            int seg_ = seg0 + i_;                                          \
            cpa16(dstA + buf_ * 10240 + seg_ * 16, Ar + k0_ + seg_ * 8, av);\
            cpa16(dstB + buf_ * 10240 + seg_ * 16, Br + k0_ + seg_ * 8, 16);\
        }                                                                  \
        cpa_commit();                                                      \
    } while (0)

    GEMM_ISSUE(0);
    GEMM_ISSUE(1);

    for (int kt = 0; kt < nk; kt++) {
        if (kt < nk - 2) asm volatile("cp.async.wait_group 1;\n" ::: "memory");
        else             asm volatile("cp.async.wait_group 0;\n" ::: "memory");
        __syncthreads();
        const unsigned* Au = su + (kt & 1) * 2560;
        const unsigned* Bu = su + 5120 + (kt & 1) * 2560;
        #pragma unroll
        for (int kk = 0; kk < 2; kk++) {
            const int kb = kk << 3;
            unsigned a[4][4], b[4][2];
            #pragma unroll
            for (int mi = 0; mi < 4; mi++) {
                int m = wm + (mi << 4);
                a[mi][0] = Au[(m + g) * 20 + kb + tig];
                a[mi][1] = Au[(m + g + 8) * 20 + kb + tig];
                a[mi][2] = Au[(m + g) * 20 + kb + tig + 4];
                a[mi][3] = Au[(m + g + 8) * 20 + kb + tig + 4];
            }
            #pragma unroll
            for (int ni = 0; ni < 4; ni++) {
                int n = wn + (ni << 3);
                b[ni][0] = Bu[(n + g) * 20 + kb + tig];
                b[ni][1] = Bu[(n + g) * 20 + kb + tig + 4];
            }
            #pragma unroll
            for (int mi = 0; mi < 4; mi++)
                #pragma unroll
                for (int ni = 0; ni < 4; ni++)
                    mma16(c[mi][ni], a[mi][0], a[mi][1], a[mi][2], a[mi][3],
                          b[ni][0], b[ni][1]);
        }
        __syncthreads();
        if (kt + 2 < nk) GEMM_ISSUE(kt + 2);
    }
    #undef GEMM_ISSUE
}

#define GEMM_PROLOGUE() \
    __shared__ unsigned su[10240]; \
    float c[4][4][4]; \
    _Pragma("unroll") \
    for (int mi = 0; mi < 4; mi++) \
        _Pragma("unroll") \
        for (int ni = 0; ni < 4; ni++) \
            _Pragma("unroll") \
            for (int j = 0; j < 4; j++) c[mi][ni][j] = 0.f; \
    const int lane = threadIdx.x & 31; \
    const int g = lane >> 2, tig = lane & 3; \
    const int w = threadIdx.x >> 5; \
    const int wm = (w >> 2) << 6, wn = (w & 3) << 5;

// Plain GEMM + bias + optional residual (fp32 out).
__global__ __launch_bounds__(256, 2) void gemm_bf16_nt(
    const __nv_bfloat16* __restrict__ A, const __nv_bfloat16* __restrict__ B,
    const float* __restrict__ bias, const float* __restrict__ resid,
    float* __restrict__ C, int M, int N, int K)
{
    const int bm = blockIdx.y * 128;
    const int bn = blockIdx.x * 128;
    GEMM_PROLOGUE();
    gemm_bf16_core(A, B, M, K, bm, bn, su, c);
    #pragma unroll
    for (int mi = 0; mi < 4; mi++)
        #pragma unroll
        for (int half = 0; half < 2; half++) {
            int row = bm + wm + (mi << 4) + g + half * 8;
            if (row >= M) continue;
            #pragma unroll
            for (int ni = 0; ni < 4; ni++) {
                int col = bn + wn + (ni << 3) + 2 * tig;
                float v0 = c[mi][ni][half * 2]     + bias[col];
                float v1 = c[mi][ni][half * 2 + 1] + bias[col + 1];
                if (resid) {
                    v0 += resid[(size_t)row * N + col];
                    v1 += resid[(size_t)row * N + col + 1];
                }
                float2 v; v.x = v0; v.y = v1;
                *(float2*)&C[(size_t)row * N + col] = v;
            }
        }
}

// MoE up-proj #1: g_h1 = x@w1^T + b1 (fp32 out)
__global__ __launch_bounds__(256, 2) void moe_up1(const float* __restrict__ Ball)
{
    int e = blockIdx.z;
    int M = g_counts[e];
    int bm = blockIdx.y * 128;
    if (bm >= M) return;
    int bn = blockIdx.x * 128;
    const __nv_bfloat16* A = g_xgb + (size_t)g_off[e] * DMODEL;
    const __nv_bfloat16* B = g_bw1 + (size_t)e * FDIM * DMODEL;
    const float* bias = Ball + (size_t)e * FDIM;
    float* C = g_h1 + (size_t)g_off[e] * FDIM;
    GEMM_PROLOGUE();
    gemm_bf16_core(A, B, M, DMODEL, bm, bn, su, c);
    #pragma unroll
    for (int mi = 0; mi < 4; mi++)
        #pragma unroll
        for (int half = 0; half < 2; half++) {
            int row = bm + wm + (mi << 4) + g + half * 8;
            if (row >= M) continue;
            #pragma unroll
            for (int ni = 0; ni < 4; ni++) {
                int col = bn + wn + (ni << 3) + 2 * tig;
                float2 v;
                v.x = c[mi][ni][half * 2]     + bias[col];
                v.y = c[mi][ni][half * 2 + 1] + bias[col + 1];
                *(float2*)&C[(size_t)row * FDIM + col] = v;
            }
        }
}

// MoE up-proj #2 fused: g_hb = bf16( silu(h1) * (x@w2^T + b2) )
__global__ __launch_bounds__(256, 2) void moe_up2(const float* __restrict__ Ball)
{
    int e = blockIdx.z;
    int M = g_counts[e];
    int bm = blockIdx.y * 128;
    if (bm >= M) return;
    int bn = blockIdx.x * 128;
    const __nv_bfloat16* A = g_xgb + (size_t)g_off[e] * DMODEL;
    const __nv_bfloat16* B = g_bw2 + (size_t)e * FDIM * DMODEL;
    const float* bias = Ball + (size_t)e * FDIM;
    const float* H1 = g_h1 + (size_t)g_off[e] * FDIM;
    __nv_bfloat16* HB = g_hb + (size_t)g_off[e] * FDIM;
    GEMM_PROLOGUE();
    gemm_bf16_core(A, B, M, DMODEL, bm, bn, su, c);
    #pragma unroll
    for (int mi = 0; mi < 4; mi++)
        #pragma unroll
        for (int half = 0; half < 2; half++) {
            int row = bm + wm + (mi << 4) + g + half * 8;
            if (row >= M) continue;
            #pragma unroll
            for (int ni = 0; ni < 4; ni++) {
                int col = bn + wn + (ni << 3) + 2 * tig;
                float2 gv = *(const float2*)&H1[(size_t)row * FDIM + col];
                float h2v0 = c[mi][ni][half * 2]     + bias[col];
                float h2v1 = c[mi][ni][half * 2 + 1] + bias[col + 1];
                float s0 = gv.x / (1.f + __expf(-gv.x));
                float s1 = gv.y / (1.f + __expf(-gv.y));
                __nv_bfloat162 p = __floats2bfloat162_rn(s0 * h2v0, s1 * h2v1);
                *(unsigned*)&HB[(size_t)row * FDIM + col] = *(unsigned*)&p;
            }
        }
}

// MoE down GEMM + scaled scatter-add into residual output.
__global__ __launch_bounds__(256, 2) void moe_down(
    const float* __restrict__ Bo, float* __restrict__ Out)
{
    int e = blockIdx.z;
    int M = g_counts[e];
    int bm = blockIdx.y * 128;
    if (bm >= M) return;
    int bn = blockIdx.x * 128;
    const __nv_bfloat16* A = g_hb + (size_t)g_off[e] * FDIM;
    const __nv_bfloat16* B = g_bwo + (size_t)e * DMODEL * FDIM;
    const float* bias = Bo + (size_t)e * DMODEL;
    GEMM_PROLOGUE();
    gemm_bf16_core(A, B, M, FDIM, bm, bn, su, c);
    #pragma unroll
    for (int mi = 0; mi < 4; mi++)
        #pragma unroll
        for (int half = 0; half < 2; half++) {
            int row = bm + wm + (mi << 4) + g + half * 8;
            if (row >= M) continue;
            int gr = g_off[e] + row;
            int tok = g_rowTok[gr];
            float sc = g_rowScale[gr];
            #pragma unroll
            for (int ni = 0; ni < 4; ni++) {
                int col = bn + wn + (ni << 3) + 2 * tig;
                atomicAdd(&Out[(size_t)tok * DMODEL + col],
                          sc * (c[mi][ni][half * 2] + bias[col]));
                atomicAdd(&Out[(size_t)tok * DMODEL + col + 1],
                          sc * (c[mi][ni][half * 2 + 1] + bias[col + 1]));
            }
        }
}

// ---------------- tf32 flash attention (no P smem: quad-shuffle refrag) -------
// Bq=128, Bk=64, 128 threads (4 warps); warp owns 32 q-rows (2 m-frags).
// Qs/Ks stride 68 (banks 4g+tig distinct); Vs stride 72 (banks 8tig+g distinct).
#define ATTN_SMEM_FLOATS (128 * 68 + 64 * 68 + 64 * 72)

__global__ __launch_bounds__(128, 3) void flash_attn_tf32(
    const float* __restrict__ qkv, __nv_bfloat16* __restrict__ outb)
{
    extern __shared__ float sm[];
    float (*Qs)[68] = (float(*)[68])sm;
    float (*Ks)[68] = (float(*)[68])(sm + 128 * 68);
    float (*Vs)[72] = (float(*)[72])(sm + 128 * 68 + 64 * 68);

    const int tid = threadIdx.x;
    const int w = tid >> 5, lane = tid & 31;
    const int g = lane >> 2, tig = lane & 3;
    const int h = blockIdx.y;
    const int q0 = blockIdx.x * 128;
    const int m0 = w * 32;
    const int srcA = (lane & 28) | (tig >> 1);
    const int srcB = srcA + 2;
    const bool odd = (tig & 1);

    // load Q tile, pre-scaled by 1/sqrt(64)
    #pragma unroll
    for (int i = 0; i < 16; i++) {
        int f = tid + i * 128;
        int r = f >> 4, d4 = (f & 15) << 2;
        float4 v = *(const float4*)(qkv + (size_t)(q0 + r) * 1536 + h * 64 + d4);
        v.x *= 0.125f; v.y *= 0.125f; v.z *= 0.125f; v.w *= 0.125f;
        *(float4*)&Qs[r][d4] = v;
    }

    float o[2][8][4];
    #pragma unroll
    for (int mi = 0; mi < 2; mi++)
        #pragma unroll
        for (int nt = 0; nt < 8; nt++)
            #pragma unroll
            for (int j = 0; j < 4; j++) o[mi][nt][j] = 0.f;
    float mr[2][2] = {{-1e30f, -1e30f}, {-1e30f, -1e30f}};
    float lr[2][2] = {{0.f, 0.f}, {0.f, 0.f}};

    for (int k0 = 0; k0 < SEQ; k0 += 64) {
        __syncthreads();   // prior iter's K/V reads complete (covers Q on iter 0)
        #pragma unroll
        for (int i = 0; i < 8; i++) {
            int f = tid + i * 128;
            int col = f >> 4, d4 = (f & 15) << 2;
            const float* base = qkv + (size_t)(k0 + col) * 1536 + 512 + h * 64 + d4;
            *(float4*)&Ks[col][d4] = *(const float4*)base;
            *(float4*)&Vs[col][d4] = *(const float4*)(base + 512);
        }
        __syncthreads();

        // S = Q K^T   (32 x 64 per warp)
        float s[2][8][4];
        #pragma unroll
        for (int mi = 0; mi < 2; mi++)
            #pragma unroll
            for (int nt = 0; nt < 8; nt++)
                #pragma unroll
                for (int j = 0; j < 4; j++) s[mi][nt][j] = 0.f;
        #pragma unroll
        for (int kt = 0; kt < 8; kt++) {
            const int kb = kt << 3;
            unsigned a[2][4];
            #pragma unroll
            for (int mi = 0; mi < 2; mi++) {
                int mb = m0 + (mi << 4);
                a[mi][0] = __float_as_uint(Qs[mb + g][kb + tig]);
                a[mi][1] = __float_as_uint(Qs[mb + g + 8][kb + tig]);
                a[mi][2] = __float_as_uint(Qs[mb + g][kb + tig + 4]);
                a[mi][3] = __float_as_uint(Qs[mb + g + 8][kb + tig + 4]);
            }
            #pragma unroll
            for (int nt = 0; nt < 8; nt++) {
                unsigned b0 = __float_as_uint(Ks[(nt << 3) + g][kb + tig]);
                unsigned b1 = __float_as_uint(Ks[(nt << 3) + g][kb + tig + 4]);
                mma8(s[0][nt], a[0][0], a[0][1], a[0][2], a[0][3], b0, b1);
                mma8(s[1][nt], a[1][0], a[1][1], a[1][2], a[1][3], b0, b1);
            }
        }

        // online softmax in registers; P stays in s[][]
        #pragma unroll
        for (int mi = 0; mi < 2; mi++) {
            float mx0 = mr[mi][0], mx1 = mr[mi][1];
            #pragma unroll
            for (int nt = 0; nt < 8; nt++) {
                mx0 = fmaxf(mx0, fmaxf(s[mi][nt][0], s[mi][nt][1]));
                mx1 = fmaxf(mx1, fmaxf(s[mi][nt][2], s[mi][nt][3]));
            }
            mx0 = fmaxf(mx0, __shfl_xor_sync(0xffffffffu, mx0, 1));
            mx0 = fmaxf(mx0, __shfl_xor_sync(0xffffffffu, mx0, 2));
            mx1 = fmaxf(mx1, __shfl_xor_sync(0xffffffffu, mx1, 1));
            mx1 = fmaxf(mx1, __shfl_xor_sync(0xffffffffu, mx1, 2));
            float al0 = __expf(mr[mi][0] - mx0);
            float al1 = __expf(mr[mi][1] - mx1);
            float sum0 = 0.f, sum1 = 0.f;
            #pragma unroll
            for (int nt = 0; nt < 8; nt++) {
                s[mi][nt][0] = __expf(s[mi][nt][0] - mx0);
                s[mi][nt][1] = __expf(s[mi][nt][1] - mx0);
                s[mi][nt][2] = __expf(s[mi][nt][2] - mx1);
                s[mi][nt][3] = __expf(s[mi][nt][3] - mx1);
                sum0 += s[mi][nt][0] + s[mi][nt][1];
                sum1 += s[mi][nt][2] + s[mi][nt][3];
            }
            sum0 += __shfl_xor_sync(0xffffffffu, sum0, 1);
            sum0 += __shfl_xor_sync(0xffffffffu, sum0, 2);
            sum1 += __shfl_xor_sync(0xffffffffu, sum1, 1);
            sum1 += __shfl_xor_sync(0xffffffffu, sum1, 2);
            lr[mi][0] = lr[mi][0] * al0 + sum0; mr[mi][0] = mx0;
            lr[mi][1] = lr[mi][1] * al1 + sum1; mr[mi][1] = mx1;
            #pragma unroll
            for (int nt = 0; nt < 8; nt++) {
                o[mi][nt][0] *= al0; o[mi][nt][1] *= al0;
                o[mi][nt][2] *= al1; o[mi][nt][3] *= al1;
            }
        }

        // O += P V : refragment P (c-frag -> a-frag) via quad shuffles
        #pragma unroll
        for (int kt = 0; kt < 8; kt++) {
            const int kb = kt << 3;
            unsigned a[2][4];
            #pragma unroll
            for (int mi = 0; mi < 2; mi++) {
                float e0 = __shfl_sync(0xffffffffu, s[mi][kt][0], srcA);
                float o0 = __shfl_sync(0xffffffffu, s[mi][kt][1], srcA);
                float e2 = __shfl_sync(0xffffffffu, s[mi][kt][0], srcB);
                float o2 = __shfl_sync(0xffffffffu, s[mi][kt][1], srcB);
                float e1 = __shfl_sync(0xffffffffu, s[mi][kt][2], srcA);
                float o1 = __shfl_sync(0xffffffffu, s[mi][kt][3], srcA);
                float e3 = __shfl_sync(0xffffffffu, s[mi][kt][2], srcB);
                float o3 = __shfl_sync(0xffffffffu, s[mi][kt][3], srcB);
                a[mi][0] = __float_as_uint(odd ? o0 : e0);
                a[mi][1] = __float_as_uint(odd ? o1 : e1);
                a[mi][2] = __float_as_uint(odd ? o2 : e2);
                a[mi][3] = __float_as_uint(odd ? o3 : e3);
            }
            #pragma unroll
            for (int nt = 0; nt < 8; nt++) {
                unsigned b0 = __float_as_uint(Vs[kb + tig][(nt << 3) + g]);
                unsigned b1 = __float_as_uint(Vs[kb + tig + 4][(nt << 3) + g]);
                mma8(o[0][nt], a[0][0], a[0][1], a[0][2], a[0][3], b0, b1);
                mma8(o[1][nt], a[1][0], a[1][1], a[1][2], a[1][3], b0, b1);
            }
        }
    }

    #pragma unroll
    for (int mi = 0; mi < 2; mi++) {
        float inv0 = 1.f / lr[mi][0], inv1 = 1.f / lr[mi][1];
        int mb = m0 + (mi << 4);
        #pragma unroll
        for (int nt = 0; nt < 8; nt++) {
            int col = h * 64 + (nt << 3) + 2 * tig;
            __nv_bfloat162 r0 = __floats2bfloat162_rn(o[mi][nt][0] * inv0,
                                                      o[mi][nt][1] * inv0);
            *(unsigned*)&outb[(size_t)(q0 + mb + g) * DMODEL + col] = *(unsigned*)&r0;
            __nv_bfloat162 r1 = __floats2bfloat162_rn(o[mi][nt][2] * inv1,
                                                      o[mi][nt][3] * inv1);
            *(unsigned*)&outb[(size_t)(q0 + mb + g + 8) * DMODEL + col] = *(unsigned*)&r1;
        }
    }
}

// ---------------- gating (fp32 path: routing must match reference) ------------
__global__ __launch_bounds__(128) void gate_topk(
    const float* __restrict__ xn, const float* __restrict__ gw,
    const float* __restrict__ gb)
{
    int warp = threadIdx.x >> 5;
    int lane = threadIdx.x & 31;
    int t = blockIdx.x * 4 + warp;
    float acc[NEXP];
    #pragma unroll
    for (int e = 0; e < NEXP; e++) acc[e] = 0.f;
    for (int d = lane; d < DMODEL; d += 32) {
        float xv = xn[(size_t)t * DMODEL + d];
        #pragma unroll
        for (int e = 0; e < NEXP; e++) acc[e] = fmaf(xv, gw[e * DMODEL + d], acc[e]);
    }
    #pragma unroll
    for (int e = 0; e < NEXP; e++)
        #pragma unroll
        for (int o = 16; o > 0; o >>= 1)
            acc[e] += __shfl_xor_sync(0xffffffffu, acc[e], o);
    if (lane == 0) {
        float lg[NEXP];
        float mx = -1e30f;
        #pragma unroll
        for (int e = 0; e < NEXP; e++) { lg[e] = acc[e] + gb[e]; mx = fmaxf(mx, lg[e]); }
        float sum = 0.f;
        #pragma unroll
        for (int e = 0; e < NEXP; e++) { lg[e] = __expf(lg[e] - mx); sum += lg[e]; }
        float inv = 1.f / sum;
        int e0 = 0; float p0 = lg[0];
        #pragma unroll
        for (int e = 1; e < NEXP; e++) if (lg[e] > p0) { p0 = lg[e]; e0 = e; }
        int e1 = -1; float p1 = -1.f;
        #pragma unroll
        for (int e = 0; e < NEXP; e++)
            if (e != e0 && lg[e] > p1) { p1 = lg[e]; e1 = e; }
        g_tidx[t * 2] = e0;         g_tidx[t * 2 + 1] = e1;
        g_tscale[t * 2] = p0 * inv; g_tscale[t * 2 + 1] = p1 * inv;
        atomicAdd(&g_counts[e0], 1);
        atomicAdd(&g_counts[e1], 1);
    }
}

__global__ void zero_counts_k() {
    if (threadIdx.x < NEXP) { g_counts[threadIdx.x] = 0; g_cursor[threadIdx.x] = 0; }
}

__global__ void calc_offsets_k() {
    int o = 0;
    for (int e = 0; e < NEXP; e++) { g_off[e] = o; o += g_counts[e]; }
}

// gather tokens into expert-contiguous bf16 rows
__global__ __launch_bounds__(128) void gather_pairs()
{
    int p = blockIdx.x;
    __shared__ int posS;
    if (threadIdx.x == 0) {
        int e = g_tidx[p];
        int pos = g_off[e] + atomicAdd(&g_cursor[e], 1);
        g_rowTok[pos] = p >> 1;
        g_rowScale[pos] = g_tscale[p];
        posS = pos;
    }
    __syncthreads();
    int pos = posS;
    int t = p >> 1;
    ((uint2*)(g_xgb + (size_t)pos * DMODEL))[threadIdx.x] =
        ((const uint2*)(g_xnb + (size_t)t * DMODEL))[threadIdx.x];
}

// ---------------- launch -----------------------------------------------------
extern "C" void kernel_launch(void* const* d_in, const int* in_sizes, int n_in,
                              void* d_out, int out_size)
{
    const float* src        = (const float*)d_in[0];
    const float* in_proj_w  = (const float*)d_in[1];
    const float* in_proj_b  = (const float*)d_in[2];
    const float* out_proj_w = (const float*)d_in[3];
    const float* out_proj_b = (const float*)d_in[4];
    const float* ln1_g      = (const float*)d_in[5];
    const float* ln1_b      = (const float*)d_in[6];
    const float* ln2_g      = (const float*)d_in[7];
    const float* ln2_b      = (const float*)d_in[8];
    const float* gate_w     = (const float*)d_in[9];
    const float* gate_b     = (const float*)d_in[10];
    const float* w1         = (const float*)d_in[11];
    const float* b1         = (const float*)d_in[12];
    const float* w2         = (const float*)d_in[13];
    const float* b2         = (const float*)d_in[14];
    const float* wo         = (const float*)d_in[15];
    const float* bo         = (const float*)d_in[16];
    float* out = (float*)d_out;

    float *xn, *qkv;
    __nv_bfloat16 *xnb, *attnb, *bwin, *bwout, *bw1, *bw2, *bwo;
    cudaGetSymbolAddress((void**)&xn,    g_xn);
    cudaGetSymbolAddress((void**)&qkv,   g_qkv);
    cudaGetSymbolAddress((void**)&xnb,   g_xnb);
    cudaGetSymbolAddress((void**)&attnb, g_attnb);
    cudaGetSymbolAddress((void**)&bwin,  g_bwin);
    cudaGetSymbolAddress((void**)&bwout, g_bwout);
    cudaGetSymbolAddress((void**)&bw1,   g_bw1);
    cudaGetSymbolAddress((void**)&bw2,   g_bw2);
    cudaGetSymbolAddress((void**)&bwo,   g_bwo);

    const int attn_smem = ATTN_SMEM_FLOATS * 4;
    cudaFuncSetAttribute(flash_attn_tf32,
                         cudaFuncAttributeMaxDynamicSharedMemorySize, attn_smem);

    // weight converts (fp32 -> bf16), counts all divisible by 1024
    f2bf_k<<<3 * DMODEL * DMODEL / 1024, 256>>>(in_proj_w, bwin);
    f2bf_k<<<DMODEL * DMODEL / 1024, 256>>>(out_proj_w, bwout);
    f2bf_k<<<NEXP * FDIM * DMODEL / 1024, 256>>>(w1, bw1);
    f2bf_k<<<NEXP * FDIM * DMODEL / 1024, 256>>>(w2, bw2);
    f2bf_k<<<NEXP * DMODEL * FDIM / 1024, 256>>>(wo, bwo);

    zero_counts_k<<<1, 32>>>();

    // ---- attention block ----
    layernorm_k<<<SEQ, 128>>>(src, ln1_g, ln1_b, xn, xnb);
    gemm_bf16_nt<<<dim3(12, 32), 256>>>(xnb, bwin, in_proj_b, nullptr, qkv,
                                        SEQ, 3 * DMODEL, DMODEL);
    flash_attn_tf32<<<dim3(SEQ / 128, NHEAD), 128, attn_smem>>>(qkv, attnb);
    gemm_bf16_nt<<<dim3(4, 32), 256>>>(attnb, bwout, out_proj_b, src, out,
                                       SEQ, DMODEL, DMODEL);

    // ---- MoE block ----
    layernorm_k<<<SEQ, 128>>>(out, ln2_g, ln2_b, xn, xnb);
    gate_topk<<<SEQ / 4, 128>>>(xn, gate_w, gate_b);
    calc_offsets_k<<<1, 1>>>();
    gather_pairs<<<NPAIR, 128>>>();
    moe_up1<<<dim3(FDIM / 128, 64, NEXP), 256>>>(b1);
    moe_up2<<<dim3(FDIM / 128, 64, NEXP), 256>>>(b2);
    moe_down<<<dim3(DMODEL / 128, 64, NEXP), 256>>>(bo, out);
}

// round 6
// speedup vs baseline: 5.3018x; 1.2543x over previous
#include <cuda_runtime.h>
#include <cuda_bf16.h>
#include <math.h>

#define SEQ 4096
#define DMODEL 512
#define NHEAD 8
#define FDIM 2048
#define NEXP 8
#define NPAIR (SEQ * 2)

// ---------------- scratch (device globals; no allocations allowed) ----------
__device__ float g_xn[SEQ * DMODEL];                 // fp32 LN out (gate path)
__device__ __nv_bfloat16 g_xnb[SEQ * DMODEL];        // bf16 LN out (GEMM A)
__device__ __nv_bfloat16 g_qkvb[SEQ * 3 * DMODEL];   // bf16 qkv (Q pre-scaled)
__device__ __nv_bfloat16 g_attnb[SEQ * DMODEL];
__device__ __nv_bfloat16 g_xgb[NPAIR * DMODEL];
__device__ float g_h1[NPAIR * FDIM];
__device__ __nv_bfloat16 g_hb[NPAIR * FDIM];
__device__ __nv_bfloat16 g_bwin[3 * DMODEL * DMODEL];
__device__ __nv_bfloat16 g_bwout[DMODEL * DMODEL];
__device__ __nv_bfloat16 g_bw1[NEXP * FDIM * DMODEL];
__device__ __nv_bfloat16 g_bw2[NEXP * FDIM * DMODEL];
__device__ __nv_bfloat16 g_bwo[NEXP * DMODEL * FDIM];
__device__ int   g_tidx[NPAIR];
__device__ float g_tscale[NPAIR];
__device__ int   g_counts[NEXP];
__device__ int   g_cursor[NEXP];
__device__ int   g_off[NEXP];
__device__ int   g_rowTok[NPAIR];
__device__ float g_rowScale[NPAIR];

// ---------------- helpers -----------------------------------------------------
__device__ __forceinline__ void mma16(float c[4],
    unsigned a0, unsigned a1, unsigned a2, unsigned a3,
    unsigned b0, unsigned b1)
{
    asm volatile(
        "mma.sync.aligned.m16n8k16.row.col.f32.bf16.bf16.f32 "
        "{%0,%1,%2,%3}, {%4,%5,%6,%7}, {%8,%9}, {%0,%1,%2,%3};\n"
        : "+f"(c[0]), "+f"(c[1]), "+f"(c[2]), "+f"(c[3])
        : "r"(a0), "r"(a1), "r"(a2), "r"(a3), "r"(b0), "r"(b1));
}

__device__ __forceinline__ void ldsm4t(unsigned& r0, unsigned& r1,
                                       unsigned& r2, unsigned& r3, unsigned addr)
{
    asm volatile(
        "ldmatrix.sync.aligned.m8n8.x4.trans.shared.b16 {%0,%1,%2,%3}, [%4];\n"
        : "=r"(r0), "=r"(r1), "=r"(r2), "=r"(r3) : "r"(addr));
}

__device__ __forceinline__ unsigned smem_u32(const void* p) {
    return (unsigned)__cvta_generic_to_shared(p);
}
__device__ __forceinline__ void cpa16(unsigned dst, const void* src, int vbytes) {
    asm volatile("cp.async.cg.shared.global [%0], [%1], 16, %2;\n"
                 :: "r"(dst), "l"(src), "r"(vbytes) : "memory");
}
__device__ __forceinline__ void cpa_commit() {
    asm volatile("cp.async.commit_group;\n" ::: "memory");
}
__device__ __forceinline__ unsigned packbf(float a, float b) {
    __nv_bfloat162 p = __floats2bfloat162_rn(a, b);
    return *(unsigned*)&p;
}

// ---------------- fp32 -> bf16 array convert (weights, once per launch) ------
__global__ __launch_bounds__(256) void f2bf_k(const float* __restrict__ in,
                                              __nv_bfloat16* __restrict__ out)
{
    size_t i = (size_t)blockIdx.x * 256 + threadIdx.x;   // per 4 elems
    float4 v = ((const float4*)in)[i];
    uint2 u; u.x = packbf(v.x, v.y); u.y = packbf(v.z, v.w);
    ((uint2*)out)[i] = u;
}

// ---------------- layernorm (dual fp32 + bf16 output) -------------------------
__global__ __launch_bounds__(128) void layernorm_k(
    const float* __restrict__ x, const float* __restrict__ g,
    const float* __restrict__ b, float* __restrict__ y,
    __nv_bfloat16* __restrict__ yb)
{
    int t = blockIdx.x;
    int tid = threadIdx.x;
    float4 v = ((const float4*)(x + (size_t)t * DMODEL))[tid];
    float s  = v.x + v.y + v.z + v.w;
    float ss = v.x * v.x + v.y * v.y + v.z * v.z + v.w * v.w;
    #pragma unroll
    for (int o = 16; o > 0; o >>= 1) {
        s  += __shfl_xor_sync(0xffffffffu, s, o);
        ss += __shfl_xor_sync(0xffffffffu, ss, o);
    }
    __shared__ float sw[4], ssw[4];
    __shared__ float meanS, rstdS;
    int lane = tid & 31, w = tid >> 5;
    if (lane == 0) { sw[w] = s; ssw[w] = ss; }
    __syncthreads();
    if (tid == 0) {
        float S = sw[0] + sw[1] + sw[2] + sw[3];
        float SS = ssw[0] + ssw[1] + ssw[2] + ssw[3];
        float mean = S / (float)DMODEL;
        float var = SS / (float)DMODEL - mean * mean;
        meanS = mean;
        rstdS = rsqrtf(var + 1e-5f);
    }
    __syncthreads();
    float mean = meanS, rstd = rstdS;
    float4 gg = ((const float4*)g)[tid];
    float4 bb = ((const float4*)b)[tid];
    float4 o;
    o.x = (v.x - mean) * rstd * gg.x + bb.x;
    o.y = (v.y - mean) * rstd * gg.y + bb.y;
    o.z = (v.z - mean) * rstd * gg.z + bb.z;
    o.w = (v.w - mean) * rstd * gg.w + bb.w;
    ((float4*)(y + (size_t)t * DMODEL))[tid] = o;
    uint2 u; u.x = packbf(o.x, o.y); u.y = packbf(o.z, o.w);
    ((uint2*)(yb + (size_t)t * DMODEL))[tid] = u;
}

// ---------------- bf16 GEMM core: C[M,N] = A[M,K] * B[N,K]^T ------------------
// BM=BN=128, BK=32, 256 threads (8 warps 2x4), warp tile 64x32, m16n8k16.
// cp.async double-buffered, smem 40KB static -> 2 CTAs/SM.
__device__ __forceinline__ void gemm_bf16_core(
    const __nv_bfloat16* __restrict__ A, const __nv_bfloat16* __restrict__ B,
    int M, int K, int bm, int bn, unsigned* su, float c[4][4][4])
{
    const int tid = threadIdx.x;
    const int lane = tid & 31, g = lane >> 2, tig = lane & 3;
    const int w = tid >> 5, wm = (w >> 2) << 6, wn = (w & 3) << 5;
    const int r = tid >> 1;
    const int seg0 = (tid & 1) << 1;
    const int nk = K >> 5;
    const int arow = (bm + r < M) ? (bm + r) : 0;
    const int av = (bm + r < M) ? 16 : 0;
    const __nv_bfloat16* Ar = A + (size_t)arow * K;
    const __nv_bfloat16* Br = B + (size_t)(bn + r) * K;
    const unsigned dstA = smem_u32(su) + (unsigned)(r * 20) * 4;
    const unsigned dstB = dstA + 5120 * 4;

    #define GEMM_ISSUE(kt_) do {                                           \
        int buf_ = (kt_) & 1;                                              \
        int k0_ = (kt_) << 5;                                              \
        _Pragma("unroll")                                                  \
        for (int i_ = 0; i_ < 2; i_++) {                                   \
            int seg_ = seg0 + i_;                                          \
            cpa16(dstA + buf_ * 10240 + seg_ * 16, Ar + k0_ + seg_ * 8, av);\
            cpa16(dstB + buf_ * 10240 + seg_ * 16, Br + k0_ + seg_ * 8, 16);\
        }                                                                  \
        cpa_commit();                                                      \
    } while (0)

    GEMM_ISSUE(0);
    GEMM_ISSUE(1);

    for (int kt = 0; kt < nk; kt++) {
        if (kt < nk - 2) asm volatile("cp.async.wait_group 1;\n" ::: "memory");
        else             asm volatile("cp.async.wait_group 0;\n" ::: "memory");
        __syncthreads();
        const unsigned* Au = su + (kt & 1) * 2560;
        const unsigned* Bu = su + 5120 + (kt & 1) * 2560;
        #pragma unroll
        for (int kk = 0; kk < 2; kk++) {
            const int kb = kk << 3;
            unsigned a[4][4], b[4][2];
            #pragma unroll
            for (int mi = 0; mi < 4; mi++) {
                int m = wm + (mi << 4);
                a[mi][0] = Au[(m + g) * 20 + kb + tig];
                a[mi][1] = Au[(m + g + 8) * 20 + kb + tig];
                a[mi][2] = Au[(m + g) * 20 + kb + tig + 4];
                a[mi][3] = Au[(m + g + 8) * 20 + kb + tig + 4];
            }
            #pragma unroll
            for (int ni = 0; ni < 4; ni++) {
                int n = wn + (ni << 3);
                b[ni][0] = Bu[(n + g) * 20 + kb + tig];
                b[ni][1] = Bu[(n + g) * 20 + kb + tig + 4];
            }
            #pragma unroll
            for (int mi = 0; mi < 4; mi++)
                #pragma unroll
                for (int ni = 0; ni < 4; ni++)
                    mma16(c[mi][ni], a[mi][0], a[mi][1], a[mi][2], a[mi][3],
                          b[ni][0], b[ni][1]);
        }
        __syncthreads();
        if (kt + 2 < nk) GEMM_ISSUE(kt + 2);
    }
    #undef GEMM_ISSUE
}

#define GEMM_PROLOGUE() \
    __shared__ unsigned su[10240]; \
    float c[4][4][4]; \
    _Pragma("unroll") \
    for (int mi = 0; mi < 4; mi++) \
        _Pragma("unroll") \
        for (int ni = 0; ni < 4; ni++) \
            _Pragma("unroll") \
            for (int j = 0; j < 4; j++) c[mi][ni][j] = 0.f; \
    const int lane = threadIdx.x & 31; \
    const int g = lane >> 2, tig = lane & 3; \
    const int w = threadIdx.x >> 5; \
    const int wm = (w >> 2) << 6, wn = (w & 3) << 5;

// GEMM + bias + optional residual, fp32 out.
__global__ __launch_bounds__(256, 2) void gemm_bf16_nt(
    const __nv_bfloat16* __restrict__ A, const __nv_bfloat16* __restrict__ B,
    const float* __restrict__ bias, const float* __restrict__ resid,
    float* __restrict__ C, int M, int N, int K)
{
    const int bm = blockIdx.y * 128;
    const int bn = blockIdx.x * 128;
    GEMM_PROLOGUE();
    gemm_bf16_core(A, B, M, K, bm, bn, su, c);
    #pragma unroll
    for (int mi = 0; mi < 4; mi++)
        #pragma unroll
        for (int half = 0; half < 2; half++) {
            int row = bm + wm + (mi << 4) + g + half * 8;
            if (row >= M) continue;
            #pragma unroll
            for (int ni = 0; ni < 4; ni++) {
                int col = bn + wn + (ni << 3) + 2 * tig;
                float v0 = c[mi][ni][half * 2]     + bias[col];
                float v1 = c[mi][ni][half * 2 + 1] + bias[col + 1];
                if (resid) {
                    v0 += resid[(size_t)row * N + col];
                    v1 += resid[(size_t)row * N + col + 1];
                }
                float2 v; v.x = v0; v.y = v1;
                *(float2*)&C[(size_t)row * N + col] = v;
            }
        }
}

// QKV GEMM: bf16 out, Q columns (col < DMODEL) pre-scaled by 1/sqrt(64).
__global__ __launch_bounds__(256, 2) void gemm_qkv(
    const __nv_bfloat16* __restrict__ A, const __nv_bfloat16* __restrict__ B,
    const float* __restrict__ bias, __nv_bfloat16* __restrict__ C,
    int M, int N, int K)
{
    const int bm = blockIdx.y * 128;
    const int bn = blockIdx.x * 128;
    GEMM_PROLOGUE();
    gemm_bf16_core(A, B, M, K, bm, bn, su, c);
    #pragma unroll
    for (int mi = 0; mi < 4; mi++)
        #pragma unroll
        for (int half = 0; half < 2; half++) {
            int row = bm + wm + (mi << 4) + g + half * 8;
            #pragma unroll
            for (int ni = 0; ni < 4; ni++) {
                int col = bn + wn + (ni << 3) + 2 * tig;
                float sc = (col < DMODEL) ? 0.125f : 1.f;
                float v0 = (c[mi][ni][half * 2]     + bias[col]) * sc;
                float v1 = (c[mi][ni][half * 2 + 1] + bias[col + 1]) * sc;
                *(unsigned*)&C[(size_t)row * N + col] = packbf(v0, v1);
            }
        }
}

// MoE up-proj #1: g_h1 = x@w1^T + b1 (fp32 out)
__global__ __launch_bounds__(256, 2) void moe_up1(const float* __restrict__ Ball)
{
    int e = blockIdx.z;
    int M = g_counts[e];
    int bm = blockIdx.y * 128;
    if (bm >= M) return;
    int bn = blockIdx.x * 128;
    const __nv_bfloat16* A = g_xgb + (size_t)g_off[e] * DMODEL;
    const __nv_bfloat16* B = g_bw1 + (size_t)e * FDIM * DMODEL;
    const float* bias = Ball + (size_t)e * FDIM;
    float* C = g_h1 + (size_t)g_off[e] * FDIM;
    GEMM_PROLOGUE();
    gemm_bf16_core(A, B, M, DMODEL, bm, bn, su, c);
    #pragma unroll
    for (int mi = 0; mi < 4; mi++)
        #pragma unroll
        for (int half = 0; half < 2; half++) {
            int row = bm + wm + (mi << 4) + g + half * 8;
            if (row >= M) continue;
            #pragma unroll
            for (int ni = 0; ni < 4; ni++) {
                int col = bn + wn + (ni << 3) + 2 * tig;
                float2 v;
                v.x = c[mi][ni][half * 2]     + bias[col];
                v.y = c[mi][ni][half * 2 + 1] + bias[col + 1];
                *(float2*)&C[(size_t)row * FDIM + col] = v;
            }
        }
}

// MoE up-proj #2 fused: g_hb = bf16( silu(h1) * (x@w2^T + b2) )
__global__ __launch_bounds__(256, 2) void moe_up2(const float* __restrict__ Ball)
{
    int e = blockIdx.z;
    int M = g_counts[e];
    int bm = blockIdx.y * 128;
    if (bm >= M) return;
    int bn = blockIdx.x * 128;
    const __nv_bfloat16* A = g_xgb + (size_t)g_off[e] * DMODEL;
    const __nv_bfloat16* B = g_bw2 + (size_t)e * FDIM * DMODEL;
    const float* bias = Ball + (size_t)e * FDIM;
    const float* H1 = g_h1 + (size_t)g_off[e] * FDIM;
    __nv_bfloat16* HB = g_hb + (size_t)g_off[e] * FDIM;
    GEMM_PROLOGUE();
    gemm_bf16_core(A, B, M, DMODEL, bm, bn, su, c);
    #pragma unroll
    for (int mi = 0; mi < 4; mi++)
        #pragma unroll
        for (int half = 0; half < 2; half++) {
            int row = bm + wm + (mi << 4) + g + half * 8;
            if (row >= M) continue;
            #pragma unroll
            for (int ni = 0; ni < 4; ni++) {
                int col = bn + wn + (ni << 3) + 2 * tig;
                float2 gv = *(const float2*)&H1[(size_t)row * FDIM + col];
                float h2v0 = c[mi][ni][half * 2]     + bias[col];
                float h2v1 = c[mi][ni][half * 2 + 1] + bias[col + 1];
                float s0 = gv.x / (1.f + __expf(-gv.x));
                float s1 = gv.y / (1.f + __expf(-gv.y));
                *(unsigned*)&HB[(size_t)row * FDIM + col] = packbf(s0 * h2v0, s1 * h2v1);
            }
        }
}

// MoE down GEMM + scaled scatter-add into residual output.
__global__ __launch_bounds__(256, 2) void moe_down(
    const float* __restrict__ Bo, float* __restrict__ Out)
{
    int e = blockIdx.z;
    int M = g_counts[e];
    int bm = blockIdx.y * 128;
    if (bm >= M) return;
    int bn = blockIdx.x * 128;
    const __nv_bfloat16* A = g_hb + (size_t)g_off[e] * FDIM;
    const __nv_bfloat16* B = g_bwo + (size_t)e * DMODEL * FDIM;
    const float* bias = Bo + (size_t)e * DMODEL;
    GEMM_PROLOGUE();
    gemm_bf16_core(A, B, M, FDIM, bm, bn, su, c);
    #pragma unroll
    for (int mi = 0; mi < 4; mi++)
        #pragma unroll
        for (int half = 0; half < 2; half++) {
            int row = bm + wm + (mi << 4) + g + half * 8;
            if (row >= M) continue;
            int gr = g_off[e] + row;
            int tok = g_rowTok[gr];
            float sc = g_rowScale[gr];
            #pragma unroll
            for (int ni = 0; ni < 4; ni++) {
                int col = bn + wn + (ni << 3) + 2 * tig;
                atomicAdd(&Out[(size_t)tok * DMODEL + col],
                          sc * (c[mi][ni][half * 2] + bias[col]));
                atomicAdd(&Out[(size_t)tok * DMODEL + col + 1],
                          sc * (c[mi][ni][half * 2 + 1] + bias[col + 1]));
            }
        }
}

// ---------------- bf16 flash attention ----------------------------------------
// Bq=128, Bk=64, 128 threads (4 warps); warp owns 32 q-rows (2 m16-frags).
// m16n8k16 everywhere. S c-frag repacks DIRECTLY into PV a-frag (no shuffles).
// V B-frags via ldmatrix.x4.trans on natural [k][d] layout.
// Q/K/V smem rows: 32 uints (bf16 pairs) + 4 pad = stride 36 (conflict-free).
__global__ __launch_bounds__(128, 3) void flash_attn_bf16(
    const __nv_bfloat16* __restrict__ qkv, __nv_bfloat16* __restrict__ outb)
{
    __shared__ unsigned Qu[128][36];
    __shared__ unsigned Ku[64][36];
    __shared__ unsigned Vu[64][36];

    const int tid = threadIdx.x;
    const int w = tid >> 5, lane = tid & 31;
    const int g = lane >> 2, tig = lane & 3;
    const int h = blockIdx.y;
    const int q0 = blockIdx.x * 128;
    const int m0 = w * 32;

    // load Q tile (already scaled by 1/8 in qkv GEMM): 1024 uint4
    #pragma unroll
    for (int i = 0; i < 8; i++) {
        int f = tid + i * 128;
        int r = f >> 3, u4 = (f & 7) << 2;
        *(uint4*)&Qu[r][u4] =
            *(const uint4*)(qkv + (size_t)(q0 + r) * 1536 + h * 64 + (u4 << 1));
    }

    float o[2][8][4];
    #pragma unroll
    for (int mi = 0; mi < 2; mi++)
        #pragma unroll
        for (int nt = 0; nt < 8; nt++)
            #pragma unroll
            for (int j = 0; j < 4; j++) o[mi][nt][j] = 0.f;
    float mr[2][2] = {{-1e30f, -1e30f}, {-1e30f, -1e30f}};
    float lr[2][2] = {{0.f, 0.f}, {0.f, 0.f}};

    // ldmatrix source address (per-lane): tile t = lane>>3, row = lane&7
    const int lt = lane >> 3, lrow = lane & 7;
    const int koff = ((lt & 1) << 3) + lrow;   // k row within 16-block
    const int doff = (lt >> 1) << 2;           // uint offset within 16-d block (8 bf16)

    for (int k0 = 0; k0 < SEQ; k0 += 64) {
        __syncthreads();
        #pragma unroll
        for (int i = 0; i < 4; i++) {
            int f = tid + i * 128;
            int col = f >> 3, u4 = (f & 7) << 2;
            const __nv_bfloat16* base =
                qkv + (size_t)(k0 + col) * 1536 + 512 + h * 64 + (u4 << 1);
            *(uint4*)&Ku[col][u4] = *(const uint4*)base;
            *(uint4*)&Vu[col][u4] = *(const uint4*)(base + 512);
        }
        __syncthreads();

        // S = Q K^T  (32 x 64 per warp, k16 steps)
        float s[2][8][4];
        #pragma unroll
        for (int mi = 0; mi < 2; mi++)
            #pragma unroll
            for (int nt = 0; nt < 8; nt++)
                #pragma unroll
                for (int j = 0; j < 4; j++) s[mi][nt][j] = 0.f;
        #pragma unroll
        for (int kt = 0; kt < 4; kt++) {
            const int kb = kt << 3;
            unsigned a[2][4];
            #pragma unroll
            for (int mi = 0; mi < 2; mi++) {
                int mb = m0 + (mi << 4);
                a[mi][0] = Qu[mb + g][kb + tig];
                a[mi][1] = Qu[mb + g + 8][kb + tig];
                a[mi][2] = Qu[mb + g][kb + tig + 4];
                a[mi][3] = Qu[mb + g + 8][kb + tig + 4];
            }
            #pragma unroll
            for (int nt = 0; nt < 8; nt++) {
                unsigned b0 = Ku[(nt << 3) + g][kb + tig];
                unsigned b1 = Ku[(nt << 3) + g][kb + tig + 4];
                mma16(s[0][nt], a[0][0], a[0][1], a[0][2], a[0][3], b0, b1);
                mma16(s[1][nt], a[1][0], a[1][1], a[1][2], a[1][3], b0, b1);
            }
        }

        // online softmax in registers
        #pragma unroll
        for (int mi = 0; mi < 2; mi++) {
            float mx0 = mr[mi][0], mx1 = mr[mi][1];
            #pragma unroll
            for (int nt = 0; nt < 8; nt++) {
                mx0 = fmaxf(mx0, fmaxf(s[mi][nt][0], s[mi][nt][1]));
                mx1 = fmaxf(mx1, fmaxf(s[mi][nt][2], s[mi][nt][3]));
            }
            mx0 = fmaxf(mx0, __shfl_xor_sync(0xffffffffu, mx0, 1));
            mx0 = fmaxf(mx0, __shfl_xor_sync(0xffffffffu, mx0, 2));
            mx1 = fmaxf(mx1, __shfl_xor_sync(0xffffffffu, mx1, 1));
            mx1 = fmaxf(mx1, __shfl_xor_sync(0xffffffffu, mx1, 2));
            float al0 = __expf(mr[mi][0] - mx0);
            float al1 = __expf(mr[mi][1] - mx1);
            float sum0 = 0.f, sum1 = 0.f;
            #pragma unroll
            for (int nt = 0; nt < 8; nt++) {
                s[mi][nt][0] = __expf(s[mi][nt][0] - mx0);
                s[mi][nt][1] = __expf(s[mi][nt][1] - mx0);
                s[mi][nt][2] = __expf(s[mi][nt][2] - mx1);
                s[mi][nt][3] = __expf(s[mi][nt][3] - mx1);
                sum0 += s[mi][nt][0] + s[mi][nt][1];
                sum1 += s[mi][nt][2] + s[mi][nt][3];
            }
            sum0 += __shfl_xor_sync(0xffffffffu, sum0, 1);
            sum0 += __shfl_xor_sync(0xffffffffu, sum0, 2);
            sum1 += __shfl_xor_sync(0xffffffffu, sum1, 1);
            sum1 += __shfl_xor_sync(0xffffffffu, sum1, 2);
            lr[mi][0] = lr[mi][0] * al0 + sum0; mr[mi][0] = mx0;
            lr[mi][1] = lr[mi][1] * al1 + sum1; mr[mi][1] = mx1;
            #pragma unroll
            for (int nt = 0; nt < 8; nt++) {
                o[mi][nt][0] *= al0; o[mi][nt][1] *= al0;
                o[mi][nt][2] *= al1; o[mi][nt][3] *= al1;
            }
        }

        // O += P V : c-frag packs directly into a-frag; V via ldmatrix.trans
        #pragma unroll
        for (int kt = 0; kt < 4; kt++) {
            unsigned a[2][4];
            #pragma unroll
            for (int mi = 0; mi < 2; mi++) {
                a[mi][0] = packbf(s[mi][2*kt][0],   s[mi][2*kt][1]);
                a[mi][1] = packbf(s[mi][2*kt][2],   s[mi][2*kt][3]);
                a[mi][2] = packbf(s[mi][2*kt+1][0], s[mi][2*kt+1][1]);
                a[mi][3] = packbf(s[mi][2*kt+1][2], s[mi][2*kt+1][3]);
            }
            const int krow = (kt << 4) + koff;
            #pragma unroll
            for (int ntp = 0; ntp < 4; ntp++) {
                unsigned b0, b1, b2, b3;
                ldsm4t(b0, b1, b2, b3, smem_u32(&Vu[krow][(ntp << 3) + doff]));
                mma16(o[0][2*ntp],   a[0][0], a[0][1], a[0][2], a[0][3], b0, b1);
                mma16(o[1][2*ntp],   a[1][0], a[1][1], a[1][2], a[1][3], b0, b1);
                mma16(o[0][2*ntp+1], a[0][0], a[0][1], a[0][2], a[0][3], b2, b3);
                mma16(o[1][2*ntp+1], a[1][0], a[1][1], a[1][2], a[1][3], b2, b3);
            }
        }
    }

    #pragma unroll
    for (int mi = 0; mi < 2; mi++) {
        float inv0 = 1.f / lr[mi][0], inv1 = 1.f / lr[mi][1];
        int mb = m0 + (mi << 4);
        #pragma unroll
        for (int nt = 0; nt < 8; nt++) {
            int col = h * 64 + (nt << 3) + 2 * tig;
            *(unsigned*)&outb[(size_t)(q0 + mb + g) * DMODEL + col] =
                packbf(o[mi][nt][0] * inv0, o[mi][nt][1] * inv0);
            *(unsigned*)&outb[(size_t)(q0 + mb + g + 8) * DMODEL + col] =
                packbf(o[mi][nt][2] * inv1, o[mi][nt][3] * inv1);
        }
    }
}

// ---------------- gating (fp32 path: routing must match reference) ------------
__global__ __launch_bounds__(128) void gate_topk(
    const float* __restrict__ xn, const float* __restrict__ gw,
    const float* __restrict__ gb)
{
    int warp = threadIdx.x >> 5;
    int lane = threadIdx.x & 31;
    int t = blockIdx.x * 4 + warp;
    float acc[NEXP];
    #pragma unroll
    for (int e = 0; e < NEXP; e++) acc[e] = 0.f;
    for (int d = lane; d < DMODEL; d += 32) {
        float xv = xn[(size_t)t * DMODEL + d];
        #pragma unroll
        for (int e = 0; e < NEXP; e++) acc[e] = fmaf(xv, gw[e * DMODEL + d], acc[e]);
    }
    #pragma unroll
    for (int e = 0; e < NEXP; e++)
        #pragma unroll
        for (int o = 16; o > 0; o >>= 1)
            acc[e] += __shfl_xor_sync(0xffffffffu, acc[e], o);
    if (lane == 0) {
        float lg[NEXP];
        float mx = -1e30f;
        #pragma unroll
        for (int e = 0; e < NEXP; e++) { lg[e] = acc[e] + gb[e]; mx = fmaxf(mx, lg[e]); }
        float sum = 0.f;
        #pragma unroll
        for (int e = 0; e < NEXP; e++) { lg[e] = __expf(lg[e] - mx); sum += lg[e]; }
        float inv = 1.f / sum;
        int e0 = 0; float p0 = lg[0];
        #pragma unroll
        for (int e = 1; e < NEXP; e++) if (lg[e] > p0) { p0 = lg[e]; e0 = e; }
        int e1 = -1; float p1 = -1.f;
        #pragma unroll
        for (int e = 0; e < NEXP; e++)
            if (e != e0 && lg[e] > p1) { p1 = lg[e]; e1 = e; }
        g_tidx[t * 2] = e0;         g_tidx[t * 2 + 1] = e1;
        g_tscale[t * 2] = p0 * inv; g_tscale[t * 2 + 1] = p1 * inv;
        atomicAdd(&g_counts[e0], 1);
        atomicAdd(&g_counts[e1], 1);
    }
}

__global__ void zero_counts_k() {
    if (threadIdx.x < NEXP) { g_counts[threadIdx.x] = 0; g_cursor[threadIdx.x] = 0; }
}

__global__ void calc_offsets_k() {
    int o = 0;
    for (int e = 0; e < NEXP; e++) { g_off[e] = o; o += g_counts[e]; }
}

__global__ __launch_bounds__(128) void gather_pairs()
{
    int p = blockIdx.x;
    __shared__ int posS;
    if (threadIdx.x == 0) {
        int e = g_tidx[p];
        int pos = g_off[e] + atomicAdd(&g_cursor[e], 1);
        g_rowTok[pos] = p >> 1;
        g_rowScale[pos] = g_tscale[p];
        posS = pos;
    }
    __syncthreads();
    int pos = posS;
    int t = p >> 1;
    ((uint2*)(g_xgb + (size_t)pos * DMODEL))[threadIdx.x] =
        ((const uint2*)(g_xnb + (size_t)t * DMODEL))[threadIdx.x];
}

// ---------------- launch -----------------------------------------------------
extern "C" void kernel_launch(void* const* d_in, const int* in_sizes, int n_in,
                              void* d_out, int out_size)
{
    const float* src        = (const float*)d_in[0];
    const float* in_proj_w  = (const float*)d_in[1];
    const float* in_proj_b  = (const float*)d_in[2];
    const float* out_proj_w = (const float*)d_in[3];
    const float* out_proj_b = (const float*)d_in[4];
    const float* ln1_g      = (const float*)d_in[5];
    const float* ln1_b      = (const float*)d_in[6];
    const float* ln2_g      = (const float*)d_in[7];
    const float* ln2_b      = (const float*)d_in[8];
    const float* gate_w     = (const float*)d_in[9];
    const float* gate_b     = (const float*)d_in[10];
    const float* w1         = (const float*)d_in[11];
    const float* b1         = (const float*)d_in[12];
    const float* w2         = (const float*)d_in[13];
    const float* b2         = (const float*)d_in[14];
    const float* wo         = (const float*)d_in[15];
    const float* bo         = (const float*)d_in[16];
    float* out = (float*)d_out;

    float *xn;
    __nv_bfloat16 *xnb, *qkvb, *attnb, *bwin, *bwout, *bw1, *bw2, *bwo;
    cudaGetSymbolAddress((void**)&xn,    g_xn);
    cudaGetSymbolAddress((void**)&xnb,   g_xnb);
    cudaGetSymbolAddress((void**)&qkvb,  g_qkvb);
    cudaGetSymbolAddress((void**)&attnb, g_attnb);
    cudaGetSymbolAddress((void**)&bwin,  g_bwin);
    cudaGetSymbolAddress((void**)&bwout, g_bwout);
    cudaGetSymbolAddress((void**)&bw1,   g_bw1);
    cudaGetSymbolAddress((void**)&bw2,   g_bw2);
    cudaGetSymbolAddress((void**)&bwo,   g_bwo);

    // weight converts (fp32 -> bf16)
    f2bf_k<<<3 * DMODEL * DMODEL / 1024, 256>>>(in_proj_w, bwin);
    f2bf_k<<<DMODEL * DMODEL / 1024, 256>>>(out_proj_w, bwout);
    f2bf_k<<<NEXP * FDIM * DMODEL / 1024, 256>>>(w1, bw1);
    f2bf_k<<<NEXP * FDIM * DMODEL / 1024, 256>>>(w2, bw2);
    f2bf_k<<<NEXP * DMODEL * FDIM / 1024, 256>>>(wo, bwo);

    zero_counts_k<<<1, 32>>>();

    // ---- attention block ----
    layernorm_k<<<SEQ, 128>>>(src, ln1_g, ln1_b, xn, xnb);
    gemm_qkv<<<dim3(12, 32), 256>>>(xnb, bwin, in_proj_b, qkvb,
                                    SEQ, 3 * DMODEL, DMODEL);
    flash_attn_bf16<<<dim3(SEQ / 128, NHEAD), 128>>>(qkvb, attnb);
    gemm_bf16_nt<<<dim3(4, 32), 256>>>(attnb, bwout, out_proj_b, src, out,
                                       SEQ, DMODEL, DMODEL);

    // ---- MoE block ----
    layernorm_k<<<SEQ, 128>>>(out, ln2_g, ln2_b, xn, xnb);
    gate_topk<<<SEQ / 4, 128>>>(xn, gate_w, gate_b);
    calc_offsets_k<<<1, 1>>>();
    gather_pairs<<<NPAIR, 128>>>();
    moe_up1<<<dim3(FDIM / 128, 64, NEXP), 256>>>(b1);
    moe_up2<<<dim3(FDIM / 128, 64, NEXP), 256>>>(b2);
    moe_down<<<dim3(DMODEL / 128, 64, NEXP), 256>>>(bo, out);
}

// round 7
// speedup vs baseline: 5.7234x; 1.0795x over previous
#include <cuda_runtime.h>
#include <cuda_bf16.h>
#include <math.h>

#define SEQ 4096
#define DMODEL 512
#define NHEAD 8
#define FDIM 2048
#define NEXP 8
#define NPAIR (SEQ * 2)
#define MAXTILE 80

// ---------------- scratch (device globals; no allocations allowed) ----------
__device__ float g_xn[SEQ * DMODEL];                 // fp32 LN out (gate path)
__device__ __nv_bfloat16 g_xnb[SEQ * DMODEL];        // bf16 LN out (GEMM A)
__device__ __nv_bfloat16 g_qkvb[SEQ * 3 * DMODEL];   // bf16 qkv (Q pre-scaled)
__device__ __nv_bfloat16 g_attnb[SEQ * DMODEL];
__device__ __nv_bfloat16 g_xgb[NPAIR * DMODEL];
__device__ __nv_bfloat16 g_h1b[NPAIR * FDIM];
__device__ __nv_bfloat16 g_hb[NPAIR * FDIM];
__device__ __nv_bfloat16 g_bwin[3 * DMODEL * DMODEL];
__device__ __nv_bfloat16 g_bwout[DMODEL * DMODEL];
__device__ __nv_bfloat16 g_bw1[NEXP * FDIM * DMODEL];
__device__ __nv_bfloat16 g_bw2[NEXP * FDIM * DMODEL];
__device__ __nv_bfloat16 g_bwo[NEXP * DMODEL * FDIM];
__device__ int   g_tidx[NPAIR];
__device__ float g_tscale[NPAIR];
__device__ int   g_counts[NEXP];
__device__ int   g_cursor[NEXP];
__device__ int   g_off[NEXP];
__device__ int   g_rowTok[NPAIR];
__device__ float g_rowScale[NPAIR];
__device__ int   g_tileE[MAXTILE];
__device__ int   g_tileBm[MAXTILE];
__device__ int   g_ntiles;

// ---------------- helpers -----------------------------------------------------
__device__ __forceinline__ void mma16(float c[4],
    unsigned a0, unsigned a1, unsigned a2, unsigned a3,
    unsigned b0, unsigned b1)
{
    asm volatile(
        "mma.sync.aligned.m16n8k16.row.col.f32.bf16.bf16.f32 "
        "{%0,%1,%2,%3}, {%4,%5,%6,%7}, {%8,%9}, {%0,%1,%2,%3};\n"
        : "+f"(c[0]), "+f"(c[1]), "+f"(c[2]), "+f"(c[3])
        : "r"(a0), "r"(a1), "r"(a2), "r"(a3), "r"(b0), "r"(b1));
}

__device__ __forceinline__ void ldsm4t(unsigned& r0, unsigned& r1,
                                       unsigned& r2, unsigned& r3, unsigned addr)
{
    asm volatile(
        "ldmatrix.sync.aligned.m8n8.x4.trans.shared.b16 {%0,%1,%2,%3}, [%4];\n"
        : "=r"(r0), "=r"(r1), "=r"(r2), "=r"(r3) : "r"(addr));
}

__device__ __forceinline__ unsigned smem_u32(const void* p) {
    return (unsigned)__cvta_generic_to_shared(p);
}
__device__ __forceinline__ void cpa16(unsigned dst, const void* src, int vbytes) {
    asm volatile("cp.async.cg.shared.global [%0], [%1], 16, %2;\n"
                 :: "r"(dst), "l"(src), "r"(vbytes) : "memory");
}
__device__ __forceinline__ void cpa_commit() {
    asm volatile("cp.async.commit_group;\n" ::: "memory");
}
__device__ __forceinline__ unsigned packbf(float a, float b) {
    __nv_bfloat162 p = __floats2bfloat162_rn(a, b);
    return *(unsigned*)&p;
}

// ---------------- fp32 -> bf16 convert: 4 x float4 per thread (MLP=4) --------
__global__ __launch_bounds__(256) void f2bf_k(const float* __restrict__ in,
                                              __nv_bfloat16* __restrict__ out)
{
    const size_t stride = (size_t)gridDim.x * 256;
    size_t i = (size_t)blockIdx.x * 256 + threadIdx.x;
    float4 v0 = ((const float4*)in)[i];
    float4 v1 = ((const float4*)in)[i + stride];
    float4 v2 = ((const float4*)in)[i + 2 * stride];
    float4 v3 = ((const float4*)in)[i + 3 * stride];
    uint2 u0; u0.x = packbf(v0.x, v0.y); u0.y = packbf(v0.z, v0.w);
    uint2 u1; u1.x = packbf(v1.x, v1.y); u1.y = packbf(v1.z, v1.w);
    uint2 u2; u2.x = packbf(v2.x, v2.y); u2.y = packbf(v2.z, v2.w);
    uint2 u3; u3.x = packbf(v3.x, v3.y); u3.y = packbf(v3.z, v3.w);
    ((uint2*)out)[i] = u0;
    ((uint2*)out)[i + stride] = u1;
    ((uint2*)out)[i + 2 * stride] = u2;
    ((uint2*)out)[i + 3 * stride] = u3;
}

// ---------------- layernorm (dual fp32 + bf16 output) -------------------------
__global__ __launch_bounds__(128) void layernorm_k(
    const float* __restrict__ x, const float* __restrict__ g,
    const float* __restrict__ b, float* __restrict__ y,
    __nv_bfloat16* __restrict__ yb)
{
    int t = blockIdx.x;
    int tid = threadIdx.x;
    float4 v = ((const float4*)(x + (size_t)t * DMODEL))[tid];
    float s  = v.x + v.y + v.z + v.w;
    float ss = v.x * v.x + v.y * v.y + v.z * v.z + v.w * v.w;
    #pragma unroll
    for (int o = 16; o > 0; o >>= 1) {
        s  += __shfl_xor_sync(0xffffffffu, s, o);
        ss += __shfl_xor_sync(0xffffffffu, ss, o);
    }
    __shared__ float sw[4], ssw[4];
    __shared__ float meanS, rstdS;
    int lane = tid & 31, w = tid >> 5;
    if (lane == 0) { sw[w] = s; ssw[w] = ss; }
    __syncthreads();
    if (tid == 0) {
        float S = sw[0] + sw[1] + sw[2] + sw[3];
        float SS = ssw[0] + ssw[1] + ssw[2] + ssw[3];
        float mean = S / (float)DMODEL;
        float var = SS / (float)DMODEL - mean * mean;
        meanS = mean;
        rstdS = rsqrtf(var + 1e-5f);
    }
    __syncthreads();
    float mean = meanS, rstd = rstdS;
    float4 gg = ((const float4*)g)[tid];
    float4 bb = ((const float4*)b)[tid];
    float4 o;
    o.x = (v.x - mean) * rstd * gg.x + bb.x;
    o.y = (v.y - mean) * rstd * gg.y + bb.y;
    o.z = (v.z - mean) * rstd * gg.z + bb.z;
    o.w = (v.w - mean) * rstd * gg.w + bb.w;
    ((float4*)(y + (size_t)t * DMODEL))[tid] = o;
    uint2 u; u.x = packbf(o.x, o.y); u.y = packbf(o.z, o.w);
    ((uint2*)(yb + (size_t)t * DMODEL))[tid] = u;
}

// ---------------- bf16 GEMM core: C[M,N] = A[M,K] * B[N,K]^T ------------------
__device__ __forceinline__ void gemm_bf16_core(
    const __nv_bfloat16* __restrict__ A, const __nv_bfloat16* __restrict__ B,
    int M, int K, int bm, int bn, unsigned* su, float c[4][4][4])
{
    const int tid = threadIdx.x;
    const int lane = tid & 31, g = lane >> 2, tig = lane & 3;
    const int w = tid >> 5, wm = (w >> 2) << 6, wn = (w & 3) << 5;
    const int r = tid >> 1;
    const int seg0 = (tid & 1) << 1;
    const int nk = K >> 5;
    const int arow = (bm + r < M) ? (bm + r) : 0;
    const int av = (bm + r < M) ? 16 : 0;
    const __nv_bfloat16* Ar = A + (size_t)arow * K;
    const __nv_bfloat16* Br = B + (size_t)(bn + r) * K;
    const unsigned dstA = smem_u32(su) + (unsigned)(r * 20) * 4;
    const unsigned dstB = dstA + 5120 * 4;

    #define GEMM_ISSUE(kt_) do {                                           \
        int buf_ = (kt_) & 1;                                              \
        int k0_ = (kt_) << 5;                                              \
        _Pragma("unroll")                                                  \
        for (int i_ = 0; i_ < 2; i_++) {                                   \
            int seg_ = seg0 + i_;                                          \
            cpa16(dstA + buf_ * 10240 + seg_ * 16, Ar + k0_ + seg_ * 8, av);\
            cpa16(dstB + buf_ * 10240 + seg_ * 16, Br + k0_ + seg_ * 8, 16);\
        }                                                                  \
        cpa_commit();                                                      \
    } while (0)

    GEMM_ISSUE(0);
    GEMM_ISSUE(1);

    for (int kt = 0; kt < nk; kt++) {
        if (kt < nk - 1) asm volatile("cp.async.wait_group 1;\n" ::: "memory");
        else             asm volatile("cp.async.wait_group 0;\n" ::: "memory");
        __syncthreads();
        const unsigned* Au = su + (kt & 1) * 2560;
        const unsigned* Bu = su + 5120 + (kt & 1) * 2560;
        #pragma unroll
        for (int kk = 0; kk < 2; kk++) {
            const int kb = kk << 3;
            unsigned a[4][4], b[4][2];
            #pragma unroll
            for (int mi = 0; mi < 4; mi++) {
                int m = wm + (mi << 4);
                a[mi][0] = Au[(m + g) * 20 + kb + tig];
                a[mi][1] = Au[(m + g + 8) * 20 + kb + tig];
                a[mi][2] = Au[(m + g) * 20 + kb + tig + 4];
                a[mi][3] = Au[(m + g + 8) * 20 + kb + tig + 4];
            }
            #pragma unroll
            for (int ni = 0; ni < 4; ni++) {
                int n = wn + (ni << 3);
                b[ni][0] = Bu[(n + g) * 20 + kb + tig];
                b[ni][1] = Bu[(n + g) * 20 + kb + tig + 4];
            }
            #pragma unroll
            for (int mi = 0; mi < 4; mi++)
                #pragma unroll
                for (int ni = 0; ni < 4; ni++)
                    mma16(c[mi][ni], a[mi][0], a[mi][1], a[mi][2], a[mi][3],
                          b[ni][0], b[ni][1]);
        }
        __syncthreads();
        if (kt + 2 < nk) GEMM_ISSUE(kt + 2);
    }
    #undef GEMM_ISSUE
}

#define GEMM_PROLOGUE() \
    __shared__ unsigned su[10240]; \
    float c[4][4][4]; \
    _Pragma("unroll") \
    for (int mi = 0; mi < 4; mi++) \
        _Pragma("unroll") \
        for (int ni = 0; ni < 4; ni++) \
            _Pragma("unroll") \
            for (int j = 0; j < 4; j++) c[mi][ni][j] = 0.f; \
    const int lane = threadIdx.x & 31; \
    const int g = lane >> 2, tig = lane & 3; \
    const int w = threadIdx.x >> 5; \
    const int wm = (w >> 2) << 6, wn = (w & 3) << 5;

// GEMM + bias + optional residual, fp32 out.
__global__ __launch_bounds__(256, 2) void gemm_bf16_nt(
    const __nv_bfloat16* __restrict__ A, const __nv_bfloat16* __restrict__ B,
    const float* __restrict__ bias, const float* __restrict__ resid,
    float* __restrict__ C, int M, int N, int K)
{
    const int bm = blockIdx.y * 128;
    const int bn = blockIdx.x * 128;
    GEMM_PROLOGUE();
    gemm_bf16_core(A, B, M, K, bm, bn, su, c);
    #pragma unroll
    for (int mi = 0; mi < 4; mi++)
        #pragma unroll
        for (int half = 0; half < 2; half++) {
            int row = bm + wm + (mi << 4) + g + half * 8;
            if (row >= M) continue;
            #pragma unroll
            for (int ni = 0; ni < 4; ni++) {
                int col = bn + wn + (ni << 3) + 2 * tig;
                float v0 = c[mi][ni][half * 2]     + bias[col];
                float v1 = c[mi][ni][half * 2 + 1] + bias[col + 1];
                if (resid) {
                    v0 += resid[(size_t)row * N + col];
                    v1 += resid[(size_t)row * N + col + 1];
                }
                float2 v; v.x = v0; v.y = v1;
                *(float2*)&C[(size_t)row * N + col] = v;
            }
        }
}

// QKV GEMM: bf16 out, Q columns (col < DMODEL) pre-scaled by 1/sqrt(64).
__global__ __launch_bounds__(256, 2) void gemm_qkv(
    const __nv_bfloat16* __restrict__ A, const __nv_bfloat16* __restrict__ B,
    const float* __restrict__ bias, __nv_bfloat16* __restrict__ C,
    int M, int N, int K)
{
    const int bm = blockIdx.y * 128;
    const int bn = blockIdx.x * 128;
    GEMM_PROLOGUE();
    gemm_bf16_core(A, B, M, K, bm, bn, su, c);
    #pragma unroll
    for (int mi = 0; mi < 4; mi++)
        #pragma unroll
        for (int half = 0; half < 2; half++) {
            int row = bm + wm + (mi << 4) + g + half * 8;
            #pragma unroll
            for (int ni = 0; ni < 4; ni++) {
                int col = bn + wn + (ni << 3) + 2 * tig;
                float sc = (col < DMODEL) ? 0.125f : 1.f;
                float v0 = (c[mi][ni][half * 2]     + bias[col]) * sc;
                float v1 = (c[mi][ni][half * 2 + 1] + bias[col + 1]) * sc;
                *(unsigned*)&C[(size_t)row * N + col] = packbf(v0, v1);
            }
        }
}

// MoE up-proj #1: g_h1b = bf16(x@w1^T + b1)
__global__ __launch_bounds__(256, 2) void moe_up1(const float* __restrict__ Ball)
{
    int ti = blockIdx.y;
    if (ti >= g_ntiles) return;
    int e = g_tileE[ti];
    int bm = g_tileBm[ti];
    int M = g_counts[e];
    int bn = blockIdx.x * 128;
    const __nv_bfloat16* A = g_xgb + (size_t)g_off[e] * DMODEL;
    const __nv_bfloat16* B = g_bw1 + (size_t)e * FDIM * DMODEL;
    const float* bias = Ball + (size_t)e * FDIM;
    __nv_bfloat16* C = g_h1b + (size_t)g_off[e] * FDIM;
    GEMM_PROLOGUE();
    gemm_bf16_core(A, B, M, DMODEL, bm, bn, su, c);
    #pragma unroll
    for (int mi = 0; mi < 4; mi++)
        #pragma unroll
        for (int half = 0; half < 2; half++) {
            int row = bm + wm + (mi << 4) + g + half * 8;
            if (row >= M) continue;
            #pragma unroll
            for (int ni = 0; ni < 4; ni++) {
                int col = bn + wn + (ni << 3) + 2 * tig;
                *(unsigned*)&C[(size_t)row * FDIM + col] =
                    packbf(c[mi][ni][half * 2]     + bias[col],
                           c[mi][ni][half * 2 + 1] + bias[col + 1]);
            }
        }
}

// MoE up-proj #2 fused: g_hb = bf16( silu(h1) * (x@w2^T + b2) )
__global__ __launch_bounds__(256, 2) void moe_up2(const float* __restrict__ Ball)
{
    int ti = blockIdx.y;
    if (ti >= g_ntiles) return;
    int e = g_tileE[ti];
    int bm = g_tileBm[ti];
    int M = g_counts[e];
    int bn = blockIdx.x * 128;
    const __nv_bfloat16* A = g_xgb + (size_t)g_off[e] * DMODEL;
    const __nv_bfloat16* B = g_bw2 + (size_t)e * FDIM * DMODEL;
    const float* bias = Ball + (size_t)e * FDIM;
    const __nv_bfloat16* H1 = g_h1b + (size_t)g_off[e] * FDIM;
    __nv_bfloat16* HB = g_hb + (size_t)g_off[e] * FDIM;
    GEMM_PROLOGUE();
    gemm_bf16_core(A, B, M, DMODEL, bm, bn, su, c);
    #pragma unroll
    for (int mi = 0; mi < 4; mi++)
        #pragma unroll
        for (int half = 0; half < 2; half++) {
            int row = bm + wm + (mi << 4) + g + half * 8;
            if (row >= M) continue;
            #pragma unroll
            for (int ni = 0; ni < 4; ni++) {
                int col = bn + wn + (ni << 3) + 2 * tig;
                unsigned hv = *(const unsigned*)&H1[(size_t)row * FDIM + col];
                __nv_bfloat162 hb2 = *(__nv_bfloat162*)&hv;
                float gx = __bfloat162float(hb2.x);
                float gy = __bfloat162float(hb2.y);
                float h2v0 = c[mi][ni][half * 2]     + bias[col];
                float h2v1 = c[mi][ni][half * 2 + 1] + bias[col + 1];
                float s0 = gx / (1.f + __expf(-gx));
                float s1 = gy / (1.f + __expf(-gy));
                *(unsigned*)&HB[(size_t)row * FDIM + col] = packbf(s0 * h2v0, s1 * h2v1);
            }
        }
}

// MoE down GEMM + scaled scatter-add into residual output.
__global__ __launch_bounds__(256, 2) void moe_down(
    const float* __restrict__ Bo, float* __restrict__ Out)
{
    int ti = blockIdx.y;
    if (ti >= g_ntiles) return;
    int e = g_tileE[ti];
    int bm = g_tileBm[ti];
    int M = g_counts[e];
    int bn = blockIdx.x * 128;
    const __nv_bfloat16* A = g_hb + (size_t)g_off[e] * FDIM;
    const __nv_bfloat16* B = g_bwo + (size_t)e * DMODEL * FDIM;
    const float* bias = Bo + (size_t)e * DMODEL;
    GEMM_PROLOGUE();
    gemm_bf16_core(A, B, M, FDIM, bm, bn, su, c);
    #pragma unroll
    for (int mi = 0; mi < 4; mi++)
        #pragma unroll
        for (int half = 0; half < 2; half++) {
            int row = bm + wm + (mi << 4) + g + half * 8;
            if (row >= M) continue;
            int gr = g_off[e] + row;
            int tok = g_rowTok[gr];
            float sc = g_rowScale[gr];
            #pragma unroll
            for (int ni = 0; ni < 4; ni++) {
                int col = bn + wn + (ni << 3) + 2 * tig;
                atomicAdd(&Out[(size_t)tok * DMODEL + col],
                          sc * (c[mi][ni][half * 2] + bias[col]));
                atomicAdd(&Out[(size_t)tok * DMODEL + col + 1],
                          sc * (c[mi][ni][half * 2 + 1] + bias[col + 1]));
            }
        }
}

// ---------------- bf16 flash attention, cp.async pipelined K/V ---------------
// Bq=128, Bk=64, 128 threads (4 warps); warp owns 32 q-rows (2 m16-frags).
// Double-buffered K/V stages. smem: Q[128][36] + 2x(K+V)[64][36] u32 = 54KB dyn.
#define ATTN_SMEM_BYTES ((128 * 36 + 4 * 64 * 36) * 4)

__global__ __launch_bounds__(128, 3) void flash_attn_bf16(
    const __nv_bfloat16* __restrict__ qkv, __nv_bfloat16* __restrict__ outb)
{
    extern __shared__ unsigned asm_[];
    unsigned (*Qu)[36] = (unsigned(*)[36])asm_;
    unsigned (*Ku)[64][36] = (unsigned(*)[64][36])(asm_ + 128 * 36);
    unsigned (*Vu)[64][36] = (unsigned(*)[64][36])(asm_ + 128 * 36 + 2 * 64 * 36);

    const int tid = threadIdx.x;
    const int w = tid >> 5, lane = tid & 31;
    const int g = lane >> 2, tig = lane & 3;
    const int h = blockIdx.y;
    const int q0 = blockIdx.x * 128;
    const int m0 = w * 32;
    const int nkt = SEQ / 64;

    // per-thread K/V cp.async slots: f = tid + i*128, col = f>>3, chunk = f&7
    #define KV_ISSUE(kt_) do {                                                   \
        int buf_ = (kt_) & 1;                                                    \
        int kr0_ = (kt_) << 6;                                                   \
        _Pragma("unroll")                                                        \
        for (int i_ = 0; i_ < 4; i_++) {                                         \
            int f_ = tid + i_ * 128;                                             \
            int col_ = f_ >> 3, ch_ = f_ & 7;                                    \
            const __nv_bfloat16* base_ =                                         \
                qkv + (size_t)(kr0_ + col_) * 1536 + 512 + h * 64 + ch_ * 8;     \
            cpa16(smem_u32(&Ku[buf_][col_][ch_ * 4]), base_, 16);                \
            cpa16(smem_u32(&Vu[buf_][col_][ch_ * 4]), base_ + 512, 16);          \
        }                                                                        \
        cpa_commit();                                                            \
    } while (0)

    KV_ISSUE(0);
    KV_ISSUE(1);

    // load Q tile (already scaled by 1/8 in qkv GEMM)
    #pragma unroll
    for (int i = 0; i < 8; i++) {
        int f = tid + i * 128;
        int r = f >> 3, u4 = (f & 7) << 2;
        *(uint4*)&Qu[r][u4] =
            *(const uint4*)(qkv + (size_t)(q0 + r) * 1536 + h * 64 + (u4 << 1));
    }

    float o[2][8][4];
    #pragma unroll
    for (int mi = 0; mi < 2; mi++)
        #pragma unroll
        for (int nt = 0; nt < 8; nt++)
            #pragma unroll
            for (int j = 0; j < 4; j++) o[mi][nt][j] = 0.f;
    float mr[2][2] = {{-1e30f, -1e30f}, {-1e30f, -1e30f}};
    float lr[2][2] = {{0.f, 0.f}, {0.f, 0.f}};

    const int lt = lane >> 3, lrow = lane & 7;
    const int koff = ((lt & 1) << 3) + lrow;
    const int doff = (lt >> 1) << 2;

    for (int kt = 0; kt < nkt; kt++) {
        if (kt < nkt - 1) asm volatile("cp.async.wait_group 1;\n" ::: "memory");
        else              asm volatile("cp.async.wait_group 0;\n" ::: "memory");
        __syncthreads();
        const int buf = kt & 1;

        // S = Q K^T  (32 x 64 per warp, k16 steps)
        float s[2][8][4];
        #pragma unroll
        for (int mi = 0; mi < 2; mi++)
            #pragma unroll
            for (int nt = 0; nt < 8; nt++)
                #pragma unroll
                for (int j = 0; j < 4; j++) s[mi][nt][j] = 0.f;
        #pragma unroll
        for (int ktt = 0; ktt < 4; ktt++) {
            const int kb = ktt << 3;
            unsigned a[2][4];
            #pragma unroll
            for (int mi = 0; mi < 2; mi++) {
                int mb = m0 + (mi << 4);
                a[mi][0] = Qu[mb + g][kb + tig];
                a[mi][1] = Qu[mb + g + 8][kb + tig];
                a[mi][2] = Qu[mb + g][kb + tig + 4];
                a[mi][3] = Qu[mb + g + 8][kb + tig + 4];
            }
            #pragma unroll
            for (int nt = 0; nt < 8; nt++) {
                unsigned b0 = Ku[buf][(nt << 3) + g][kb + tig];
                unsigned b1 = Ku[buf][(nt << 3) + g][kb + tig + 4];
                mma16(s[0][nt], a[0][0], a[0][1], a[0][2], a[0][3], b0, b1);
                mma16(s[1][nt], a[1][0], a[1][1], a[1][2], a[1][3], b0, b1);
            }
        }

        // online softmax in registers
        #pragma unroll
        for (int mi = 0; mi < 2; mi++) {
            float mx0 = mr[mi][0], mx1 = mr[mi][1];
            #pragma unroll
            for (int nt = 0; nt < 8; nt++) {
                mx0 = fmaxf(mx0, fmaxf(s[mi][nt][0], s[mi][nt][1]));
                mx1 = fmaxf(mx1, fmaxf(s[mi][nt][2], s[mi][nt][3]));
            }
            mx0 = fmaxf(mx0, __shfl_xor_sync(0xffffffffu, mx0, 1));
            mx0 = fmaxf(mx0, __shfl_xor_sync(0xffffffffu, mx0, 2));
            mx1 = fmaxf(mx1, __shfl_xor_sync(0xffffffffu, mx1, 1));
            mx1 = fmaxf(mx1, __shfl_xor_sync(0xffffffffu, mx1, 2));
            float al0 = __expf(mr[mi][0] - mx0);
            float al1 = __expf(mr[mi][1] - mx1);
            float sum0 = 0.f, sum1 = 0.f;
            #pragma unroll
            for (int nt = 0; nt < 8; nt++) {
                s[mi][nt][0] = __expf(s[mi][nt][0] - mx0);
                s[mi][nt][1] = __expf(s[mi][nt][1] - mx0);
                s[mi][nt][2] = __expf(s[mi][nt][2] - mx1);
                s[mi][nt][3] = __expf(s[mi][nt][3] - mx1);
                sum0 += s[mi][nt][0] + s[mi][nt][1];
                sum1 += s[mi][nt][2] + s[mi][nt][3];
            }
            sum0 += __shfl_xor_sync(0xffffffffu, sum0, 1);
            sum0 += __shfl_xor_sync(0xffffffffu, sum0, 2);
            sum1 += __shfl_xor_sync(0xffffffffu, sum1, 1);
            sum1 += __shfl_xor_sync(0xffffffffu, sum1, 2);
            lr[mi][0] = lr[mi][0] * al0 + sum0; mr[mi][0] = mx0;
            lr[mi][1] = lr[mi][1] * al1 + sum1; mr[mi][1] = mx1;
            #pragma unroll
            for (int nt = 0; nt < 8; nt++) {
                o[mi][nt][0] *= al0; o[mi][nt][1] *= al0;
                o[mi][nt][2] *= al1; o[mi][nt][3] *= al1;
            }
        }

        // O += P V : c-frag packs directly into a-frag; V via ldmatrix.trans
        #pragma unroll
        for (int ktt = 0; ktt < 4; ktt++) {
            unsigned a[2][4];
            #pragma unroll
            for (int mi = 0; mi < 2; mi++) {
                a[mi][0] = packbf(s[mi][2*ktt][0],   s[mi][2*ktt][1]);
                a[mi][1] = packbf(s[mi][2*ktt][2],   s[mi][2*ktt][3]);
                a[mi][2] = packbf(s[mi][2*ktt+1][0], s[mi][2*ktt+1][1]);
                a[mi][3] = packbf(s[mi][2*ktt+1][2], s[mi][2*ktt+1][3]);
            }
            const int krow = (ktt << 4) + koff;
            #pragma unroll
            for (int ntp = 0; ntp < 4; ntp++) {
                unsigned b0, b1, b2, b3;
                ldsm4t(b0, b1, b2, b3,
                       smem_u32(&Vu[buf][krow][(ntp << 3) + doff]));
                mma16(o[0][2*ntp],   a[0][0], a[0][1], a[0][2], a[0][3], b0, b1);
                mma16(o[1][2*ntp],   a[1][0], a[1][1], a[1][2], a[1][3], b0, b1);
                mma16(o[0][2*ntp+1], a[0][0], a[0][1], a[0][2], a[0][3], b2, b3);
                mma16(o[1][2*ntp+1], a[1][0], a[1][1], a[1][2], a[1][3], b2, b3);
            }
        }
        __syncthreads();
        if (kt + 2 < nkt) KV_ISSUE(kt + 2);
    }
    #undef KV_ISSUE

    #pragma unroll
    for (int mi = 0; mi < 2; mi++) {
        float inv0 = 1.f / lr[mi][0], inv1 = 1.f / lr[mi][1];
        int mb = m0 + (mi << 4);
        #pragma unroll
        for (int nt = 0; nt < 8; nt++) {
            int col = h * 64 + (nt << 3) + 2 * tig;
            *(unsigned*)&outb[(size_t)(q0 + mb + g) * DMODEL + col] =
                packbf(o[mi][nt][0] * inv0, o[mi][nt][1] * inv0);
            *(unsigned*)&outb[(size_t)(q0 + mb + g + 8) * DMODEL + col] =
                packbf(o[mi][nt][2] * inv1, o[mi][nt][3] * inv1);
        }
    }
}

// ---------------- gating (fp32 path: routing must match reference) ------------
__global__ __launch_bounds__(128) void gate_topk(
    const float* __restrict__ xn, const float* __restrict__ gw,
    const float* __restrict__ gb)
{
    int warp = threadIdx.x >> 5;
    int lane = threadIdx.x & 31;
    int t = blockIdx.x * 4 + warp;
    float acc[NEXP];
    #pragma unroll
    for (int e = 0; e < NEXP; e++) acc[e] = 0.f;
    for (int d = lane; d < DMODEL; d += 32) {
        float xv = xn[(size_t)t * DMODEL + d];
        #pragma unroll
        for (int e = 0; e < NEXP; e++) acc[e] = fmaf(xv, gw[e * DMODEL + d], acc[e]);
    }
    #pragma unroll
    for (int e = 0; e < NEXP; e++)
        #pragma unroll
        for (int o = 16; o > 0; o >>= 1)
            acc[e] += __shfl_xor_sync(0xffffffffu, acc[e], o);
    if (lane == 0) {
        float lg[NEXP];
        float mx = -1e30f;
        #pragma unroll
        for (int e = 0; e < NEXP; e++) { lg[e] = acc[e] + gb[e]; mx = fmaxf(mx, lg[e]); }
        float sum = 0.f;
        #pragma unroll
        for (int e = 0; e < NEXP; e++) { lg[e] = __expf(lg[e] - mx); sum += lg[e]; }
        float inv = 1.f / sum;
        int e0 = 0; float p0 = lg[0];
        #pragma unroll
        for (int e = 1; e < NEXP; e++) if (lg[e] > p0) { p0 = lg[e]; e0 = e; }
        int e1 = -1; float p1 = -1.f;
        #pragma unroll
        for (int e = 0; e < NEXP; e++)
            if (e != e0 && lg[e] > p1) { p1 = lg[e]; e1 = e; }
        g_tidx[t * 2] = e0;         g_tidx[t * 2 + 1] = e1;
        g_tscale[t * 2] = p0 * inv; g_tscale[t * 2 + 1] = p1 * inv;
        atomicAdd(&g_counts[e0], 1);
        atomicAdd(&g_counts[e1], 1);
    }
}

__global__ void zero_counts_k() {
    if (threadIdx.x < NEXP) { g_counts[threadIdx.x] = 0; g_cursor[threadIdx.x] = 0; }
}

// offsets + device-side MoE tile list (expert, bm) pairs
__global__ void calc_offsets_k() {
    int o = 0, nt = 0;
    for (int e = 0; e < NEXP; e++) {
        g_off[e] = o;
        o += g_counts[e];
    }
    for (int e = 0; e < NEXP; e++)
        for (int bm = 0; bm < g_counts[e]; bm += 128) {
            g_tileE[nt] = e;
            g_tileBm[nt] = bm;
            nt++;
        }
    g_ntiles = nt;
}

__global__ __launch_bounds__(128) void gather_pairs()
{
    int p = blockIdx.x;
    __shared__ int posS;
    if (threadIdx.x == 0) {
        int e = g_tidx[p];
        int pos = g_off[e] + atomicAdd(&g_cursor[e], 1);
        g_rowTok[pos] = p >> 1;
        g_rowScale[pos] = g_tscale[p];
        posS = pos;
    }
    __syncthreads();
    int pos = posS;
    int t = p >> 1;
    ((uint2*)(g_xgb + (size_t)pos * DMODEL))[threadIdx.x] =
        ((const uint2*)(g_xnb + (size_t)t * DMODEL))[threadIdx.x];
}

// ---------------- launch -----------------------------------------------------
extern "C" void kernel_launch(void* const* d_in, const int* in_sizes, int n_in,
                              void* d_out, int out_size)
{
    const float* src        = (const float*)d_in[0];
    const float* in_proj_w  = (const float*)d_in[1];
    const float* in_proj_b  = (const float*)d_in[2];
    const float* out_proj_w = (const float*)d_in[3];
    const float* out_proj_b = (const float*)d_in[4];
    const float* ln1_g      = (const float*)d_in[5];
    const float* ln1_b      = (const float*)d_in[6];
    const float* ln2_g      = (const float*)d_in[7];
    const float* ln2_b      = (const float*)d_in[8];
    const float* gate_w     = (const float*)d_in[9];
    const float* gate_b     = (const float*)d_in[10];
    const float* w1         = (const float*)d_in[11];
    const float* b1         = (const float*)d_in[12];
    const float* w2         = (const float*)d_in[13];
    const float* b2         = (const float*)d_in[14];
    const float* wo         = (const float*)d_in[15];
    const float* bo         = (const float*)d_in[16];
    float* out = (float*)d_out;

    float *xn;
    __nv_bfloat16 *xnb, *qkvb, *attnb, *bwin, *bwout, *bw1, *bw2, *bwo;
    cudaGetSymbolAddress((void**)&xn,    g_xn);
    cudaGetSymbolAddress((void**)&xnb,   g_xnb);
    cudaGetSymbolAddress((void**)&qkvb,  g_qkvb);
    cudaGetSymbolAddress((void**)&attnb, g_attnb);
    cudaGetSymbolAddress((void**)&bwin,  g_bwin);
    cudaGetSymbolAddress((void**)&bwout, g_bwout);
    cudaGetSymbolAddress((void**)&bw1,   g_bw1);
    cudaGetSymbolAddress((void**)&bw2,   g_bw2);
    cudaGetSymbolAddress((void**)&bwo,   g_bwo);

    cudaFuncSetAttribute(flash_attn_bf16,
                         cudaFuncAttributeMaxDynamicSharedMemorySize,
                         ATTN_SMEM_BYTES);

    // weight converts (fp32 -> bf16); 4 float4 per thread
    f2bf_k<<<3 * DMODEL * DMODEL / 4096, 256>>>(in_proj_w, bwin);
    f2bf_k<<<DMODEL * DMODEL / 4096, 256>>>(out_proj_w, bwout);
    f2bf_k<<<NEXP * FDIM * DMODEL / 4096, 256>>>(w1, bw1);
    f2bf_k<<<NEXP * FDIM * DMODEL / 4096, 256>>>(w2, bw2);
    f2bf_k<<<NEXP * DMODEL * FDIM / 4096, 256>>>(wo, bwo);

    zero_counts_k<<<1, 32>>>();

    // ---- attention block ----
    layernorm_k<<<SEQ, 128>>>(src, ln1_g, ln1_b, xn, xnb);
    gemm_qkv<<<dim3(12, 32), 256>>>(xnb, bwin, in_proj_b, qkvb,
                                    SEQ, 3 * DMODEL, DMODEL);
    flash_attn_bf16<<<dim3(SEQ / 128, NHEAD), 128, ATTN_SMEM_BYTES>>>(qkvb, attnb);
    gemm_bf16_nt<<<dim3(4, 32), 256>>>(attnb, bwout, out_proj_b, src, out,
                                       SEQ, DMODEL, DMODEL);

    // ---- MoE block ----
    layernorm_k<<<SEQ, 128>>>(out, ln2_g, ln2_b, xn, xnb);
    gate_topk<<<SEQ / 4, 128>>>(xn, gate_w, gate_b);
    calc_offsets_k<<<1, 1>>>();
    gather_pairs<<<NPAIR, 128>>>();
    moe_up1<<<dim3(FDIM / 128, MAXTILE - 8), 256>>>(b1);
    moe_up2<<<dim3(FDIM / 128, MAXTILE - 8), 256>>>(b2);
    moe_down<<<dim3(DMODEL / 128, MAXTILE - 8), 256>>>(bo, out);
}

// round 9
// speedup vs baseline: 5.8380x; 1.0200x over previous
#include <cuda_runtime.h>
#include <cuda_bf16.h>
#include <math.h>

#define SEQ 4096
#define DMODEL 512
#define NHEAD 8
#define FDIM 2048
#define NEXP 8
#define NPAIR (SEQ * 2)
#define MAXTILE 80

// ---------------- scratch (device globals; no allocations allowed) ----------
__device__ float g_xn[SEQ * DMODEL];                 // fp32 LN out (gate path)
__device__ __nv_bfloat16 g_xnb[SEQ * DMODEL];        // bf16 LN out (GEMM A)
__device__ __nv_bfloat16 g_qkvb[SEQ * 3 * DMODEL];   // bf16 qkv (Q pre-scaled)
__device__ __nv_bfloat16 g_attnb[SEQ * DMODEL];
__device__ __nv_bfloat16 g_xgb[NPAIR * DMODEL];
__device__ __nv_bfloat16 g_h1b[NPAIR * FDIM];
__device__ __nv_bfloat16 g_hb[NPAIR * FDIM];
__device__ float g_dout[NPAIR * DMODEL];             // per-pair scaled expert out
__device__ __nv_bfloat16 g_bwin[3 * DMODEL * DMODEL];
__device__ __nv_bfloat16 g_bwout[DMODEL * DMODEL];
__device__ __nv_bfloat16 g_bw1[NEXP * FDIM * DMODEL];
__device__ __nv_bfloat16 g_bw2[NEXP * FDIM * DMODEL];
__device__ __nv_bfloat16 g_bwo[NEXP * DMODEL * FDIM];
__device__ int   g_tidx[NPAIR];
__device__ float g_tscale[NPAIR];
__device__ int   g_counts[NEXP];
__device__ int   g_cursor[NEXP];
__device__ int   g_off[NEXP];
__device__ float g_rowScale[NPAIR];
__device__ int   g_pairRow[NPAIR];                   // (token,k) pair -> gathered row
__device__ int   g_tileE[MAXTILE];
__device__ int   g_tileBm[MAXTILE];
__device__ int   g_ntiles;

// ---------------- helpers -----------------------------------------------------
__device__ __forceinline__ void mma16(float c[4],
    unsigned a0, unsigned a1, unsigned a2, unsigned a3,
    unsigned b0, unsigned b1)
{
    asm volatile(
        "mma.sync.aligned.m16n8k16.row.col.f32.bf16.bf16.f32 "
        "{%0,%1,%2,%3}, {%4,%5,%6,%7}, {%8,%9}, {%0,%1,%2,%3};\n"
        : "+f"(c[0]), "+f"(c[1]), "+f"(c[2]), "+f"(c[3])
        : "r"(a0), "r"(a1), "r"(a2), "r"(a3), "r"(b0), "r"(b1));
}

__device__ __forceinline__ void ldsm4(unsigned& r0, unsigned& r1,
                                      unsigned& r2, unsigned& r3, unsigned addr)
{
    asm volatile(
        "ldmatrix.sync.aligned.m8n8.x4.shared.b16 {%0,%1,%2,%3}, [%4];\n"
        : "=r"(r0), "=r"(r1), "=r"(r2), "=r"(r3) : "r"(addr));
}

__device__ __forceinline__ void ldsm4t(unsigned& r0, unsigned& r1,
                                       unsigned& r2, unsigned& r3, unsigned addr)
{
    asm volatile(
        "ldmatrix.sync.aligned.m8n8.x4.trans.shared.b16 {%0,%1,%2,%3}, [%4];\n"
        : "=r"(r0), "=r"(r1), "=r"(r2), "=r"(r3) : "r"(addr));
}

__device__ __forceinline__ unsigned smem_u32(const void* p) {
    return (unsigned)__cvta_generic_to_shared(p);
}
__device__ __forceinline__ void cpa16(unsigned dst, const void* src, int vbytes) {
    asm volatile("cp.async.cg.shared.global [%0], [%1], 16, %2;\n"
                 :: "r"(dst), "l"(src), "r"(vbytes) : "memory");
}
__device__ __forceinline__ void cpa_commit() {
    asm volatile("cp.async.commit_group;\n" ::: "memory");
}
__device__ __forceinline__ unsigned packbf(float a, float b) {
    __nv_bfloat162 p = __floats2bfloat162_rn(a, b);
    return *(unsigned*)&p;
}

// ldmatrix lane-role offsets (shared by GEMM + attention QK):
// A x4: m0=rows r..r+7 @k0, m1=rows+8 @k0, m2=rows @k+8, m3=rows+8 @k+8
// B x4: m0=n..n+7 @k0, m1=same rows @k+8, m2=n+8.. @k0, m3=n+8.. @k+8
#define LDSM_OFFS() \
    const int rl_ = lane & 7, quad_ = lane >> 3; \
    const int arow_off = rl_ + ((quad_ & 1) << 3); \
    const int acol_off = (quad_ >> 1) << 2; \
    const int brow_off = rl_ + ((quad_ >> 1) << 3); \
    const int bcol_off = (quad_ & 1) << 2;

// ---------------- fp32 -> bf16 convert: 4 x float4 per thread (MLP=4) --------
__global__ __launch_bounds__(256) void f2bf_k(const float* __restrict__ in,
                                              __nv_bfloat16* __restrict__ out)
{
    const size_t stride = (size_t)gridDim.x * 256;
    size_t i = (size_t)blockIdx.x * 256 + threadIdx.x;
    float4 v0 = ((const float4*)in)[i];
    float4 v1 = ((const float4*)in)[i + stride];
    float4 v2 = ((const float4*)in)[i + 2 * stride];
    float4 v3 = ((const float4*)in)[i + 3 * stride];
    uint2 u0; u0.x = packbf(v0.x, v0.y); u0.y = packbf(v0.z, v0.w);
    uint2 u1; u1.x = packbf(v1.x, v1.y); u1.y = packbf(v1.z, v1.w);
    uint2 u2; u2.x = packbf(v2.x, v2.y); u2.y = packbf(v2.z, v2.w);
    uint2 u3; u3.x = packbf(v3.x, v3.y); u3.y = packbf(v3.z, v3.w);
    ((uint2*)out)[i] = u0;
    ((uint2*)out)[i + stride] = u1;
    ((uint2*)out)[i + 2 * stride] = u2;
    ((uint2*)out)[i + 3 * stride] = u3;
}

// ---------------- layernorm (dual fp32 + bf16 output) -------------------------
__global__ __launch_bounds__(128) void layernorm_k(
    const float* __restrict__ x, const float* __restrict__ g,
    const float* __restrict__ b, float* __restrict__ y,
    __nv_bfloat16* __restrict__ yb)
{
    int t = blockIdx.x;
    int tid = threadIdx.x;
    float4 v = ((const float4*)(x + (size_t)t * DMODEL))[tid];
    float s  = v.x + v.y + v.z + v.w;
    float ss = v.x * v.x + v.y * v.y + v.z * v.z + v.w * v.w;
    #pragma unroll
    for (int o = 16; o > 0; o >>= 1) {
        s  += __shfl_xor_sync(0xffffffffu, s, o);
        ss += __shfl_xor_sync(0xffffffffu, ss, o);
    }
    __shared__ float sw[4], ssw[4];
    __shared__ float meanS, rstdS;
    int lane = tid & 31, w = tid >> 5;
    if (lane == 0) { sw[w] = s; ssw[w] = ss; }
    __syncthreads();
    if (tid == 0) {
        float S = sw[0] + sw[1] + sw[2] + sw[3];
        float SS = ssw[0] + ssw[1] + ssw[2] + ssw[3];
        float mean = S / (float)DMODEL;
        float var = SS / (float)DMODEL - mean * mean;
        meanS = mean;
        rstdS = rsqrtf(var + 1e-5f);
    }
    __syncthreads();
    float mean = meanS, rstd = rstdS;
    float4 gg = ((const float4*)g)[tid];
    float4 bb = ((const float4*)b)[tid];
    float4 o;
    o.x = (v.x - mean) * rstd * gg.x + bb.x;
    o.y = (v.y - mean) * rstd * gg.y + bb.y;
    o.z = (v.z - mean) * rstd * gg.z + bb.z;
    o.w = (v.w - mean) * rstd * gg.w + bb.w;
    ((float4*)(y + (size_t)t * DMODEL))[tid] = o;
    uint2 u; u.x = packbf(o.x, o.y); u.y = packbf(o.z, o.w);
    ((uint2*)(yb + (size_t)t * DMODEL))[tid] = u;
}

// ---------------- bf16 GEMM core: C[M,N] = A[M,K] * B[N,K]^T ------------------
// BM=BN=128, BK=32, 256 threads (8 warps 2x4), warp tile 64x32, m16n8k16.
// ldmatrix.x4 fragment loads; cp.async double-buffered; 40KB static smem.
__device__ __forceinline__ void gemm_bf16_core(
    const __nv_bfloat16* __restrict__ A, const __nv_bfloat16* __restrict__ B,
    int M, int K, int bm, int bn, unsigned* su, float c[4][4][4])
{
    const int tid = threadIdx.x;
    const int lane = tid & 31;
    const int w = tid >> 5, wm = (w >> 2) << 6, wn = (w & 3) << 5;
    LDSM_OFFS();
    const int r = tid >> 1;
    const int seg0 = (tid & 1) << 1;
    const int nk = K >> 5;
    const int arow = (bm + r < M) ? (bm + r) : 0;
    const int av = (bm + r < M) ? 16 : 0;
    const __nv_bfloat16* Ar = A + (size_t)arow * K;
    const __nv_bfloat16* Br = B + (size_t)(bn + r) * K;
    const unsigned suB = smem_u32(su);
    const unsigned dstA = suB + (unsigned)(r * 20) * 4;
    const unsigned dstB = dstA + 5120 * 4;

    // stage layout (bytes from suB): A buf0 @0, buf1 @10240; B @20480 (+buf*10240)
    #define GEMM_ISSUE(kt_) do {                                           \
        int buf_ = (kt_) & 1;                                              \
        int k0_ = (kt_) << 5;                                              \
        _Pragma("unroll")                                                  \
        for (int i_ = 0; i_ < 2; i_++) {                                   \
            int seg_ = seg0 + i_;                                          \
            cpa16(dstA + buf_ * 10240 + seg_ * 16, Ar + k0_ + seg_ * 8, av);\
            cpa16(dstB + buf_ * 10240 + seg_ * 16, Br + k0_ + seg_ * 8, 16);\
        }                                                                  \
        cpa_commit();                                                      \
    } while (0)

    GEMM_ISSUE(0);
    GEMM_ISSUE(1);

    for (int kt = 0; kt < nk; kt++) {
        if (kt < nk - 1) asm volatile("cp.async.wait_group 1;\n" ::: "memory");
        else             asm volatile("cp.async.wait_group 0;\n" ::: "memory");
        __syncthreads();
        const unsigned stageA = suB + (unsigned)((kt & 1) * 10240);   // BYTES
        const unsigned stageB = stageA + 5120 * 4;
        #pragma unroll
        for (int kk = 0; kk < 2; kk++) {
            const int kb = kk << 3;
            unsigned a[4][4], b[4][2];
            const unsigned aAddr =
                stageA + (unsigned)((wm + arow_off) * 20 + kb + acol_off) * 4;
            #pragma unroll
            for (int mi = 0; mi < 4; mi++)
                ldsm4(a[mi][0], a[mi][1], a[mi][2], a[mi][3],
                      aAddr + (unsigned)(mi * 16 * 20) * 4);
            const unsigned bAddr =
                stageB + (unsigned)((wn + brow_off) * 20 + kb + bcol_off) * 4;
            ldsm4(b[0][0], b[0][1], b[1][0], b[1][1], bAddr);
            ldsm4(b[2][0], b[2][1], b[3][0], b[3][1],
                  bAddr + (unsigned)(16 * 20) * 4);
            #pragma unroll
            for (int mi = 0; mi < 4; mi++)
                #pragma unroll
                for (int ni = 0; ni < 4; ni++)
                    mma16(c[mi][ni], a[mi][0], a[mi][1], a[mi][2], a[mi][3],
                          b[ni][0], b[ni][1]);
        }
        __syncthreads();
        if (kt + 2 < nk) GEMM_ISSUE(kt + 2);
    }
    #undef GEMM_ISSUE
}

#define GEMM_PROLOGUE() \
    __shared__ unsigned su[10240]; \
    float c[4][4][4]; \
    _Pragma("unroll") \
    for (int mi = 0; mi < 4; mi++) \
        _Pragma("unroll") \
        for (int ni = 0; ni < 4; ni++) \
            _Pragma("unroll") \
            for (int j = 0; j < 4; j++) c[mi][ni][j] = 0.f; \
    const int lane = threadIdx.x & 31; \
    const int g = lane >> 2, tig = lane & 3; \
    const int w = threadIdx.x >> 5; \
    const int wm = (w >> 2) << 6, wn = (w & 3) << 5;

// GEMM + bias + optional residual, fp32 out.
__global__ __launch_bounds__(256, 2) void gemm_bf16_nt(
    const __nv_bfloat16* __restrict__ A, const __nv_bfloat16* __restrict__ B,
    const float* __restrict__ bias, const float* __restrict__ resid,
    float* __restrict__ C, int M, int N, int K)
{
    const int bm = blockIdx.y * 128;
    const int bn = blockIdx.x * 128;
    GEMM_PROLOGUE();
    gemm_bf16_core(A, B, M, K, bm, bn, su, c);
    #pragma unroll
    for (int mi = 0; mi < 4; mi++)
        #pragma unroll
        for (int half = 0; half < 2; half++) {
            int row = bm + wm + (mi << 4) + g + half * 8;
            if (row >= M) continue;
            #pragma unroll
            for (int ni = 0; ni < 4; ni++) {
                int col = bn + wn + (ni << 3) + 2 * tig;
                float v0 = c[mi][ni][half * 2]     + bias[col];
                float v1 = c[mi][ni][half * 2 + 1] + bias[col + 1];
                if (resid) {
                    v0 += resid[(size_t)row * N + col];
                    v1 += resid[(size_t)row * N + col + 1];
                }
                float2 v; v.x = v0; v.y = v1;
                *(float2*)&C[(size_t)row * N + col] = v;
            }
        }
}

// QKV GEMM: bf16 out, Q columns (col < DMODEL) pre-scaled by 1/sqrt(64).
__global__ __launch_bounds__(256, 2) void gemm_qkv(
    const __nv_bfloat16* __restrict__ A, const __nv_bfloat16* __restrict__ B,
    const float* __restrict__ bias, __nv_bfloat16* __restrict__ C,
    int M, int N, int K)
{
    const int bm = blockIdx.y * 128;
    const int bn = blockIdx.x * 128;
    GEMM_PROLOGUE();
    gemm_bf16_core(A, B, M, K, bm, bn, su, c);
    #pragma unroll
    for (int mi = 0; mi < 4; mi++)
        #pragma unroll
        for (int half = 0; half < 2; half++) {
            int row = bm + wm + (mi << 4) + g + half * 8;
            #pragma unroll
            for (int ni = 0; ni < 4; ni++) {
                int col = bn + wn + (ni << 3) + 2 * tig;
                float sc = (col < DMODEL) ? 0.125f : 1.f;
                float v0 = (c[mi][ni][half * 2]     + bias[col]) * sc;
                float v1 = (c[mi][ni][half * 2 + 1] + bias[col + 1]) * sc;
                *(unsigned*)&C[(size_t)row * N + col] = packbf(v0, v1);
            }
        }
}

// MoE up-proj #1: g_h1b = bf16(x@w1^T + b1)
__global__ __launch_bounds__(256, 2) void moe_up1(const float* __restrict__ Ball)
{
    int ti = blockIdx.y;
    if (ti >= g_ntiles) return;
    int e = g_tileE[ti];
    int bm = g_tileBm[ti];
    int M = g_counts[e];
    int bn = blockIdx.x * 128;
    const __nv_bfloat16* A = g_xgb + (size_t)g_off[e] * DMODEL;
    const __nv_bfloat16* B = g_bw1 + (size_t)e * FDIM * DMODEL;
    const float* bias = Ball + (size_t)e * FDIM;
    __nv_bfloat16* C = g_h1b + (size_t)g_off[e] * FDIM;
    GEMM_PROLOGUE();
    gemm_bf16_core(A, B, M, DMODEL, bm, bn, su, c);
    #pragma unroll
    for (int mi = 0; mi < 4; mi++)
        #pragma unroll
        for (int half = 0; half < 2; half++) {
            int row = bm + wm + (mi << 4) + g + half * 8;
            if (row >= M) continue;
            #pragma unroll
            for (int ni = 0; ni < 4; ni++) {
                int col = bn + wn + (ni << 3) + 2 * tig;
                *(unsigned*)&C[(size_t)row * FDIM + col] =
                    packbf(c[mi][ni][half * 2]     + bias[col],
                           c[mi][ni][half * 2 + 1] + bias[col + 1]);
            }
        }
}

// MoE up-proj #2 fused: g_hb = bf16( silu(h1) * (x@w2^T + b2) )
__global__ __launch_bounds__(256, 2) void moe_up2(const float* __restrict__ Ball)
{
    int ti = blockIdx.y;
    if (ti >= g_ntiles) return;
    int e = g_tileE[ti];
    int bm = g_tileBm[ti];
    int M = g_counts[e];
    int bn = blockIdx.x * 128;
    const __nv_bfloat16* A = g_xgb + (size_t)g_off[e] * DMODEL;
    const __nv_bfloat16* B = g_bw2 + (size_t)e * FDIM * DMODEL;
    const float* bias = Ball + (size_t)e * FDIM;
    const __nv_bfloat16* H1 = g_h1b + (size_t)g_off[e] * FDIM;
    __nv_bfloat16* HB = g_hb + (size_t)g_off[e] * FDIM;
    GEMM_PROLOGUE();
    gemm_bf16_core(A, B, M, DMODEL, bm, bn, su, c);
    #pragma unroll
    for (int mi = 0; mi < 4; mi++)
        #pragma unroll
        for (int half = 0; half < 2; half++) {
            int row = bm + wm + (mi << 4) + g + half * 8;
            if (row >= M) continue;
            #pragma unroll
            for (int ni = 0; ni < 4; ni++) {
                int col = bn + wn + (ni << 3) + 2 * tig;
                unsigned hv = *(const unsigned*)&H1[(size_t)row * FDIM + col];
                __nv_bfloat162 hb2 = *(__nv_bfloat162*)&hv;
                float gx = __bfloat162float(hb2.x);
                float gy = __bfloat162float(hb2.y);
                float h2v0 = c[mi][ni][half * 2]     + bias[col];
                float h2v1 = c[mi][ni][half * 2 + 1] + bias[col + 1];
                float s0 = gx / (1.f + __expf(-gx));
                float s1 = gy / (1.f + __expf(-gy));
                *(unsigned*)&HB[(size_t)row * FDIM + col] = packbf(s0 * h2v0, s1 * h2v1);
            }
        }
}

// MoE down GEMM: dense per-row scaled output (no atomics).
__global__ __launch_bounds__(256, 2) void moe_down(const float* __restrict__ Bo)
{
    int ti = blockIdx.y;
    if (ti >= g_ntiles) return;
    int e = g_tileE[ti];
    int bm = g_tileBm[ti];
    int M = g_counts[e];
    int bn = blockIdx.x * 128;
    const __nv_bfloat16* A = g_hb + (size_t)g_off[e] * FDIM;
    const __nv_bfloat16* B = g_bwo + (size_t)e * DMODEL * FDIM;
    const float* bias = Bo + (size_t)e * DMODEL;
    GEMM_PROLOGUE();
    gemm_bf16_core(A, B, M, FDIM, bm, bn, su, c);
    #pragma unroll
    for (int mi = 0; mi < 4; mi++)
        #pragma unroll
        for (int half = 0; half < 2; half++) {
            int row = bm + wm + (mi << 4) + g + half * 8;
            if (row >= M) continue;
            int gr = g_off[e] + row;
            float sc = g_rowScale[gr];
            #pragma unroll
            for (int ni = 0; ni < 4; ni++) {
                int col = bn + wn + (ni << 3) + 2 * tig;
                float2 v;
                v.x = sc * (c[mi][ni][half * 2]     + bias[col]);
                v.y = sc * (c[mi][ni][half * 2 + 1] + bias[col + 1]);
                *(float2*)&g_dout[(size_t)gr * DMODEL + col] = v;
            }
        }
}

// Combine: out[t] += dout[rowA] + dout[rowB]
__global__ __launch_bounds__(128) void moe_combine(float* __restrict__ Out)
{
    int t = blockIdx.x;
    int tid = threadIdx.x;
    int r0 = g_pairRow[t * 2];
    int r1 = g_pairRow[t * 2 + 1];
    float4 a = ((const float4*)(g_dout + (size_t)r0 * DMODEL))[tid];
    float4 b = ((const float4*)(g_dout + (size_t)r1 * DMODEL))[tid];
    float4 o = ((const float4*)(Out + (size_t)t * DMODEL))[tid];
    o.x += a.x + b.x; o.y += a.y + b.y;
    o.z += a.z + b.z; o.w += a.w + b.w;
    ((float4*)(Out + (size_t)t * DMODEL))[tid] = o;
}

// ---------------- bf16 flash attention, cp.async pipelined K/V ---------------
// Bq=128, Bk=64, 128 threads (4 warps); warp owns 32 q-rows (2 m16-frags).
#define ATTN_SMEM_BYTES ((128 * 36 + 4 * 64 * 36) * 4)

__global__ __launch_bounds__(128, 3) void flash_attn_bf16(
    const __nv_bfloat16* __restrict__ qkv, __nv_bfloat16* __restrict__ outb)
{
    extern __shared__ unsigned asm_[];
    unsigned (*Qu)[36] = (unsigned(*)[36])asm_;
    unsigned (*Ku)[64][36] = (unsigned(*)[64][36])(asm_ + 128 * 36);
    unsigned (*Vu)[64][36] = (unsigned(*)[64][36])(asm_ + 128 * 36 + 2 * 64 * 36);

    const int tid = threadIdx.x;
    const int w = tid >> 5, lane = tid & 31;
    const int g = lane >> 2, tig = lane & 3;
    LDSM_OFFS();
    const int h = blockIdx.y;
    const int q0 = blockIdx.x * 128;
    const int m0 = w * 32;
    const int nkt = SEQ / 64;

    #define KV_ISSUE(kt_) do {                                                   \
        int buf_ = (kt_) & 1;                                                    \
        int kr0_ = (kt_) << 6;                                                   \
        _Pragma("unroll")                                                        \
        for (int i_ = 0; i_ < 4; i_++) {                                         \
            int f_ = tid + i_ * 128;                                             \
            int col_ = f_ >> 3, ch_ = f_ & 7;                                    \
            const __nv_bfloat16* base_ =                                         \
                qkv + (size_t)(kr0_ + col_) * 1536 + 512 + h * 64 + ch_ * 8;     \
            cpa16(smem_u32(&Ku[buf_][col_][ch_ * 4]), base_, 16);                \
            cpa16(smem_u32(&Vu[buf_][col_][ch_ * 4]), base_ + 512, 16);          \
        }                                                                        \
        cpa_commit();                                                            \
    } while (0)

    KV_ISSUE(0);
    KV_ISSUE(1);

    // load Q tile (already scaled by 1/8 in qkv GEMM)
    #pragma unroll
    for (int i = 0; i < 8; i++) {
        int f = tid + i * 128;
        int rq = f >> 3, u4 = (f & 7) << 2;
        *(uint4*)&Qu[rq][u4] =
            *(const uint4*)(qkv + (size_t)(q0 + rq) * 1536 + h * 64 + (u4 << 1));
    }

    float o[2][8][4];
    #pragma unroll
    for (int mi = 0; mi < 2; mi++)
        #pragma unroll
        for (int nt = 0; nt < 8; nt++)
            #pragma unroll
            for (int j = 0; j < 4; j++) o[mi][nt][j] = 0.f;
    float mr[2][2] = {{-1e30f, -1e30f}, {-1e30f, -1e30f}};
    float lr[2][2] = {{0.f, 0.f}, {0.f, 0.f}};

    const int lt = lane >> 3, lrow = lane & 7;
    const int koff = ((lt & 1) << 3) + lrow;
    const int doff = (lt >> 1) << 2;

    for (int kt = 0; kt < nkt; kt++) {
        if (kt < nkt - 1) asm volatile("cp.async.wait_group 1;\n" ::: "memory");
        else              asm volatile("cp.async.wait_group 0;\n" ::: "memory");
        __syncthreads();
        const int buf = kt & 1;

        // S = Q K^T  (32 x 64 per warp, ldmatrix frags)
        float s[2][8][4];
        #pragma unroll
        for (int mi = 0; mi < 2; mi++)
            #pragma unroll
            for (int nt = 0; nt < 8; nt++)
                #pragma unroll
                for (int j = 0; j < 4; j++) s[mi][nt][j] = 0.f;
        #pragma unroll
        for (int ktt = 0; ktt < 4; ktt++) {
            const int kb = ktt << 3;
            unsigned a[2][4];
            #pragma unroll
            for (int mi = 0; mi < 2; mi++)
                ldsm4(a[mi][0], a[mi][1], a[mi][2], a[mi][3],
                      smem_u32(&Qu[m0 + (mi << 4) + arow_off][kb + acol_off]));
            #pragma unroll
            for (int ntp = 0; ntp < 4; ntp++) {
                unsigned b00, b01, b10, b11;
                ldsm4(b00, b01, b10, b11,
                      smem_u32(&Ku[buf][(ntp << 4) + brow_off][kb + bcol_off]));
                mma16(s[0][2*ntp],   a[0][0], a[0][1], a[0][2], a[0][3], b00, b01);
                mma16(s[1][2*ntp],   a[1][0], a[1][1], a[1][2], a[1][3], b00, b01);
                mma16(s[0][2*ntp+1], a[0][0], a[0][1], a[0][2], a[0][3], b10, b11);
                mma16(s[1][2*ntp+1], a[1][0], a[1][1], a[1][2], a[1][3], b10, b11);
            }
        }

        // online softmax in registers
        #pragma unroll
        for (int mi = 0; mi < 2; mi++) {
            float mx0 = mr[mi][0], mx1 = mr[mi][1];
            #pragma unroll
            for (int nt = 0; nt < 8; nt++) {
                mx0 = fmaxf(mx0, fmaxf(s[mi][nt][0], s[mi][nt][1]));
                mx1 = fmaxf(mx1, fmaxf(s[mi][nt][2], s[mi][nt][3]));
            }
            mx0 = fmaxf(mx0, __shfl_xor_sync(0xffffffffu, mx0, 1));
            mx0 = fmaxf(mx0, __shfl_xor_sync(0xffffffffu, mx0, 2));
            mx1 = fmaxf(mx1, __shfl_xor_sync(0xffffffffu, mx1, 1));
            mx1 = fmaxf(mx1, __shfl_xor_sync(0xffffffffu, mx1, 2));
            float al0 = __expf(mr[mi][0] - mx0);
            float al1 = __expf(mr[mi][1] - mx1);
            float sum0 = 0.f, sum1 = 0.f;
            #pragma unroll
            for (int nt = 0; nt < 8; nt++) {
                s[mi][nt][0] = __expf(s[mi][nt][0] - mx0);
                s[mi][nt][1] = __expf(s[mi][nt][1] - mx0);
                s[mi][nt][2] = __expf(s[mi][nt][2] - mx1);
                s[mi][nt][3] = __expf(s[mi][nt][3] - mx1);
                sum0 += s[mi][nt][0] + s[mi][nt][1];
                sum1 += s[mi][nt][2] + s[mi][nt][3];
            }
            sum0 += __shfl_xor_sync(0xffffffffu, sum0, 1);
            sum0 += __shfl_xor_sync(0xffffffffu, sum0, 2);
            sum1 += __shfl_xor_sync(0xffffffffu, sum1, 1);
            sum1 += __shfl_xor_sync(0xffffffffu, sum1, 2);
            lr[mi][0] = lr[mi][0] * al0 + sum0; mr[mi][0] = mx0;
            lr[mi][1] = lr[mi][1] * al1 + sum1; mr[mi][1] = mx1;
            #pragma unroll
            for (int nt = 0; nt < 8; nt++) {
                o[mi][nt][0] *= al0; o[mi][nt][1] *= al0;
                o[mi][nt][2] *= al1; o[mi][nt][3] *= al1;
            }
        }

        // O += P V : c-frag packs directly into a-frag; V via ldmatrix.trans
        #pragma unroll
        for (int ktt = 0; ktt < 4; ktt++) {
            unsigned a[2][4];
            #pragma unroll
            for (int mi = 0; mi < 2; mi++) {
                a[mi][0] = packbf(s[mi][2*ktt][0],   s[mi][2*ktt][1]);
                a[mi][1] = packbf(s[mi][2*ktt][2],   s[mi][2*ktt][3]);
                a[mi][2] = packbf(s[mi][2*ktt+1][0], s[mi][2*ktt+1][1]);
                a[mi][3] = packbf(s[mi][2*ktt+1][2], s[mi][2*ktt+1][3]);
            }
            const int krow = (ktt << 4) + koff;
            #pragma unroll
            for (int ntp = 0; ntp < 4; ntp++) {
                unsigned b0, b1, b2, b3;
                ldsm4t(b0, b1, b2, b3,
                       smem_u32(&Vu[buf][krow][(ntp << 3) + doff]));
                mma16(o[0][2*ntp],   a[0][0], a[0][1], a[0][2], a[0][3], b0, b1);
                mma16(o[1][2*ntp],   a[1][0], a[1][1], a[1][2], a[1][3], b0, b1);
                mma16(o[0][2*ntp+1], a[0][0], a[0][1], a[0][2], a[0][3], b2, b3);
                mma16(o[1][2*ntp+1], a[1][0], a[1][1], a[1][2], a[1][3], b2, b3);
            }
        }
        __syncthreads();
        if (kt + 2 < nkt) KV_ISSUE(kt + 2);
    }
    #undef KV_ISSUE

    #pragma unroll
    for (int mi = 0; mi < 2; mi++) {
        float inv0 = 1.f / lr[mi][0], inv1 = 1.f / lr[mi][1];
        int mb = m0 + (mi << 4);
        #pragma unroll
        for (int nt = 0; nt < 8; nt++) {
            int col = h * 64 + (nt << 3) + 2 * tig;
            *(unsigned*)&outb[(size_t)(q0 + mb + g) * DMODEL + col] =
                packbf(o[mi][nt][0] * inv0, o[mi][nt][1] * inv0);
            *(unsigned*)&outb[(size_t)(q0 + mb + g + 8) * DMODEL + col] =
                packbf(o[mi][nt][2] * inv1, o[mi][nt][3] * inv1);
        }
    }
}

// ---------------- gating (fp32 path: routing must match reference) ------------
__global__ __launch_bounds__(128) void gate_topk(
    const float* __restrict__ xn, const float* __restrict__ gw,
    const float* __restrict__ gb)
{
    int warp = threadIdx.x >> 5;
    int lane = threadIdx.x & 31;
    int t = blockIdx.x * 4 + warp;
    float acc[NEXP];
    #pragma unroll
    for (int e = 0; e < NEXP; e++) acc[e] = 0.f;
    for (int d = lane; d < DMODEL; d += 32) {
        float xv = xn[(size_t)t * DMODEL + d];
        #pragma unroll
        for (int e = 0; e < NEXP; e++) acc[e] = fmaf(xv, gw[e * DMODEL + d], acc[e]);
    }
    #pragma unroll
    for (int e = 0; e < NEXP; e++)
        #pragma unroll
        for (int o = 16; o > 0; o >>= 1)
            acc[e] += __shfl_xor_sync(0xffffffffu, acc[e], o);
    if (lane == 0) {
        float lg[NEXP];
        float mx = -1e30f;
        #pragma unroll
        for (int e = 0; e < NEXP; e++) { lg[e] = acc[e] + gb[e]; mx = fmaxf(mx, lg[e]); }
        float sum = 0.f;
        #pragma unroll
        for (int e = 0; e < NEXP; e++) { lg[e] = __expf(lg[e] - mx); sum += lg[e]; }
        float inv = 1.f / sum;
        int e0 = 0; float p0 = lg[0];
        #pragma unroll
        for (int e = 1; e < NEXP; e++) if (lg[e] > p0) { p0 = lg[e]; e0 = e; }
        int e1 = -1; float p1 = -1.f;
        #pragma unroll
        for (int e = 0; e < NEXP; e++)
            if (e != e0 && lg[e] > p1) { p1 = lg[e]; e1 = e; }
        g_tidx[t * 2] = e0;         g_tidx[t * 2 + 1] = e1;
        g_tscale[t * 2] = p0 * inv; g_tscale[t * 2 + 1] = p1 * inv;
        atomicAdd(&g_counts[e0], 1);
        atomicAdd(&g_counts[e1], 1);
    }
}

__global__ void zero_counts_k() {
    if (threadIdx.x < NEXP) { g_counts[threadIdx.x] = 0; g_cursor[threadIdx.x] = 0; }
}

__global__ void calc_offsets_k() {
    int o = 0, nt = 0;
    for (int e = 0; e < NEXP; e++) {
        g_off[e] = o;
        o += g_counts[e];
    }
    for (int e = 0; e < NEXP; e++)
        for (int bm = 0; bm < g_counts[e]; bm += 128) {
            g_tileE[nt] = e;
            g_tileBm[nt] = bm;
            nt++;
        }
    g_ntiles = nt;
}

__global__ __launch_bounds__(128) void gather_pairs()
{
    int p = blockIdx.x;
    __shared__ int posS;
    if (threadIdx.x == 0) {
        int e = g_tidx[p];
        int pos = g_off[e] + atomicAdd(&g_cursor[e], 1);
        g_rowScale[pos] = g_tscale[p];
        g_pairRow[p] = pos;
        posS = pos;
    }
    __syncthreads();
    int pos = posS;
    int t = p >> 1;
    ((uint2*)(g_xgb + (size_t)pos * DMODEL))[threadIdx.x] =
        ((const uint2*)(g_xnb + (size_t)t * DMODEL))[threadIdx.x];
}

// ---------------- launch -----------------------------------------------------
extern "C" void kernel_launch(void* const* d_in, const int* in_sizes, int n_in,
                              void* d_out, int out_size)
{
    const float* src        = (const float*)d_in[0];
    const float* in_proj_w  = (const float*)d_in[1];
    const float* in_proj_b  = (const float*)d_in[2];
    const float* out_proj_w = (const float*)d_in[3];
    const float* out_proj_b = (const float*)d_in[4];
    const float* ln1_g      = (const float*)d_in[5];
    const float* ln1_b      = (const float*)d_in[6];
    const float* ln2_g      = (const float*)d_in[7];
    const float* ln2_b      = (const float*)d_in[8];
    const float* gate_w     = (const float*)d_in[9];
    const float* gate_b     = (const float*)d_in[10];
    const float* w1         = (const float*)d_in[11];
    const float* b1         = (const float*)d_in[12];
    const float* w2         = (const float*)d_in[13];
    const float* b2         = (const float*)d_in[14];
    const float* wo         = (const float*)d_in[15];
    const float* bo         = (const float*)d_in[16];
    float* out = (float*)d_out;

    float *xn;
    __nv_bfloat16 *xnb, *qkvb, *attnb, *bwin, *bwout, *bw1, *bw2, *bwo;
    cudaGetSymbolAddress((void**)&xn,    g_xn);
    cudaGetSymbolAddress((void**)&xnb,   g_xnb);
    cudaGetSymbolAddress((void**)&qkvb,  g_qkvb);
    cudaGetSymbolAddress((void**)&attnb, g_attnb);
    cudaGetSymbolAddress((void**)&bwin,  g_bwin);
    cudaGetSymbolAddress((void**)&bwout, g_bwout);
    cudaGetSymbolAddress((void**)&bw1,   g_bw1);
    cudaGetSymbolAddress((void**)&bw2,   g_bw2);
    cudaGetSymbolAddress((void**)&bwo,   g_bwo);

    cudaFuncSetAttribute(flash_attn_bf16,
                         cudaFuncAttributeMaxDynamicSharedMemorySize,
                         ATTN_SMEM_BYTES);

    // weight converts (fp32 -> bf16); 4 float4 per thread
    f2bf_k<<<3 * DMODEL * DMODEL / 4096, 256>>>(in_proj_w, bwin);
    f2bf_k<<<DMODEL * DMODEL / 4096, 256>>>(out_proj_w, bwout);
    f2bf_k<<<NEXP * FDIM * DMODEL / 4096, 256>>>(w1, bw1);
    f2bf_k<<<NEXP * FDIM * DMODEL / 4096, 256>>>(w2, bw2);
    f2bf_k<<<NEXP * DMODEL * FDIM / 4096, 256>>>(wo, bwo);

    zero_counts_k<<<1, 32>>>();

    // ---- attention block ----
    layernorm_k<<<SEQ, 128>>>(src, ln1_g, ln1_b, xn, xnb);
    gemm_qkv<<<dim3(12, 32), 256>>>(xnb, bwin, in_proj_b, qkvb,
                                    SEQ, 3 * DMODEL, DMODEL);
    flash_attn_bf16<<<dim3(SEQ / 128, NHEAD), 128, ATTN_SMEM_BYTES>>>(qkvb, attnb);
    gemm_bf16_nt<<<dim3(4, 32), 256>>>(attnb, bwout, out_proj_b, src, out,
                                       SEQ, DMODEL, DMODEL);

    // ---- MoE block ----
    layernorm_k<<<SEQ, 128>>>(out, ln2_g, ln2_b, xn, xnb);
    gate_topk<<<SEQ / 4, 128>>>(xn, gate_w, gate_b);
    calc_offsets_k<<<1, 1>>>();
    gather_pairs<<<NPAIR, 128>>>();
    moe_up1<<<dim3(FDIM / 128, MAXTILE - 8), 256>>>(b1);
    moe_up2<<<dim3(FDIM / 128, MAXTILE - 8), 256>>>(b2);
    moe_down<<<dim3(DMODEL / 128, MAXTILE - 8), 256>>>(bo);
    moe_combine<<<SEQ, 128>>>(out);
}